// round 1
// baseline (speedup 1.0000x reference)
#include <cuda_runtime.h>
#include <math.h>
#include <cfloat>

// ---------------- constants ----------------
#define TAU_F   0.4f
#define ALPHA_F 1.0f
#define GAMMA_F 0.7f
#define DELTA_F 0.6f
#define MU_F    0.6f
#define NU_F    0.3f

#define N_  8192
#define E_  2048
#define D_  256
#define SAMP_ 100
#define MFN_  100
#define MHN_  200
#define ECAP_ 500

// ---------------- scratch (device globals; no allocation allowed) ----------------
__device__ float g_tmp[N_ * D_];           // MLP intermediate (8 MB)
__device__ float g_z[N_ * D_];             // node MLP output  (8 MB)
__device__ float g_znorm[N_];
__device__ int   g_cnt[512];
__device__ float g_edge_part[8][512 * D_]; // split-K partials for maskT@z (4 MB)
__device__ float g_emean[ECAP_ * D_];
__device__ float g_etmp[ECAP_ * D_];
__device__ float g_hedges[ECAP_ * D_];
__device__ float g_hnorm[ECAP_];
__device__ float g_sim[MHN_ * MHN_];
__device__ float g_attdot[MHN_ * MHN_];
__device__ float g_attm[MHN_ * 8], g_atts[MHN_ * 8];
__device__ float g_att[MHN_ * MHN_];
__device__ float g_lsem[MFN_ * 8], g_lses[MFN_ * 8];
__device__ float g_lse[MFN_];
__device__ float g_clrow[ECAP_];
__device__ float g_fnval[MFN_ * MFN_];
__device__ float g_fnflag[MFN_ * MFN_];
__device__ float g_hnsum[MHN_], g_hncnt[MHN_];
__device__ unsigned long long g_nzc[2];
__device__ float g_dnon[2];

// ---------------- reduction helpers ----------------
__device__ __forceinline__ float warp_sum(float v) {
#pragma unroll
    for (int o = 16; o > 0; o >>= 1) v += __shfl_xor_sync(0xffffffffu, v, o);
    return v;
}
__device__ __forceinline__ float warp_max(float v) {
#pragma unroll
    for (int o = 16; o > 0; o >>= 1) v = fmaxf(v, __shfl_xor_sync(0xffffffffu, v, o));
    return v;
}
__device__ __forceinline__ int warp_sum_i(int v) {
#pragma unroll
    for (int o = 16; o > 0; o >>= 1) v += __shfl_xor_sync(0xffffffffu, v, o);
    return v;
}
// deterministic block reductions (fixed tree)
__device__ float block_sum(float v, float* sm) {
    int w = threadIdx.x >> 5, lane = threadIdx.x & 31, nw = blockDim.x >> 5;
    v = warp_sum(v);
    if (lane == 0) sm[w] = v;
    __syncthreads();
    float r = (threadIdx.x < nw) ? sm[threadIdx.x] : 0.f;
    if (w == 0) r = warp_sum(r);
    if (threadIdx.x == 0) sm[0] = r;
    __syncthreads();
    r = sm[0];
    __syncthreads();
    return r;
}
__device__ float block_max(float v, float* sm) {
    int w = threadIdx.x >> 5, lane = threadIdx.x & 31, nw = blockDim.x >> 5;
    v = warp_max(v);
    if (lane == 0) sm[w] = v;
    __syncthreads();
    float r = (threadIdx.x < nw) ? sm[threadIdx.x] : -FLT_MAX;
    if (w == 0) r = warp_max(r);
    if (threadIdx.x == 0) sm[0] = r;
    __syncthreads();
    r = sm[0];
    __syncthreads();
    return r;
}

// ---------------- kernels ----------------

// zero the scratch that is accumulated / sparsely written
__global__ void init_kernel() {
    int i = blockIdx.x * 256 + threadIdx.x;
    if (i < 2)   g_nzc[i] = 0ull;
    if (i < 512) g_cnt[i] = 0;
    if (i < MFN_ * MFN_) { g_fnval[i] = 0.f; g_fnflag[i] = 0.f; }
}

// nonzero counts over both H matrices (vectorized, integer atomics = exact)
__global__ void count_nz_kernel(const float4* __restrict__ a, const float4* __restrict__ b) {
    const int n4 = N_ * E_ / 4;
    int ca = 0, cb = 0;
    for (int i = blockIdx.x * blockDim.x + threadIdx.x; i < n4; i += gridDim.x * blockDim.x) {
        float4 x = a[i];
        ca += (x.x != 0.f) + (x.y != 0.f) + (x.z != 0.f) + (x.w != 0.f);
        float4 y = b[i];
        cb += (y.x != 0.f) + (y.y != 0.f) + (y.z != 0.f) + (y.w != 0.f);
    }
    __shared__ int sa[32], sb[32];
    int w = threadIdx.x >> 5, lane = threadIdx.x & 31;
    ca = warp_sum_i(ca); cb = warp_sum_i(cb);
    if (lane == 0) { sa[w] = ca; sb[w] = cb; }
    __syncthreads();
    if (w == 0) {
        int x = (lane < 8) ? sa[lane] : 0;
        int y = (lane < 8) ? sb[lane] : 0;
        x = warp_sum_i(x); y = warp_sum_i(y);
        if (lane == 0) {
            atomicAdd(&g_nzc[0], (unsigned long long)x);
            atomicAdd(&g_nzc[1], (unsigned long long)y);
        }
    }
}

// topology term: ||A_s - Ap_s||^2 and ||A_s||^2 over the 100x100 sample (single block = deterministic)
__global__ void topo_kernel(const float* __restrict__ Ho, const float* __restrict__ Hp) {
    float dn2 = 0.f, on2 = 0.f;
    for (int p = threadIdx.x; p < SAMP_ * SAMP_; p += blockDim.x) {
        int i = p / SAMP_, j = p % SAMP_;
        const float* hoi = Ho + i * E_; const float* hoj = Ho + j * E_;
        const float* hpi = Hp + i * E_; const float* hpj = Hp + j * E_;
        float as = 0.f, aps = 0.f;
        for (int k = 0; k < SAMP_; k++) { as += hoi[k] * hoj[k]; aps += hpi[k] * hpj[k]; }
        float d = as - aps;
        dn2 += d * d; on2 += as * as;
    }
    __shared__ float sm[32];
    float D2 = block_sum(dn2, sm);
    float O2 = block_sum(on2, sm);
    if (threadIdx.x == 0) { g_dnon[0] = D2; g_dnon[1] = O2; }
}

// C[M,256] = act(A[M,256] @ B[256,256] + bias), tiled 64x64, BK=16, 4x4 register tile
template <bool RELU>
__global__ void gemm_bias_kernel(const float* __restrict__ A, const float* __restrict__ B,
                                 const float* __restrict__ bias, float* __restrict__ C, int M) {
    const int K = D_, Nn = D_;
    __shared__ float As[16][65];   // transposed A tile, padded vs bank conflicts
    __shared__ float Bs[16][68];
    int bm = blockIdx.x * 64, bn = blockIdx.y * 64;
    int tid = threadIdx.x, tx = tid & 15, ty = tid >> 4;
    float acc[4][4] = {};
    for (int k0 = 0; k0 < K; k0 += 16) {
#pragma unroll
        for (int l = 0; l < 4; l++) {
            int idx = tid + l * 256; int r = idx >> 4, c = idx & 15;
            int row = bm + r;
            As[c][r] = (row < M) ? A[row * K + k0 + c] : 0.f;
        }
#pragma unroll
        for (int l = 0; l < 4; l++) {
            int idx = tid + l * 256; int r = idx >> 6, c = idx & 63;
            Bs[r][c] = B[(k0 + r) * Nn + bn + c];
        }
        __syncthreads();
#pragma unroll
        for (int kk = 0; kk < 16; kk++) {
            float a[4], b[4];
#pragma unroll
            for (int u = 0; u < 4; u++) a[u] = As[kk][ty * 4 + u];
#pragma unroll
            for (int u = 0; u < 4; u++) b[u] = Bs[kk][tx * 4 + u];
#pragma unroll
            for (int i = 0; i < 4; i++)
#pragma unroll
                for (int j = 0; j < 4; j++) acc[i][j] += a[i] * b[j];
        }
        __syncthreads();
    }
#pragma unroll
    for (int i = 0; i < 4; i++) {
        int row = bm + ty * 4 + i;
        if (row >= M) continue;
#pragma unroll
        for (int j = 0; j < 4; j++) {
            int col = bn + tx * 4 + j;
            float v = acc[i][j] + bias[col];
            if (RELU) v = fmaxf(v, 0.f);
            C[row * Nn + col] = v;
        }
    }
}

// per-row L2 norms (warp per row)
__global__ void rownorm_kernel(const float* __restrict__ X, float* __restrict__ nrm, int rows) {
    int r = blockIdx.x * 8 + (threadIdx.x >> 5);
    int lane = threadIdx.x & 31;
    if (r >= rows) return;
    float s = 0.f;
#pragma unroll
    for (int t = 0; t < 8; t++) { float v = X[r * D_ + lane + 32 * t]; s += v * v; }
    s = warp_sum(s);
    if (lane == 0) nrm[r] = fmaxf(sqrtf(s), 1e-8f);
}

// per-edge counts (coalesced along e; integer atomics = exact)
__global__ void cnt_kernel(const float* __restrict__ Hp) {
    int e = threadIdx.x;
    if (e >= ECAP_) return;
    int i0 = blockIdx.x * 512;
    int c = 0;
    for (int i = i0; i < i0 + 512; i++) c += (Hp[i * E_ + e] > 0.f);
    atomicAdd(&g_cnt[e], c);
}

// edge_sum partials: part[sp] += mask(i in split sp)^T @ z, tile 64e x 64d, chunk 16 i's
__global__ void edge_gemm_kernel(const float* __restrict__ Hp, const float* __restrict__ z) {
    __shared__ float Ms[16][64];
    __shared__ float Zs[16][64];
    int be = blockIdx.x * 64, bd = blockIdx.y * 64, sp = blockIdx.z;
    int tid = threadIdx.x, tx = tid & 15, ty = tid >> 4;
    float acc[4][4] = {};
    int i0base = sp * 1024;
    for (int ic = 0; ic < 1024; ic += 16) {
        int i0 = i0base + ic;
#pragma unroll
        for (int l = 0; l < 4; l++) {
            int idx = tid + l * 256; int r = idx >> 6, c = idx & 63;
            int e = be + c;
            float v = (e < ECAP_) ? Hp[(i0 + r) * E_ + e] : 0.f;
            Ms[r][c] = (v > 0.f) ? 1.f : 0.f;
        }
#pragma unroll
        for (int l = 0; l < 4; l++) {
            int idx = tid + l * 256; int r = idx >> 6, c = idx & 63;
            Zs[r][c] = z[(i0 + r) * D_ + bd + c];
        }
        __syncthreads();
#pragma unroll
        for (int kk = 0; kk < 16; kk++) {
            float a[4], b[4];
#pragma unroll
            for (int u = 0; u < 4; u++) a[u] = Ms[kk][ty * 4 + u];
#pragma unroll
            for (int u = 0; u < 4; u++) b[u] = Zs[kk][tx * 4 + u];
#pragma unroll
            for (int i = 0; i < 4; i++)
#pragma unroll
                for (int j = 0; j < 4; j++) acc[i][j] += a[i] * b[j];
        }
        __syncthreads();
    }
#pragma unroll
    for (int i = 0; i < 4; i++) {
        int e = be + ty * 4 + i;  // e < 512 always (padded buffer)
#pragma unroll
        for (int j = 0; j < 4; j++)
            g_edge_part[sp][e * D_ + bd + tx * 4 + j] = acc[i][j];
    }
}

// deterministic partial reduce + mean
__global__ void edge_reduce_kernel() {
    int idx = blockIdx.x * 256 + threadIdx.x;  // 500*256 launched exactly
    int e = idx / D_;
    float s = 0.f;
#pragma unroll
    for (int p = 0; p < 8; p++) s += g_edge_part[p][idx + (e * D_ >= 0 ? 0 : 0)];
    // note: part buffers are indexed with e padded to 512, but idx here runs over e<500
    // and part layout uses e*256+d directly, identical for e<500.
    int c = g_cnt[e];
    g_emean[idx] = (c > 0) ? s / (float)c : 0.f;
}

// sim = zn[:200] @ zn[:200]^T
__global__ void sim_kernel() {
    __shared__ float zi[256];
    int i = blockIdx.x, tid = threadIdx.x;
    zi[tid] = g_z[i * D_ + tid] / g_znorm[i];
    __syncthreads();
    int w = tid >> 5, lane = tid & 31;
    for (int j = w; j < MHN_; j += 8) {
        float s = 0.f;
#pragma unroll
        for (int t = 0; t < 8; t++) { int k = lane + 32 * t; s += zi[k] * g_z[j * D_ + k]; }
        s = warp_sum(s);
        if (lane == 0) g_sim[i * MHN_ + j] = s / g_znorm[j];
    }
}

// att partial softmax: 8 rows/block, 8 j-splits of 1024; store raw dots for j<200 (split 0)
__global__ void att_kernel() {
    __shared__ float zi[8][256];
    __shared__ float smm[8][8], sms[8][8];
    int rg = blockIdx.x, sp = blockIdx.y;
    int tid = threadIdx.x;
#pragma unroll
    for (int r = 0; r < 8; r++) zi[r][tid] = g_z[(rg * 8 + r) * D_ + tid];
    __syncthreads();
    int w = tid >> 5, lane = tid & 31;
    float m[8], s[8];
#pragma unroll
    for (int r = 0; r < 8; r++) { m[r] = -FLT_MAX; s[r] = 0.f; }
    int j0 = sp * 1024;
    for (int jj = w; jj < 1024; jj += 8) {
        int j = j0 + jj;
        float d[8];
#pragma unroll
        for (int r = 0; r < 8; r++) d[r] = 0.f;
#pragma unroll
        for (int t = 0; t < 8; t++) {
            int k = lane + 32 * t;
            float zj = g_z[j * D_ + k];
#pragma unroll
            for (int r = 0; r < 8; r++) d[r] += zi[r][k] * zj;
        }
#pragma unroll
        for (int r = 0; r < 8; r++) d[r] = warp_sum(d[r]);
        if (sp == 0 && j < MHN_ && lane == 0) {
#pragma unroll
            for (int r = 0; r < 8; r++) g_attdot[(rg * 8 + r) * MHN_ + j] = d[r];
        }
#pragma unroll
        for (int r = 0; r < 8; r++) {
            float mn = fmaxf(m[r], d[r]);
            s[r] = s[r] * expf(m[r] - mn) + expf(d[r] - mn);
            m[r] = mn;
        }
    }
    if (lane == 0) {
#pragma unroll
        for (int r = 0; r < 8; r++) { smm[w][r] = m[r]; sms[w][r] = s[r]; }
    }
    __syncthreads();
    if (tid < 8) {
        float M = -FLT_MAX;
        for (int q = 0; q < 8; q++) M = fmaxf(M, smm[q][tid]);
        float S = 0.f;
        for (int q = 0; q < 8; q++) S += sms[q][tid] * expf(smm[q][tid] - M);
        g_attm[(rg * 8 + tid) * 8 + sp] = M;
        g_atts[(rg * 8 + tid) * 8 + sp] = S;
    }
}

// lse_all partial logsumexp: 4 rows/block (zn-normalized, /TAU), 8 j-splits
__global__ void lse_kernel() {
    __shared__ float zi[4][256];
    __shared__ float smm[8][4], sms[8][4];
    int rg = blockIdx.x, sp = blockIdx.y;
    int tid = threadIdx.x;
#pragma unroll
    for (int r = 0; r < 4; r++) {
        int row = rg * 4 + r;
        zi[r][tid] = g_z[row * D_ + tid] / g_znorm[row];
    }
    __syncthreads();
    int w = tid >> 5, lane = tid & 31;
    float m[4], s[4];
#pragma unroll
    for (int r = 0; r < 4; r++) { m[r] = -FLT_MAX; s[r] = 0.f; }
    int j0 = sp * 1024;
    for (int jj = w; jj < 1024; jj += 8) {
        int j = j0 + jj;
        float d[4];
#pragma unroll
        for (int r = 0; r < 4; r++) d[r] = 0.f;
#pragma unroll
        for (int t = 0; t < 8; t++) {
            int k = lane + 32 * t;
            float zj = g_z[j * D_ + k];
#pragma unroll
            for (int r = 0; r < 4; r++) d[r] += zi[r][k] * zj;
        }
        float inv = 1.f / (g_znorm[j] * TAU_F);
#pragma unroll
        for (int r = 0; r < 4; r++) {
            float v = warp_sum(d[r]) * inv;
            float mn = fmaxf(m[r], v);
            s[r] = s[r] * expf(m[r] - mn) + expf(v - mn);
            m[r] = mn;
        }
    }
    if (lane == 0) {
#pragma unroll
        for (int r = 0; r < 4; r++) { smm[w][r] = m[r]; sms[w][r] = s[r]; }
    }
    __syncthreads();
    if (tid < 4) {
        float M = -FLT_MAX;
        for (int q = 0; q < 8; q++) M = fmaxf(M, smm[q][tid]);
        float S = 0.f;
        for (int q = 0; q < 8; q++) S += sms[q][tid] * expf(smm[q][tid] - M);
        g_lsem[(rg * 4 + tid) * 8 + sp] = M;
        g_lses[(rg * 4 + tid) * 8 + sp] = S;
    }
}

__global__ void att_merge_kernel() {
    int i = blockIdx.x;
    __shared__ float Ms, Ss;
    if (threadIdx.x == 0) {
        float M = -FLT_MAX;
        for (int p = 0; p < 8; p++) M = fmaxf(M, g_attm[i * 8 + p]);
        float S = 0.f;
        for (int p = 0; p < 8; p++) S += g_atts[i * 8 + p] * expf(g_attm[i * 8 + p] - M);
        Ms = M; Ss = S;
    }
    __syncthreads();
    for (int j = threadIdx.x; j < MHN_; j += blockDim.x)
        g_att[i * MHN_ + j] = expf(g_attdot[i * MHN_ + j] - Ms) / Ss;
}

__global__ void lse_merge_kernel() {
    int i = threadIdx.x;
    if (i >= MFN_) return;
    float M = -FLT_MAX;
    for (int p = 0; p < 8; p++) M = fmaxf(M, g_lsem[i * 8 + p]);
    float S = 0.f;
    for (int p = 0; p < 8; p++) S += g_lses[i * 8 + p] * expf(g_lsem[i * 8 + p] - M);
    g_lse[i] = M + logf(S);
}

// contrastive loss per row: logits over 500 edges, log-softmax diag
__global__ void cl_kernel() {
    __shared__ float zi[256];
    __shared__ float logit[500];
    __shared__ float sm[32];
    int i = blockIdx.x, tid = threadIdx.x;
    zi[tid] = g_z[i * D_ + tid] / g_znorm[i];
    __syncthreads();
    int w = tid >> 5, lane = tid & 31;
    for (int j = w; j < ECAP_; j += 8) {
        float s = 0.f;
#pragma unroll
        for (int t = 0; t < 8; t++) { int k = lane + 32 * t; s += zi[k] * g_hedges[j * D_ + k]; }
        s = warp_sum(s);
        if (lane == 0) logit[j] = s / (g_hnorm[j] * TAU_F);
    }
    __syncthreads();
    float lm = -FLT_MAX;
    for (int j = tid; j < ECAP_; j += 256) lm = fmaxf(lm, logit[j]);
    float M = block_max(lm, sm);
    float ls = 0.f;
    for (int j = tid; j < ECAP_; j += 256) ls += expf(logit[j] - M);
    float S = block_sum(ls, sm);
    if (tid == 0) g_clrow[i] = logit[i] - (M + logf(S));
}

// false-negative pairs: early-exit on sim/att masks, then exact-zero tests on A100/Ap100
__global__ void fn_kernel(const float* __restrict__ Ho, const float* __restrict__ Hp) {
    int j = blockIdx.x, i = blockIdx.y;
    if (j <= i) return;
    float simv = g_sim[i * MHN_ + j];
    float attv = g_att[i * MHN_ + j];
    if (!(simv > GAMMA_F && attv > DELTA_F)) return;
    __shared__ float sm[32];
    float ao = 0.f, ap = 0.f;
    for (int k = threadIdx.x; k < E_; k += 256) {
        ao += Ho[i * E_ + k] * Ho[j * E_ + k];
        ap += Hp[i * E_ + k] * Hp[j * E_ + k];
    }
    ao = block_sum(ao, sm);
    ap = block_sum(ap, sm);
    if (threadIdx.x == 0 && ap == 0.f && ao > 0.f) {
        g_fnval[i * MFN_ + j] = -(simv / TAU_F - g_lse[i]);
        g_fnflag[i * MFN_ + j] = 1.f;
    }
}

// hard-negative loss per row
__global__ void hn_kernel() {
    __shared__ float sm[32];
    int i = blockIdx.x;
    int j = threadIdx.x;
    bool act = j < MHN_;
    float simv = act ? g_sim[i * MHN_ + j] : 0.f;
    float attv = act ? g_att[i * MHN_ + j] : 1.f;
    bool mask = act && (j != i) && (simv > MU_F) && (attv < NU_F);
    float neg = -simv / TAU_F;
    float m = block_max(mask ? neg : -FLT_MAX, sm);
    if (m == -FLT_MAX) {
        if (threadIdx.x == 0) { g_hnsum[i] = 0.f; g_hncnt[i] = 0.f; }
        return;
    }
    float s = block_sum(mask ? expf(neg - m) : 0.f, sm);
    float lse = m + logf(s);
    float wgt = fminf(simv / MU_F, 1.f);
    float pair = -wgt * (neg - lse);
    float ps = block_sum(mask ? pair : 0.f, sm);
    float pc = block_sum(mask ? 1.f : 0.f, sm);
    if (threadIdx.x == 0) { g_hnsum[i] = ps; g_hncnt[i] = pc; }
}

// final scalar combine (single block, deterministic)
__global__ void final_kernel(const float* __restrict__ bw, float* __restrict__ out) {
    __shared__ float sm[32];
    int tid = threadIdx.x;
    float v = 0.f;
    for (int i = tid; i < ECAP_; i += 512) v += g_clrow[i];
    float clsum = block_sum(v, sm);
    v = 0.f; float c = 0.f;
    for (int p = tid; p < MFN_ * MFN_; p += 512) { v += g_fnval[p]; c += g_fnflag[p]; }
    float fnsum = block_sum(v, sm);
    float fncnt = block_sum(c, sm);
    v = 0.f; c = 0.f;
    for (int i = tid; i < MHN_; i += 512) { v += g_hnsum[i]; c += g_hncnt[i]; }
    float hnsum = block_sum(v, sm);
    float hncnt = block_sum(c, sm);
    if (tid == 0) {
        float cl_loss = -clsum / (float)ECAP_;
        float fn_loss = (fncnt > 0.f) ? fnsum / fmaxf(fncnt, 1.f) : 0.f;
        float hard_loss = (hncnt > 0.f) ? hnsum / fmaxf(hncnt, 1.f) : 0.f;
        float nz = (float)g_nzc[0], nzp = (float)g_nzc[1];
        float sparsity = (nz > 0.f) ? nzp / fmaxf(nz, 1.f) : 1.f;
        float dn = sqrtf(g_dnon[0]), on = sqrtf(g_dnon[1]);
        float topo = (on > 0.f) ? expf(-ALPHA_F * dn / fmaxf(on, 1e-12f)) : 1.f;
        float retention = sparsity * topo;
        out[0] = bw[0] * (retention * cl_loss + fn_loss + hard_loss);
    }
}

// ---------------- launch ----------------
extern "C" void kernel_launch(void* const* d_in, const int* in_sizes, int n_in,
                              void* d_out, int out_size) {
    (void)in_sizes; (void)n_in; (void)out_size;
    const float* Ho  = (const float*)d_in[0];
    const float* Hp  = (const float*)d_in[1];
    const float* ne  = (const float*)d_in[2];
    const float* bw  = (const float*)d_in[3];
    const float* Wn1 = (const float*)d_in[4];
    const float* bn1 = (const float*)d_in[5];
    const float* Wn2 = (const float*)d_in[6];
    const float* bn2 = (const float*)d_in[7];
    const float* We1 = (const float*)d_in[8];
    const float* be1 = (const float*)d_in[9];
    const float* We2 = (const float*)d_in[10];
    const float* be2 = (const float*)d_in[11];
    float* out = (float*)d_out;

    void *p;
    float *p_tmp, *p_z, *p_znorm, *p_emean, *p_etmp, *p_hedges, *p_hnorm;
    cudaGetSymbolAddress(&p, g_tmp);    p_tmp    = (float*)p;
    cudaGetSymbolAddress(&p, g_z);      p_z      = (float*)p;
    cudaGetSymbolAddress(&p, g_znorm);  p_znorm  = (float*)p;
    cudaGetSymbolAddress(&p, g_emean);  p_emean  = (float*)p;
    cudaGetSymbolAddress(&p, g_etmp);   p_etmp   = (float*)p;
    cudaGetSymbolAddress(&p, g_hedges); p_hedges = (float*)p;
    cudaGetSymbolAddress(&p, g_hnorm);  p_hnorm  = (float*)p;

    init_kernel<<<40, 256>>>();
    count_nz_kernel<<<2048, 256>>>((const float4*)Ho, (const float4*)Hp);
    topo_kernel<<<1, 1024>>>(Ho, Hp);

    // node MLP
    gemm_bias_kernel<true ><<<dim3(128, 4), 256>>>(ne,    Wn1, bn1, p_tmp, N_);
    gemm_bias_kernel<false><<<dim3(128, 4), 256>>>(p_tmp, Wn2, bn2, p_z,   N_);
    rownorm_kernel<<<N_ / 8, 256>>>(p_z, p_znorm, N_);

    // edge aggregation
    cnt_kernel<<<16, 512>>>(Hp);
    edge_gemm_kernel<<<dim3(8, 4, 8), 256>>>(Hp, p_z);
    edge_reduce_kernel<<<ECAP_, 256>>>();

    // edge MLP
    gemm_bias_kernel<true ><<<dim3(8, 4), 256>>>(p_emean, We1, be1, p_etmp,   ECAP_);
    gemm_bias_kernel<false><<<dim3(8, 4), 256>>>(p_etmp,  We2, be2, p_hedges, ECAP_);
    rownorm_kernel<<<(ECAP_ + 7) / 8, 256>>>(p_hedges, p_hnorm, ECAP_);

    // similarity / attention / logsumexp
    sim_kernel<<<MHN_, 256>>>();
    att_kernel<<<dim3(25, 8), 256>>>();
    lse_kernel<<<dim3(25, 8), 256>>>();
    att_merge_kernel<<<MHN_, 256>>>();
    lse_merge_kernel<<<1, 128>>>();

    // losses
    cl_kernel<<<ECAP_, 256>>>();
    fn_kernel<<<dim3(MFN_, MFN_), 256>>>(Ho, Hp);
    hn_kernel<<<MHN_, 256>>>();

    final_kernel<<<1, 512>>>(bw, out);
}

// round 2
// speedup vs baseline: 2.3758x; 2.3758x over previous
#include <cuda_runtime.h>
#include <math.h>
#include <cfloat>

// ---------------- constants ----------------
#define TAU_F   0.4f
#define ALPHA_F 1.0f
#define GAMMA_F 0.7f
#define DELTA_F 0.6f
#define MU_F    0.6f
#define NU_F    0.3f

#define N_  8192
#define E_  2048
#define D_  256
#define SAMP_ 100
#define MFN_  100
#define MHN_  200
#define ECAP_ 500

// ---------------- scratch (device globals; no allocation allowed) ----------------
__device__ float g_tmp[N_ * D_];           // MLP intermediate (8 MB)
__device__ float g_z[N_ * D_];             // node MLP output  (8 MB)
__device__ float g_znorm[N_];
__device__ int   g_cnt[512];
__device__ float g_edge_part[8][512 * D_]; // split-K partials for maskT@z (4 MB)
__device__ float g_emean[ECAP_ * D_];
__device__ float g_etmp[ECAP_ * D_];
__device__ float g_hedges[ECAP_ * D_];
__device__ float g_hnorm[ECAP_];
__device__ float g_sim[MHN_ * MHN_];
__device__ float g_attdot[MHN_ * MHN_];
__device__ float g_attm[MHN_ * 8], g_atts[MHN_ * 8];
__device__ float g_att[MHN_ * MHN_];
__device__ float g_lsem[MFN_ * 8], g_lses[MFN_ * 8];
__device__ float g_lse[MFN_];
__device__ float g_clrow[ECAP_];
__device__ float g_fnval[MFN_ * MFN_];
__device__ float g_fnflag[MFN_ * MFN_];
__device__ float g_hnsum[MHN_], g_hncnt[MHN_];
__device__ unsigned long long g_nzc[2];
__device__ float g_topo[SAMP_ * 2];        // per-block (dn2, on2) partials

// ---------------- reduction helpers ----------------
__device__ __forceinline__ float warp_sum(float v) {
#pragma unroll
    for (int o = 16; o > 0; o >>= 1) v += __shfl_xor_sync(0xffffffffu, v, o);
    return v;
}
__device__ __forceinline__ float warp_max(float v) {
#pragma unroll
    for (int o = 16; o > 0; o >>= 1) v = fmaxf(v, __shfl_xor_sync(0xffffffffu, v, o));
    return v;
}
__device__ __forceinline__ int warp_sum_i(int v) {
#pragma unroll
    for (int o = 16; o > 0; o >>= 1) v += __shfl_xor_sync(0xffffffffu, v, o);
    return v;
}
// deterministic block reductions (fixed tree)
__device__ float block_sum(float v, float* sm) {
    int w = threadIdx.x >> 5, lane = threadIdx.x & 31, nw = blockDim.x >> 5;
    v = warp_sum(v);
    if (lane == 0) sm[w] = v;
    __syncthreads();
    float r = (threadIdx.x < nw) ? sm[threadIdx.x] : 0.f;
    if (w == 0) r = warp_sum(r);
    if (threadIdx.x == 0) sm[0] = r;
    __syncthreads();
    r = sm[0];
    __syncthreads();
    return r;
}
__device__ float block_max(float v, float* sm) {
    int w = threadIdx.x >> 5, lane = threadIdx.x & 31, nw = blockDim.x >> 5;
    v = warp_max(v);
    if (lane == 0) sm[w] = v;
    __syncthreads();
    float r = (threadIdx.x < nw) ? sm[threadIdx.x] : -FLT_MAX;
    if (w == 0) r = warp_max(r);
    if (threadIdx.x == 0) sm[0] = r;
    __syncthreads();
    r = sm[0];
    __syncthreads();
    return r;
}

// ---------------- kernels ----------------

__global__ void init_kernel() {
    int i = blockIdx.x * 256 + threadIdx.x;
    if (i < 2)   g_nzc[i] = 0ull;
    if (i < 512) g_cnt[i] = 0;
    if (i < MFN_ * MFN_) { g_fnval[i] = 0.f; g_fnflag[i] = 0.f; }
}

// nonzero counts over both H matrices (vectorized, integer atomics = exact)
__global__ void count_nz_kernel(const float4* __restrict__ a, const float4* __restrict__ b) {
    const int n4 = N_ * E_ / 4;
    int ca = 0, cb = 0;
    for (int i = blockIdx.x * blockDim.x + threadIdx.x; i < n4; i += gridDim.x * blockDim.x) {
        float4 x = a[i];
        ca += (x.x != 0.f) + (x.y != 0.f) + (x.z != 0.f) + (x.w != 0.f);
        float4 y = b[i];
        cb += (y.x != 0.f) + (y.y != 0.f) + (y.z != 0.f) + (y.w != 0.f);
    }
    __shared__ int sa[32], sb[32];
    int w = threadIdx.x >> 5, lane = threadIdx.x & 31;
    ca = warp_sum_i(ca); cb = warp_sum_i(cb);
    if (lane == 0) { sa[w] = ca; sb[w] = cb; }
    __syncthreads();
    if (w == 0) {
        int x = (lane < 8) ? sa[lane] : 0;
        int y = (lane < 8) ? sb[lane] : 0;
        x = warp_sum_i(x); y = warp_sum_i(y);
        if (lane == 0) {
            atomicAdd(&g_nzc[0], (unsigned long long)x);
            atomicAdd(&g_nzc[1], (unsigned long long)y);
        }
    }
}

// topology: one block per row i of the 100x100 sample; partials to g_topo
__global__ void topo_kernel(const float* __restrict__ Ho, const float* __restrict__ Hp) {
    __shared__ float hoi[128], hpi[128];
    __shared__ float sm[32];
    int i = blockIdx.x;
    int tid = threadIdx.x;        // 128 threads, 4 warps
    if (tid < SAMP_) {
        hoi[tid] = Ho[i * E_ + tid];
        hpi[tid] = Hp[i * E_ + tid];
    } else if (tid < 128) {
        hoi[tid] = 0.f; hpi[tid] = 0.f;
    }
    __syncthreads();
    int w = tid >> 5, lane = tid & 31;
    float dn2 = 0.f, on2 = 0.f;
    for (int j = w; j < SAMP_; j += 4) {
        float as = 0.f, aps = 0.f;
#pragma unroll
        for (int t = 0; t < 4; t++) {
            int k = lane + 32 * t;
            if (k < SAMP_) {
                as  += hoi[k] * Ho[j * E_ + k];
                aps += hpi[k] * Hp[j * E_ + k];
            }
        }
        as = warp_sum(as);
        aps = warp_sum(aps);
        if (lane == 0) {
            float d = as - aps;
            dn2 += d * d;
            on2 += as * as;
        }
    }
    float D2 = block_sum(dn2, sm);
    float O2 = block_sum(on2, sm);
    if (tid == 0) { g_topo[i * 2] = D2; g_topo[i * 2 + 1] = O2; }
}

// C[M,256] = act(A[M,256] @ B[256,256] + bias); BM=BN=128, BK=16, 8x8 microtile
template <bool RELU>
__global__ void gemm128_kernel(const float* __restrict__ A, const float* __restrict__ B,
                               const float* __restrict__ bias, float* __restrict__ C, int M) {
    __shared__ float As[16][132];  // As[k][row]
    __shared__ float Bs[16][132];  // Bs[k][col]
    const int bm = blockIdx.x * 128, bn = blockIdx.y * 128;
    const int tid = threadIdx.x;
    const int tx = tid & 15, ty = tid >> 4;
    float acc[8][8] = {};
    for (int k0 = 0; k0 < D_; k0 += 16) {
        // load A tile (128 rows x 16 k), transpose into As[k][row]
#pragma unroll
        for (int l = 0; l < 2; l++) {
            int id = tid * 2 + l;           // float4 id in [0,512)
            int r = id >> 2, c4 = id & 3;   // 4 float4 per row
            int row = bm + r;
            float4 v = make_float4(0.f, 0.f, 0.f, 0.f);
            if (row < M) v = *(const float4*)&A[row * D_ + k0 + c4 * 4];
            As[c4 * 4 + 0][r] = v.x;
            As[c4 * 4 + 1][r] = v.y;
            As[c4 * 4 + 2][r] = v.z;
            As[c4 * 4 + 3][r] = v.w;
        }
        // load B tile (16 k x 128 cols)
#pragma unroll
        for (int l = 0; l < 2; l++) {
            int id = tid * 2 + l;
            int r = id >> 5, c4 = id & 31;  // 32 float4 per row
            float4 v = *(const float4*)&B[(k0 + r) * D_ + bn + c4 * 4];
            *(float4*)&Bs[r][c4 * 4] = v;
        }
        __syncthreads();
#pragma unroll
        for (int kk = 0; kk < 16; kk++) {
            float a[8], b[8];
#pragma unroll
            for (int u = 0; u < 8; u++) a[u] = As[kk][ty * 8 + u];
#pragma unroll
            for (int u = 0; u < 8; u++) b[u] = Bs[kk][tx * 8 + u];
#pragma unroll
            for (int i = 0; i < 8; i++)
#pragma unroll
                for (int j = 0; j < 8; j++) acc[i][j] += a[i] * b[j];
        }
        __syncthreads();
    }
#pragma unroll
    for (int i = 0; i < 8; i++) {
        int row = bm + ty * 8 + i;
        if (row >= M) continue;
#pragma unroll
        for (int j = 0; j < 8; j++) {
            int col = bn + tx * 8 + j;
            float v = acc[i][j] + bias[col];
            if (RELU) v = fmaxf(v, 0.f);
            C[row * D_ + col] = v;
        }
    }
}

// per-row L2 norms (warp per row)
__global__ void rownorm_kernel(const float* __restrict__ X, float* __restrict__ nrm, int rows) {
    int r = blockIdx.x * 8 + (threadIdx.x >> 5);
    int lane = threadIdx.x & 31;
    if (r >= rows) return;
    float s = 0.f;
#pragma unroll
    for (int t = 0; t < 8; t++) { float v = X[r * D_ + lane + 32 * t]; s += v * v; }
    s = warp_sum(s);
    if (lane == 0) nrm[r] = fmaxf(sqrtf(s), 1e-8f);
}

// per-edge counts (coalesced along e; integer atomics = exact)
__global__ void cnt_kernel(const float* __restrict__ Hp) {
    int e = threadIdx.x;
    if (e >= ECAP_) return;
    int i0 = blockIdx.x * 128;
    int c = 0;
    for (int i = i0; i < i0 + 128; i++) c += (Hp[i * E_ + e] > 0.f);
    atomicAdd(&g_cnt[e], c);
}

// edge_sum partials: part[sp] = mask(i-split sp)^T @ z; 128e x 128d tiles, 16-i chunks
__global__ void edge_gemm_kernel(const float* __restrict__ Hp, const float* __restrict__ z) {
    __shared__ float Ms[16][132];  // Ms[i][e] (mask)
    __shared__ float Zs[16][132];  // Zs[i][d]
    const int be = blockIdx.x * 128, bd = blockIdx.y * 128, sp = blockIdx.z;
    const int tid = threadIdx.x;
    const int tx = tid & 15, ty = tid >> 4;
    float acc[8][8] = {};
    const int i0base = sp * 1024;
    for (int ic = 0; ic < 1024; ic += 16) {
        int i0 = i0base + ic;
#pragma unroll
        for (int l = 0; l < 2; l++) {
            int id = tid * 2 + l;
            int r = id >> 5, c4 = id & 31;
            int e = be + c4 * 4;
            float4 v = *(const float4*)&Hp[(i0 + r) * E_ + e];
            Ms[r][c4 * 4 + 0] = (e + 0 < ECAP_ && v.x > 0.f) ? 1.f : 0.f;
            Ms[r][c4 * 4 + 1] = (e + 1 < ECAP_ && v.y > 0.f) ? 1.f : 0.f;
            Ms[r][c4 * 4 + 2] = (e + 2 < ECAP_ && v.z > 0.f) ? 1.f : 0.f;
            Ms[r][c4 * 4 + 3] = (e + 3 < ECAP_ && v.w > 0.f) ? 1.f : 0.f;
        }
#pragma unroll
        for (int l = 0; l < 2; l++) {
            int id = tid * 2 + l;
            int r = id >> 5, c4 = id & 31;
            float4 v = *(const float4*)&z[(i0 + r) * D_ + bd + c4 * 4];
            *(float4*)&Zs[r][c4 * 4] = v;
        }
        __syncthreads();
#pragma unroll
        for (int kk = 0; kk < 16; kk++) {
            float a[8], b[8];
#pragma unroll
            for (int u = 0; u < 8; u++) a[u] = Ms[kk][ty * 8 + u];
#pragma unroll
            for (int u = 0; u < 8; u++) b[u] = Zs[kk][tx * 8 + u];
#pragma unroll
            for (int i = 0; i < 8; i++)
#pragma unroll
                for (int j = 0; j < 8; j++) acc[i][j] += a[i] * b[j];
        }
        __syncthreads();
    }
#pragma unroll
    for (int i = 0; i < 8; i++) {
        int e = be + ty * 8 + i;   // e < 512 always (padded buffer)
#pragma unroll
        for (int j = 0; j < 8; j++)
            g_edge_part[sp][e * D_ + bd + tx * 8 + j] = acc[i][j];
    }
}

// deterministic partial reduce + mean
__global__ void edge_reduce_kernel() {
    int idx = blockIdx.x * 256 + threadIdx.x;  // ECAP_*256 threads exactly
    int e = idx / D_;
    float s = 0.f;
#pragma unroll
    for (int p = 0; p < 8; p++) s += g_edge_part[p][idx];
    int c = g_cnt[e];
    g_emean[idx] = (c > 0) ? s / (float)c : 0.f;
}

// sim = zn[:200] @ zn[:200]^T
__global__ void sim_kernel() {
    __shared__ float zi[256];
    int i = blockIdx.x, tid = threadIdx.x;
    zi[tid] = g_z[i * D_ + tid] / g_znorm[i];
    __syncthreads();
    int w = tid >> 5, lane = tid & 31;
    for (int j = w; j < MHN_; j += 8) {
        float s = 0.f;
#pragma unroll
        for (int t = 0; t < 8; t++) { int k = lane + 32 * t; s += zi[k] * g_z[j * D_ + k]; }
        s = warp_sum(s);
        if (lane == 0) g_sim[i * MHN_ + j] = s / g_znorm[j];
    }
}

// att partial softmax: 8 rows/block, 8 j-splits of 1024; raw dots stored for j<200 (split 0)
__global__ void att_kernel() {
    __shared__ float zi[8][256];
    __shared__ float smm[8][8], sms[8][8];
    int rg = blockIdx.x, sp = blockIdx.y;
    int tid = threadIdx.x;
#pragma unroll
    for (int r = 0; r < 8; r++) zi[r][tid] = g_z[(rg * 8 + r) * D_ + tid];
    __syncthreads();
    int w = tid >> 5, lane = tid & 31;
    float m[8], s[8];
#pragma unroll
    for (int r = 0; r < 8; r++) { m[r] = -FLT_MAX; s[r] = 0.f; }
    int j0 = sp * 1024;
    for (int jj = w; jj < 1024; jj += 8) {
        int j = j0 + jj;
        float d[8];
#pragma unroll
        for (int r = 0; r < 8; r++) d[r] = 0.f;
#pragma unroll
        for (int t = 0; t < 8; t++) {
            int k = lane + 32 * t;
            float zj = g_z[j * D_ + k];
#pragma unroll
            for (int r = 0; r < 8; r++) d[r] += zi[r][k] * zj;
        }
#pragma unroll
        for (int r = 0; r < 8; r++) d[r] = warp_sum(d[r]);
        if (sp == 0 && j < MHN_ && lane == 0) {
#pragma unroll
            for (int r = 0; r < 8; r++) g_attdot[(rg * 8 + r) * MHN_ + j] = d[r];
        }
#pragma unroll
        for (int r = 0; r < 8; r++) {
            float mn = fmaxf(m[r], d[r]);
            s[r] = s[r] * expf(m[r] - mn) + expf(d[r] - mn);
            m[r] = mn;
        }
    }
    if (lane == 0) {
#pragma unroll
        for (int r = 0; r < 8; r++) { smm[w][r] = m[r]; sms[w][r] = s[r]; }
    }
    __syncthreads();
    if (tid < 8) {
        float M = -FLT_MAX;
        for (int q = 0; q < 8; q++) M = fmaxf(M, smm[q][tid]);
        float S = 0.f;
        for (int q = 0; q < 8; q++) S += sms[q][tid] * expf(smm[q][tid] - M);
        g_attm[(rg * 8 + tid) * 8 + sp] = M;
        g_atts[(rg * 8 + tid) * 8 + sp] = S;
    }
}

// lse_all partial logsumexp: 4 rows/block (zn-normalized, /TAU), 8 j-splits
__global__ void lse_kernel() {
    __shared__ float zi[4][256];
    __shared__ float smm[8][4], sms[8][4];
    int rg = blockIdx.x, sp = blockIdx.y;
    int tid = threadIdx.x;
#pragma unroll
    for (int r = 0; r < 4; r++) {
        int row = rg * 4 + r;
        zi[r][tid] = g_z[row * D_ + tid] / g_znorm[row];
    }
    __syncthreads();
    int w = tid >> 5, lane = tid & 31;
    float m[4], s[4];
#pragma unroll
    for (int r = 0; r < 4; r++) { m[r] = -FLT_MAX; s[r] = 0.f; }
    int j0 = sp * 1024;
    for (int jj = w; jj < 1024; jj += 8) {
        int j = j0 + jj;
        float d[4];
#pragma unroll
        for (int r = 0; r < 4; r++) d[r] = 0.f;
#pragma unroll
        for (int t = 0; t < 8; t++) {
            int k = lane + 32 * t;
            float zj = g_z[j * D_ + k];
#pragma unroll
            for (int r = 0; r < 4; r++) d[r] += zi[r][k] * zj;
        }
        float inv = 1.f / (g_znorm[j] * TAU_F);
#pragma unroll
        for (int r = 0; r < 4; r++) {
            float v = warp_sum(d[r]) * inv;
            float mn = fmaxf(m[r], v);
            s[r] = s[r] * expf(m[r] - mn) + expf(v - mn);
            m[r] = mn;
        }
    }
    if (lane == 0) {
#pragma unroll
        for (int r = 0; r < 4; r++) { smm[w][r] = m[r]; sms[w][r] = s[r]; }
    }
    __syncthreads();
    if (tid < 4) {
        float M = -FLT_MAX;
        for (int q = 0; q < 8; q++) M = fmaxf(M, smm[q][tid]);
        float S = 0.f;
        for (int q = 0; q < 8; q++) S += sms[q][tid] * expf(smm[q][tid] - M);
        g_lsem[(rg * 4 + tid) * 8 + sp] = M;
        g_lses[(rg * 4 + tid) * 8 + sp] = S;
    }
}

__global__ void att_merge_kernel() {
    int i = blockIdx.x;
    __shared__ float Ms, Ss;
    if (threadIdx.x == 0) {
        float M = -FLT_MAX;
        for (int p = 0; p < 8; p++) M = fmaxf(M, g_attm[i * 8 + p]);
        float S = 0.f;
        for (int p = 0; p < 8; p++) S += g_atts[i * 8 + p] * expf(g_attm[i * 8 + p] - M);
        Ms = M; Ss = S;
    }
    __syncthreads();
    for (int j = threadIdx.x; j < MHN_; j += blockDim.x)
        g_att[i * MHN_ + j] = expf(g_attdot[i * MHN_ + j] - Ms) / Ss;
}

__global__ void lse_merge_kernel() {
    int i = threadIdx.x;
    if (i >= MFN_) return;
    float M = -FLT_MAX;
    for (int p = 0; p < 8; p++) M = fmaxf(M, g_lsem[i * 8 + p]);
    float S = 0.f;
    for (int p = 0; p < 8; p++) S += g_lses[i * 8 + p] * expf(g_lsem[i * 8 + p] - M);
    g_lse[i] = M + logf(S);
}

// contrastive loss per row: logits over 500 edges, log-softmax diag
__global__ void cl_kernel() {
    __shared__ float zi[256];
    __shared__ float logit[500];
    __shared__ float sm[32];
    int i = blockIdx.x, tid = threadIdx.x;
    zi[tid] = g_z[i * D_ + tid] / g_znorm[i];
    __syncthreads();
    int w = tid >> 5, lane = tid & 31;
    for (int j = w; j < ECAP_; j += 8) {
        float s = 0.f;
#pragma unroll
        for (int t = 0; t < 8; t++) { int k = lane + 32 * t; s += zi[k] * g_hedges[j * D_ + k]; }
        s = warp_sum(s);
        if (lane == 0) logit[j] = s / (g_hnorm[j] * TAU_F);
    }
    __syncthreads();
    float lm = -FLT_MAX;
    for (int j = tid; j < ECAP_; j += 256) lm = fmaxf(lm, logit[j]);
    float M = block_max(lm, sm);
    float ls = 0.f;
    for (int j = tid; j < ECAP_; j += 256) ls += expf(logit[j] - M);
    float S = block_sum(ls, sm);
    if (tid == 0) g_clrow[i] = logit[i] - (M + logf(S));
}

// false-negative pairs: early-exit on sim/att masks, then exact-zero tests on A100/Ap100
__global__ void fn_kernel(const float* __restrict__ Ho, const float* __restrict__ Hp) {
    int j = blockIdx.x, i = blockIdx.y;
    if (j <= i) return;
    float simv = g_sim[i * MHN_ + j];
    float attv = g_att[i * MHN_ + j];
    if (!(simv > GAMMA_F && attv > DELTA_F)) return;
    __shared__ float sm[32];
    float ao = 0.f, ap = 0.f;
    for (int k = threadIdx.x; k < E_; k += 256) {
        ao += Ho[i * E_ + k] * Ho[j * E_ + k];
        ap += Hp[i * E_ + k] * Hp[j * E_ + k];
    }
    ao = block_sum(ao, sm);
    ap = block_sum(ap, sm);
    if (threadIdx.x == 0 && ap == 0.f && ao > 0.f) {
        g_fnval[i * MFN_ + j] = -(simv / TAU_F - g_lse[i]);
        g_fnflag[i * MFN_ + j] = 1.f;
    }
}

// hard-negative loss per row
__global__ void hn_kernel() {
    __shared__ float sm[32];
    int i = blockIdx.x;
    int j = threadIdx.x;
    bool act = j < MHN_;
    float simv = act ? g_sim[i * MHN_ + j] : 0.f;
    float attv = act ? g_att[i * MHN_ + j] : 1.f;
    bool mask = act && (j != i) && (simv > MU_F) && (attv < NU_F);
    float neg = -simv / TAU_F;
    float m = block_max(mask ? neg : -FLT_MAX, sm);
    if (m == -FLT_MAX) {
        if (threadIdx.x == 0) { g_hnsum[i] = 0.f; g_hncnt[i] = 0.f; }
        return;
    }
    float s = block_sum(mask ? expf(neg - m) : 0.f, sm);
    float lse = m + logf(s);
    float wgt = fminf(simv / MU_F, 1.f);
    float pair = -wgt * (neg - lse);
    float ps = block_sum(mask ? pair : 0.f, sm);
    float pc = block_sum(mask ? 1.f : 0.f, sm);
    if (threadIdx.x == 0) { g_hnsum[i] = ps; g_hncnt[i] = pc; }
}

// final scalar combine (single block, deterministic)
__global__ void final_kernel(const float* __restrict__ bw, float* __restrict__ out) {
    __shared__ float sm[32];
    int tid = threadIdx.x;
    float v = 0.f;
    for (int i = tid; i < ECAP_; i += 512) v += g_clrow[i];
    float clsum = block_sum(v, sm);
    v = 0.f; float c = 0.f;
    for (int p = tid; p < MFN_ * MFN_; p += 512) { v += g_fnval[p]; c += g_fnflag[p]; }
    float fnsum = block_sum(v, sm);
    float fncnt = block_sum(c, sm);
    v = 0.f; c = 0.f;
    for (int i = tid; i < MHN_; i += 512) { v += g_hnsum[i]; c += g_hncnt[i]; }
    float hnsum = block_sum(v, sm);
    float hncnt = block_sum(c, sm);
    float d2 = 0.f, o2 = 0.f;
    for (int i = tid; i < SAMP_; i += 512) { d2 += g_topo[i * 2]; o2 += g_topo[i * 2 + 1]; }
    float D2 = block_sum(d2, sm);
    float O2 = block_sum(o2, sm);
    if (tid == 0) {
        float cl_loss = -clsum / (float)ECAP_;
        float fn_loss = (fncnt > 0.f) ? fnsum / fmaxf(fncnt, 1.f) : 0.f;
        float hard_loss = (hncnt > 0.f) ? hnsum / fmaxf(hncnt, 1.f) : 0.f;
        float nz = (float)g_nzc[0], nzp = (float)g_nzc[1];
        float sparsity = (nz > 0.f) ? nzp / fmaxf(nz, 1.f) : 1.f;
        float dn = sqrtf(D2), on = sqrtf(O2);
        float topo = (on > 0.f) ? expf(-ALPHA_F * dn / fmaxf(on, 1e-12f)) : 1.f;
        float retention = sparsity * topo;
        out[0] = bw[0] * (retention * cl_loss + fn_loss + hard_loss);
    }
}

// ---------------- launch ----------------
extern "C" void kernel_launch(void* const* d_in, const int* in_sizes, int n_in,
                              void* d_out, int out_size) {
    (void)in_sizes; (void)n_in; (void)out_size;
    const float* Ho  = (const float*)d_in[0];
    const float* Hp  = (const float*)d_in[1];
    const float* ne  = (const float*)d_in[2];
    const float* bw  = (const float*)d_in[3];
    const float* Wn1 = (const float*)d_in[4];
    const float* bn1 = (const float*)d_in[5];
    const float* Wn2 = (const float*)d_in[6];
    const float* bn2 = (const float*)d_in[7];
    const float* We1 = (const float*)d_in[8];
    const float* be1 = (const float*)d_in[9];
    const float* We2 = (const float*)d_in[10];
    const float* be2 = (const float*)d_in[11];
    float* out = (float*)d_out;

    void *p;
    float *p_tmp, *p_z, *p_znorm, *p_emean, *p_etmp, *p_hedges, *p_hnorm;
    cudaGetSymbolAddress(&p, g_tmp);    p_tmp    = (float*)p;
    cudaGetSymbolAddress(&p, g_z);      p_z      = (float*)p;
    cudaGetSymbolAddress(&p, g_znorm);  p_znorm  = (float*)p;
    cudaGetSymbolAddress(&p, g_emean);  p_emean  = (float*)p;
    cudaGetSymbolAddress(&p, g_etmp);   p_etmp   = (float*)p;
    cudaGetSymbolAddress(&p, g_hedges); p_hedges = (float*)p;
    cudaGetSymbolAddress(&p, g_hnorm);  p_hnorm  = (float*)p;

    init_kernel<<<40, 256>>>();
    count_nz_kernel<<<2048, 256>>>((const float4*)Ho, (const float4*)Hp);
    topo_kernel<<<SAMP_, 128>>>(Ho, Hp);

    // node MLP
    gemm128_kernel<true ><<<dim3(64, 2), 256>>>(ne,    Wn1, bn1, p_tmp, N_);
    gemm128_kernel<false><<<dim3(64, 2), 256>>>(p_tmp, Wn2, bn2, p_z,   N_);
    rownorm_kernel<<<N_ / 8, 256>>>(p_z, p_znorm, N_);

    // edge aggregation
    cnt_kernel<<<64, 512>>>(Hp);
    edge_gemm_kernel<<<dim3(4, 2, 8), 256>>>(Hp, p_z);
    edge_reduce_kernel<<<ECAP_, 256>>>();

    // edge MLP
    gemm128_kernel<true ><<<dim3(4, 2), 256>>>(p_emean, We1, be1, p_etmp,   ECAP_);
    gemm128_kernel<false><<<dim3(4, 2), 256>>>(p_etmp,  We2, be2, p_hedges, ECAP_);
    rownorm_kernel<<<(ECAP_ + 7) / 8, 256>>>(p_hedges, p_hnorm, ECAP_);

    // similarity / attention / logsumexp
    sim_kernel<<<MHN_, 256>>>();
    att_kernel<<<dim3(25, 8), 256>>>();
    lse_kernel<<<dim3(25, 8), 256>>>();
    att_merge_kernel<<<MHN_, 256>>>();
    lse_merge_kernel<<<1, 128>>>();

    // losses
    cl_kernel<<<ECAP_, 256>>>();
    fn_kernel<<<dim3(MFN_, MFN_), 256>>>(Ho, Hp);
    hn_kernel<<<MHN_, 256>>>();

    final_kernel<<<1, 512>>>(bw, out);
}

// round 3
// speedup vs baseline: 2.3790x; 1.0013x over previous
#include <cuda_runtime.h>
#include <math.h>
#include <cfloat>

// ---------------- constants ----------------
#define TAU_F   0.4f
#define ALPHA_F 1.0f
#define GAMMA_F 0.7f
#define DELTA_F 0.6f
#define MU_F    0.6f
#define NU_F    0.3f

#define N_  8192
#define E_  2048
#define D_  256
#define SAMP_ 100
#define MFN_  100
#define MHN_  200
#define ECAP_ 500

// ---------------- scratch (device globals) ----------------
__device__ float g_tmp[N_ * D_];
__device__ float g_z[N_ * D_];
__device__ float g_znorm[N_];
__device__ float g_emean[ECAP_ * D_];
__device__ float g_etmp[ECAP_ * D_];
__device__ float g_hedges[ECAP_ * D_];
__device__ float g_hnorm[ECAP_];
__device__ float g_sim[MHN_ * MHN_];
__device__ float g_attdot[MHN_ * MHN_];
__device__ float g_attm[MHN_ * 8], g_atts[MHN_ * 8];
__device__ float g_att[MHN_ * MHN_];
__device__ float g_lsem[MFN_ * 8], g_lses[MFN_ * 8];
__device__ float g_lse[MFN_];
__device__ float g_clrow[ECAP_];
__device__ float g_fnval[MFN_ * MFN_];
__device__ float g_fnflag[MFN_ * MFN_];
__device__ float g_hnsum[MHN_], g_hncnt[MHN_];
__device__ unsigned long long g_nzc[2];
__device__ float g_topo[SAMP_ * 2];

// ---------------- reduction helpers ----------------
__device__ __forceinline__ float warp_sum(float v) {
#pragma unroll
    for (int o = 16; o > 0; o >>= 1) v += __shfl_xor_sync(0xffffffffu, v, o);
    return v;
}
__device__ __forceinline__ float warp_max(float v) {
#pragma unroll
    for (int o = 16; o > 0; o >>= 1) v = fmaxf(v, __shfl_xor_sync(0xffffffffu, v, o));
    return v;
}
__device__ __forceinline__ int warp_sum_i(int v) {
#pragma unroll
    for (int o = 16; o > 0; o >>= 1) v += __shfl_xor_sync(0xffffffffu, v, o);
    return v;
}
__device__ float block_sum(float v, float* sm) {
    int w = threadIdx.x >> 5, lane = threadIdx.x & 31, nw = blockDim.x >> 5;
    v = warp_sum(v);
    if (lane == 0) sm[w] = v;
    __syncthreads();
    float r = (threadIdx.x < nw) ? sm[threadIdx.x] : 0.f;
    if (w == 0) r = warp_sum(r);
    if (threadIdx.x == 0) sm[0] = r;
    __syncthreads();
    r = sm[0];
    __syncthreads();
    return r;
}
__device__ float block_max(float v, float* sm) {
    int w = threadIdx.x >> 5, lane = threadIdx.x & 31, nw = blockDim.x >> 5;
    v = warp_max(v);
    if (lane == 0) sm[w] = v;
    __syncthreads();
    float r = (threadIdx.x < nw) ? sm[threadIdx.x] : -FLT_MAX;
    if (w == 0) r = warp_max(r);
    if (threadIdx.x == 0) sm[0] = r;
    __syncthreads();
    r = sm[0];
    __syncthreads();
    return r;
}

// ---------------- kernels ----------------

__global__ void init_kernel() {
    int i = blockIdx.x * 256 + threadIdx.x;
    if (i < 2) g_nzc[i] = 0ull;
    if (i < MFN_ * MFN_) { g_fnval[i] = 0.f; g_fnflag[i] = 0.f; }
}

__global__ void count_nz_kernel(const float4* __restrict__ a, const float4* __restrict__ b) {
    const int n4 = N_ * E_ / 4;
    int ca = 0, cb = 0;
    for (int i = blockIdx.x * blockDim.x + threadIdx.x; i < n4; i += gridDim.x * blockDim.x) {
        float4 x = a[i];
        ca += (x.x != 0.f) + (x.y != 0.f) + (x.z != 0.f) + (x.w != 0.f);
        float4 y = b[i];
        cb += (y.x != 0.f) + (y.y != 0.f) + (y.z != 0.f) + (y.w != 0.f);
    }
    __shared__ int sa[32], sb[32];
    int w = threadIdx.x >> 5, lane = threadIdx.x & 31;
    ca = warp_sum_i(ca); cb = warp_sum_i(cb);
    if (lane == 0) { sa[w] = ca; sb[w] = cb; }
    __syncthreads();
    if (w == 0) {
        int x = (lane < 8) ? sa[lane] : 0;
        int y = (lane < 8) ? sb[lane] : 0;
        x = warp_sum_i(x); y = warp_sum_i(y);
        if (lane == 0) {
            atomicAdd(&g_nzc[0], (unsigned long long)x);
            atomicAdd(&g_nzc[1], (unsigned long long)y);
        }
    }
}

// topology: one block per row i of the 100x100 sample
__global__ void topo_kernel(const float* __restrict__ Ho, const float* __restrict__ Hp) {
    __shared__ float hoi[128], hpi[128];
    __shared__ float sm[32];
    int i = blockIdx.x;
    int tid = threadIdx.x;   // 128 threads
    if (tid < SAMP_) { hoi[tid] = Ho[i * E_ + tid]; hpi[tid] = Hp[i * E_ + tid]; }
    else             { hoi[tid] = 0.f; hpi[tid] = 0.f; }
    __syncthreads();
    int w = tid >> 5, lane = tid & 31;
    float dn2 = 0.f, on2 = 0.f;
    for (int j = w; j < SAMP_; j += 4) {
        float as = 0.f, aps = 0.f;
#pragma unroll
        for (int t = 0; t < 4; t++) {
            int k = lane + 32 * t;
            if (k < SAMP_) {
                as  += hoi[k] * Ho[j * E_ + k];
                aps += hpi[k] * Hp[j * E_ + k];
            }
        }
        as = warp_sum(as);
        aps = warp_sum(aps);
        if (lane == 0) {
            float d = as - aps;
            dn2 += d * d;
            on2 += as * as;
        }
    }
    float D2 = block_sum(dn2, sm);
    float O2 = block_sum(on2, sm);
    if (tid == 0) { g_topo[i * 2] = D2; g_topo[i * 2 + 1] = O2; }
}

// node MLP GEMM: BM=128, BN=64, BK=16, 8x4 microtile, 256 threads. M multiple of 128.
template <bool RELU>
__global__ void gemm_nk_kernel(const float* __restrict__ A, const float* __restrict__ B,
                               const float* __restrict__ bias, float* __restrict__ C) {
    __shared__ float As[16][132];
    __shared__ float Bs[16][68];
    const int bm = blockIdx.x * 128, bn = blockIdx.y * 64;
    const int tid = threadIdx.x;
    const int tx = tid & 15, ty = tid >> 4;
    float acc[8][4] = {};
    for (int k0 = 0; k0 < D_; k0 += 16) {
#pragma unroll
        for (int l = 0; l < 2; l++) {
            int id = tid * 2 + l;
            int r = id >> 2, c4 = id & 3;
            float4 v = *(const float4*)&A[(bm + r) * D_ + k0 + c4 * 4];
            As[c4 * 4 + 0][r] = v.x;
            As[c4 * 4 + 1][r] = v.y;
            As[c4 * 4 + 2][r] = v.z;
            As[c4 * 4 + 3][r] = v.w;
        }
        {
            int r = tid >> 4, c4 = tid & 15;
            float4 v = *(const float4*)&B[(k0 + r) * D_ + bn + c4 * 4];
            *(float4*)&Bs[r][c4 * 4] = v;
        }
        __syncthreads();
#pragma unroll
        for (int kk = 0; kk < 16; kk++) {
            float a[8], b[4];
#pragma unroll
            for (int u = 0; u < 8; u++) a[u] = As[kk][ty * 8 + u];
#pragma unroll
            for (int u = 0; u < 4; u++) b[u] = Bs[kk][tx * 4 + u];
#pragma unroll
            for (int i = 0; i < 8; i++)
#pragma unroll
                for (int j = 0; j < 4; j++) acc[i][j] += a[i] * b[j];
        }
        __syncthreads();
    }
#pragma unroll
    for (int i = 0; i < 8; i++) {
        int row = bm + ty * 8 + i;
#pragma unroll
        for (int j = 0; j < 4; j++) {
            int col = bn + tx * 4 + j;
            float v = acc[i][j] + bias[col];
            if (RELU) v = fmaxf(v, 0.f);
            C[row * D_ + col] = v;
        }
    }
}

// small-M GEMM: BM=BN=64, BK=16, 4x4 microtile, 256 threads, row guards
template <bool RELU>
__global__ void gemm64_kernel(const float* __restrict__ A, const float* __restrict__ B,
                              const float* __restrict__ bias, float* __restrict__ C, int M) {
    __shared__ float As[16][68];
    __shared__ float Bs[16][68];
    const int bm = blockIdx.x * 64, bn = blockIdx.y * 64;
    const int tid = threadIdx.x;
    const int tx = tid & 15, ty = tid >> 4;
    float acc[4][4] = {};
    for (int k0 = 0; k0 < D_; k0 += 16) {
        {
            int r = tid >> 2, c4 = tid & 3;
            int row = bm + r;
            float4 v = make_float4(0.f, 0.f, 0.f, 0.f);
            if (row < M) v = *(const float4*)&A[row * D_ + k0 + c4 * 4];
            As[c4 * 4 + 0][r] = v.x;
            As[c4 * 4 + 1][r] = v.y;
            As[c4 * 4 + 2][r] = v.z;
            As[c4 * 4 + 3][r] = v.w;
        }
        {
            int r = tid >> 4, c4 = tid & 15;
            float4 v = *(const float4*)&B[(k0 + r) * D_ + bn + c4 * 4];
            *(float4*)&Bs[r][c4 * 4] = v;
        }
        __syncthreads();
#pragma unroll
        for (int kk = 0; kk < 16; kk++) {
            float a[4], b[4];
#pragma unroll
            for (int u = 0; u < 4; u++) a[u] = As[kk][ty * 4 + u];
#pragma unroll
            for (int u = 0; u < 4; u++) b[u] = Bs[kk][tx * 4 + u];
#pragma unroll
            for (int i = 0; i < 4; i++)
#pragma unroll
                for (int j = 0; j < 4; j++) acc[i][j] += a[i] * b[j];
        }
        __syncthreads();
    }
#pragma unroll
    for (int i = 0; i < 4; i++) {
        int row = bm + ty * 4 + i;
        if (row >= M) continue;
#pragma unroll
        for (int j = 0; j < 4; j++) {
            int col = bn + tx * 4 + j;
            float v = acc[i][j] + bias[col];
            if (RELU) v = fmaxf(v, 0.f);
            C[row * D_ + col] = v;
        }
    }
}

// per-row L2 norms (warp per row)
__global__ void rownorm_kernel(const float* __restrict__ X, float* __restrict__ nrm, int rows) {
    int r = blockIdx.x * 8 + (threadIdx.x >> 5);
    int lane = threadIdx.x & 31;
    if (r >= rows) return;
    float s = 0.f;
#pragma unroll
    for (int t = 0; t < 8; t++) { float v = X[r * D_ + lane + 32 * t]; s += v * v; }
    s = warp_sum(s);
    if (lane == 0) nrm[r] = fmaxf(sqrtf(s), 1e-8f);
}

// Sparse edge aggregation: block handles 4 edges (e0=4*bx), deterministic ascending-i sums.
// Produces g_emean directly (sum/cnt, zero when cnt==0). ECAP_=500=125*4 exactly.
__global__ void edge_sparse_kernel(const float* __restrict__ Hp, const float* __restrict__ z) {
    __shared__ short slist[256];
    __shared__ unsigned char smask[256];
    __shared__ int scnt[8];
    const int tid = threadIdx.x;
    const int lane = tid & 31, w = tid >> 5;
    const int e0 = blockIdx.x * 4;
    float a0 = 0.f, a1 = 0.f, a2 = 0.f, a3 = 0.f;
    int c0 = 0, c1 = 0, c2 = 0, c3 = 0;
    for (int i0 = 0; i0 < N_; i0 += 256) {
        float4 v = *(const float4*)&Hp[(i0 + tid) * E_ + e0];
        int m = (v.x > 0.f) | ((v.y > 0.f) << 1) | ((v.z > 0.f) << 2) | ((v.w > 0.f) << 3);
        unsigned b = __ballot_sync(0xffffffffu, m != 0);
        int pre = __popc(b & ((1u << lane) - 1u));
        if (m) { slist[w * 32 + pre] = (short)tid; smask[w * 32 + pre] = (unsigned char)m; }
        if (lane == 0) scnt[w] = __popc(b);
        __syncthreads();
#pragma unroll 1
        for (int w2 = 0; w2 < 8; w2++) {
            int n = scnt[w2];
            for (int k = 0; k < n; k++) {
                int t = slist[w2 * 32 + k];
                int mm = smask[w2 * 32 + k];
                float zv = z[(i0 + t) * D_ + tid];
                if (mm & 1) { a0 += zv; c0++; }
                if (mm & 2) { a1 += zv; c1++; }
                if (mm & 4) { a2 += zv; c2++; }
                if (mm & 8) { a3 += zv; c3++; }
            }
        }
        __syncthreads();
    }
    g_emean[(e0 + 0) * D_ + tid] = (c0 > 0) ? a0 / (float)c0 : 0.f;
    g_emean[(e0 + 1) * D_ + tid] = (c1 > 0) ? a1 / (float)c1 : 0.f;
    g_emean[(e0 + 2) * D_ + tid] = (c2 > 0) ? a2 / (float)c2 : 0.f;
    g_emean[(e0 + 3) * D_ + tid] = (c3 > 0) ? a3 / (float)c3 : 0.f;
}

// Fused att/sim/lse over j: grid (25 rowgroups, 8 j-splits)
// - att online softmax partials (m,s) for rows < 200 over all 8192 j
// - raw dots + sim stored for (i<200, j<200) in split 0
// - lse online partials for rows < 100 with v = d*inv_i*inv_j/TAU
__global__ void attlse_kernel() {
    __shared__ float zi[8][256];
    __shared__ float inv_i[8];
    __shared__ float smm[8][8], sms[8][8];
    __shared__ float smm2[8][8], sms2[8][8];
    const int rg = blockIdx.x, sp = blockIdx.y;
    const int tid = threadIdx.x;
    const int row0 = rg * 8;
#pragma unroll
    for (int r = 0; r < 8; r++) zi[r][tid] = g_z[(row0 + r) * D_ + tid];
    if (tid < 8) inv_i[tid] = 1.f / g_znorm[row0 + tid];
    __syncthreads();
    const int w = tid >> 5, lane = tid & 31;
    const bool anylse = (row0 < MFN_);
    float m[8], s[8], m2[8], s2[8];
#pragma unroll
    for (int r = 0; r < 8; r++) { m[r] = -FLT_MAX; s[r] = 0.f; m2[r] = -FLT_MAX; s2[r] = 0.f; }
    const int j0 = sp * 1024;
    for (int jj = w; jj < 1024; jj += 8) {
        int j = j0 + jj;
        float d[8];
#pragma unroll
        for (int r = 0; r < 8; r++) d[r] = 0.f;
#pragma unroll
        for (int t = 0; t < 8; t++) {
            int k = lane + 32 * t;
            float zj = g_z[j * D_ + k];
#pragma unroll
            for (int r = 0; r < 8; r++) d[r] += zi[r][k] * zj;
        }
#pragma unroll
        for (int r = 0; r < 8; r++) d[r] = warp_sum(d[r]);
        float invj = 1.f / g_znorm[j];
        if (sp == 0 && j < MHN_ && lane == 0) {
#pragma unroll
            for (int r = 0; r < 8; r++) {
                g_attdot[(row0 + r) * MHN_ + j] = d[r];
                g_sim[(row0 + r) * MHN_ + j] = d[r] * inv_i[r] * invj;
            }
        }
#pragma unroll
        for (int r = 0; r < 8; r++) {
            float x = d[r];
            if (x <= m[r]) s[r] += __expf(x - m[r]);
            else { s[r] = s[r] * __expf(m[r] - x) + 1.f; m[r] = x; }
        }
        if (anylse) {
            float sc = invj * (1.f / TAU_F);
#pragma unroll
            for (int r = 0; r < 8; r++) {
                if (row0 + r < MFN_) {
                    float v = d[r] * inv_i[r] * sc;
                    if (v <= m2[r]) s2[r] += __expf(v - m2[r]);
                    else { s2[r] = s2[r] * __expf(m2[r] - v) + 1.f; m2[r] = v; }
                }
            }
        }
    }
    if (lane == 0) {
#pragma unroll
        for (int r = 0; r < 8; r++) { smm[w][r] = m[r]; sms[w][r] = s[r]; smm2[w][r] = m2[r]; sms2[w][r] = s2[r]; }
    }
    __syncthreads();
    if (tid < 8) {
        float M = -FLT_MAX;
        for (int q = 0; q < 8; q++) M = fmaxf(M, smm[q][tid]);
        float S = 0.f;
        for (int q = 0; q < 8; q++) S += sms[q][tid] * __expf(smm[q][tid] - M);
        g_attm[(row0 + tid) * 8 + sp] = M;
        g_atts[(row0 + tid) * 8 + sp] = S;
        if (row0 + tid < MFN_) {
            float M2 = -FLT_MAX;
            for (int q = 0; q < 8; q++) M2 = fmaxf(M2, smm2[q][tid]);
            float S2 = 0.f;
            for (int q = 0; q < 8; q++) S2 += sms2[q][tid] * __expf(smm2[q][tid] - M2);
            g_lsem[(row0 + tid) * 8 + sp] = M2;
            g_lses[(row0 + tid) * 8 + sp] = S2;
        }
    }
}

__global__ void att_merge_kernel() {
    int i = blockIdx.x;
    __shared__ float Ms, Ss;
    if (threadIdx.x == 0) {
        float M = -FLT_MAX;
        for (int p = 0; p < 8; p++) M = fmaxf(M, g_attm[i * 8 + p]);
        float S = 0.f;
        for (int p = 0; p < 8; p++) S += g_atts[i * 8 + p] * __expf(g_attm[i * 8 + p] - M);
        Ms = M; Ss = S;
    }
    __syncthreads();
    for (int j = threadIdx.x; j < MHN_; j += blockDim.x)
        g_att[i * MHN_ + j] = __expf(g_attdot[i * MHN_ + j] - Ms) / Ss;
}

__global__ void lse_merge_kernel() {
    int i = threadIdx.x;
    if (i >= MFN_) return;
    float M = -FLT_MAX;
    for (int p = 0; p < 8; p++) M = fmaxf(M, g_lsem[i * 8 + p]);
    float S = 0.f;
    for (int p = 0; p < 8; p++) S += g_lses[i * 8 + p] * __expf(g_lsem[i * 8 + p] - M);
    g_lse[i] = M + logf(S);
}

// contrastive loss per row
__global__ void cl_kernel() {
    __shared__ float zi[256];
    __shared__ float logit[500];
    __shared__ float sm[32];
    int i = blockIdx.x, tid = threadIdx.x;
    zi[tid] = g_z[i * D_ + tid] / g_znorm[i];
    __syncthreads();
    int w = tid >> 5, lane = tid & 31;
    for (int j = w; j < ECAP_; j += 8) {
        float s = 0.f;
#pragma unroll
        for (int t = 0; t < 8; t++) { int k = lane + 32 * t; s += zi[k] * g_hedges[j * D_ + k]; }
        s = warp_sum(s);
        if (lane == 0) logit[j] = s / (g_hnorm[j] * TAU_F);
    }
    __syncthreads();
    float lm = -FLT_MAX;
    for (int j = tid; j < ECAP_; j += 256) lm = fmaxf(lm, logit[j]);
    float M = block_max(lm, sm);
    float ls = 0.f;
    for (int j = tid; j < ECAP_; j += 256) ls += __expf(logit[j] - M);
    float S = block_sum(ls, sm);
    if (tid == 0) g_clrow[i] = logit[i] - (M + logf(S));
}

// false-negative pairs
__global__ void fn_kernel(const float* __restrict__ Ho, const float* __restrict__ Hp) {
    int j = blockIdx.x, i = blockIdx.y;
    if (j <= i) return;
    float simv = g_sim[i * MHN_ + j];
    float attv = g_att[i * MHN_ + j];
    if (!(simv > GAMMA_F && attv > DELTA_F)) return;
    __shared__ float sm[32];
    float ao = 0.f, ap = 0.f;
    for (int k = threadIdx.x; k < E_; k += 256) {
        ao += Ho[i * E_ + k] * Ho[j * E_ + k];
        ap += Hp[i * E_ + k] * Hp[j * E_ + k];
    }
    ao = block_sum(ao, sm);
    ap = block_sum(ap, sm);
    if (threadIdx.x == 0 && ap == 0.f && ao > 0.f) {
        g_fnval[i * MFN_ + j] = -(simv / TAU_F - g_lse[i]);
        g_fnflag[i * MFN_ + j] = 1.f;
    }
}

// hard-negative loss per row
__global__ void hn_kernel() {
    __shared__ float sm[32];
    int i = blockIdx.x;
    int j = threadIdx.x;
    bool act = j < MHN_;
    float simv = act ? g_sim[i * MHN_ + j] : 0.f;
    float attv = act ? g_att[i * MHN_ + j] : 1.f;
    bool mask = act && (j != i) && (simv > MU_F) && (attv < NU_F);
    float neg = -simv / TAU_F;
    float m = block_max(mask ? neg : -FLT_MAX, sm);
    if (m == -FLT_MAX) {
        if (threadIdx.x == 0) { g_hnsum[i] = 0.f; g_hncnt[i] = 0.f; }
        return;
    }
    float s = block_sum(mask ? expf(neg - m) : 0.f, sm);
    float lse = m + logf(s);
    float wgt = fminf(simv / MU_F, 1.f);
    float pair = -wgt * (neg - lse);
    float ps = block_sum(mask ? pair : 0.f, sm);
    float pc = block_sum(mask ? 1.f : 0.f, sm);
    if (threadIdx.x == 0) { g_hnsum[i] = ps; g_hncnt[i] = pc; }
}

// final combine (single block, deterministic)
__global__ void final_kernel(const float* __restrict__ bw, float* __restrict__ out) {
    __shared__ float sm[32];
    int tid = threadIdx.x;
    float v = 0.f;
    for (int i = tid; i < ECAP_; i += 512) v += g_clrow[i];
    float clsum = block_sum(v, sm);
    v = 0.f; float c = 0.f;
    for (int p = tid; p < MFN_ * MFN_; p += 512) { v += g_fnval[p]; c += g_fnflag[p]; }
    float fnsum = block_sum(v, sm);
    float fncnt = block_sum(c, sm);
    v = 0.f; c = 0.f;
    for (int i = tid; i < MHN_; i += 512) { v += g_hnsum[i]; c += g_hncnt[i]; }
    float hnsum = block_sum(v, sm);
    float hncnt = block_sum(c, sm);
    float d2 = 0.f, o2 = 0.f;
    for (int i = tid; i < SAMP_; i += 512) { d2 += g_topo[i * 2]; o2 += g_topo[i * 2 + 1]; }
    float D2 = block_sum(d2, sm);
    float O2 = block_sum(o2, sm);
    if (tid == 0) {
        float cl_loss = -clsum / (float)ECAP_;
        float fn_loss = (fncnt > 0.f) ? fnsum / fmaxf(fncnt, 1.f) : 0.f;
        float hard_loss = (hncnt > 0.f) ? hnsum / fmaxf(hncnt, 1.f) : 0.f;
        float nz = (float)g_nzc[0], nzp = (float)g_nzc[1];
        float sparsity = (nz > 0.f) ? nzp / fmaxf(nz, 1.f) : 1.f;
        float dn = sqrtf(D2), on = sqrtf(O2);
        float topo = (on > 0.f) ? expf(-ALPHA_F * dn / fmaxf(on, 1e-12f)) : 1.f;
        float retention = sparsity * topo;
        out[0] = bw[0] * (retention * cl_loss + fn_loss + hard_loss);
    }
}

// ---------------- launch ----------------
extern "C" void kernel_launch(void* const* d_in, const int* in_sizes, int n_in,
                              void* d_out, int out_size) {
    (void)in_sizes; (void)n_in; (void)out_size;
    const float* Ho  = (const float*)d_in[0];
    const float* Hp  = (const float*)d_in[1];
    const float* ne  = (const float*)d_in[2];
    const float* bw  = (const float*)d_in[3];
    const float* Wn1 = (const float*)d_in[4];
    const float* bn1 = (const float*)d_in[5];
    const float* Wn2 = (const float*)d_in[6];
    const float* bn2 = (const float*)d_in[7];
    const float* We1 = (const float*)d_in[8];
    const float* be1 = (const float*)d_in[9];
    const float* We2 = (const float*)d_in[10];
    const float* be2 = (const float*)d_in[11];
    float* out = (float*)d_out;

    void *p;
    float *p_tmp, *p_z, *p_znorm, *p_emean, *p_etmp, *p_hedges, *p_hnorm;
    cudaGetSymbolAddress(&p, g_tmp);    p_tmp    = (float*)p;
    cudaGetSymbolAddress(&p, g_z);      p_z      = (float*)p;
    cudaGetSymbolAddress(&p, g_znorm);  p_znorm  = (float*)p;
    cudaGetSymbolAddress(&p, g_emean);  p_emean  = (float*)p;
    cudaGetSymbolAddress(&p, g_etmp);   p_etmp   = (float*)p;
    cudaGetSymbolAddress(&p, g_hedges); p_hedges = (float*)p;
    cudaGetSymbolAddress(&p, g_hnorm);  p_hnorm  = (float*)p;

    init_kernel<<<40, 256>>>();
    count_nz_kernel<<<2048, 256>>>((const float4*)Ho, (const float4*)Hp);
    topo_kernel<<<SAMP_, 128>>>(Ho, Hp);

    // node MLP
    gemm_nk_kernel<true ><<<dim3(64, 4), 256>>>(ne,    Wn1, bn1, p_tmp);
    gemm_nk_kernel<false><<<dim3(64, 4), 256>>>(p_tmp, Wn2, bn2, p_z);
    rownorm_kernel<<<N_ / 8, 256>>>(p_z, p_znorm, N_);

    // sparse edge aggregation (sum + count + mean in one)
    edge_sparse_kernel<<<ECAP_ / 4, 256>>>(Hp, p_z);

    // edge MLP (small M)
    gemm64_kernel<true ><<<dim3(8, 4), 256>>>(p_emean, We1, be1, p_etmp,   ECAP_);
    gemm64_kernel<false><<<dim3(8, 4), 256>>>(p_etmp,  We2, be2, p_hedges, ECAP_);
    rownorm_kernel<<<(ECAP_ + 7) / 8, 256>>>(p_hedges, p_hnorm, ECAP_);

    // fused attention / sim / lse
    attlse_kernel<<<dim3(25, 8), 256>>>();
    att_merge_kernel<<<MHN_, 256>>>();
    lse_merge_kernel<<<1, 128>>>();

    // losses
    cl_kernel<<<ECAP_, 256>>>();
    fn_kernel<<<dim3(MFN_, MFN_), 256>>>(Ho, Hp);
    hn_kernel<<<MHN_, 256>>>();

    final_kernel<<<1, 512>>>(bw, out);
}

// round 4
// speedup vs baseline: 2.6608x; 1.1185x over previous
#include <cuda_runtime.h>
#include <math.h>
#include <cfloat>

// ---------------- constants ----------------
#define TAU_F   0.4f
#define ALPHA_F 1.0f
#define GAMMA_F 0.7f
#define DELTA_F 0.6f
#define MU_F    0.6f
#define NU_F    0.3f

#define N_  8192
#define E_  2048
#define D_  256
#define SAMP_ 100
#define MFN_  100
#define MHN_  200
#define ECAP_ 500

// ---------------- scratch (device globals) ----------------
__device__ float g_tmp[N_ * D_];
__device__ float g_z[N_ * D_];
__device__ float g_znorm[N_];
__device__ float g_edge_part[8][512 * D_];
__device__ int   g_cntp[8][512];
__device__ float g_emean[ECAP_ * D_];
__device__ float g_etmp[ECAP_ * D_];
__device__ float g_hedges[ECAP_ * D_];
__device__ float g_hnorm[ECAP_];
__device__ float g_sim[MHN_ * MHN_];
__device__ float g_attdot[MHN_ * MHN_];
__device__ float g_attm[MHN_ * 8], g_atts[MHN_ * 8];
__device__ float g_att[MHN_ * MHN_];
__device__ float g_lsem[MFN_ * 8], g_lses[MFN_ * 8];
__device__ float g_lse[MFN_];
__device__ float g_clrow[ECAP_];
__device__ float g_fnval[MFN_ * MFN_];
__device__ float g_fnflag[MFN_ * MFN_];
__device__ float g_hnsum[MHN_], g_hncnt[MHN_];
__device__ unsigned long long g_nzc[2];
__device__ float g_topo[SAMP_ * 2];

// ---------------- reduction helpers ----------------
__device__ __forceinline__ float warp_sum(float v) {
#pragma unroll
    for (int o = 16; o > 0; o >>= 1) v += __shfl_xor_sync(0xffffffffu, v, o);
    return v;
}
__device__ __forceinline__ float warp_max(float v) {
#pragma unroll
    for (int o = 16; o > 0; o >>= 1) v = fmaxf(v, __shfl_xor_sync(0xffffffffu, v, o));
    return v;
}
__device__ __forceinline__ int warp_sum_i(int v) {
#pragma unroll
    for (int o = 16; o > 0; o >>= 1) v += __shfl_xor_sync(0xffffffffu, v, o);
    return v;
}
__device__ float block_sum(float v, float* sm) {
    int w = threadIdx.x >> 5, lane = threadIdx.x & 31, nw = blockDim.x >> 5;
    v = warp_sum(v);
    if (lane == 0) sm[w] = v;
    __syncthreads();
    float r = (threadIdx.x < nw) ? sm[threadIdx.x] : 0.f;
    if (w == 0) r = warp_sum(r);
    if (threadIdx.x == 0) sm[0] = r;
    __syncthreads();
    r = sm[0];
    __syncthreads();
    return r;
}
__device__ float block_max(float v, float* sm) {
    int w = threadIdx.x >> 5, lane = threadIdx.x & 31, nw = blockDim.x >> 5;
    v = warp_max(v);
    if (lane == 0) sm[w] = v;
    __syncthreads();
    float r = (threadIdx.x < nw) ? sm[threadIdx.x] : -FLT_MAX;
    if (w == 0) r = warp_max(r);
    if (threadIdx.x == 0) sm[0] = r;
    __syncthreads();
    r = sm[0];
    __syncthreads();
    return r;
}

// ---------------- kernels ----------------

__global__ void init_kernel() {
    int i = blockIdx.x * 256 + threadIdx.x;
    if (i < 2) g_nzc[i] = 0ull;
    if (i < MFN_ * MFN_) { g_fnval[i] = 0.f; g_fnflag[i] = 0.f; }
}

__global__ void count_nz_kernel(const float4* __restrict__ a, const float4* __restrict__ b) {
    const int n4 = N_ * E_ / 4;
    int ca = 0, cb = 0;
    for (int i = blockIdx.x * blockDim.x + threadIdx.x; i < n4; i += gridDim.x * blockDim.x) {
        float4 x = a[i];
        ca += (x.x != 0.f) + (x.y != 0.f) + (x.z != 0.f) + (x.w != 0.f);
        float4 y = b[i];
        cb += (y.x != 0.f) + (y.y != 0.f) + (y.z != 0.f) + (y.w != 0.f);
    }
    __shared__ int sa[32], sb[32];
    int w = threadIdx.x >> 5, lane = threadIdx.x & 31;
    ca = warp_sum_i(ca); cb = warp_sum_i(cb);
    if (lane == 0) { sa[w] = ca; sb[w] = cb; }
    __syncthreads();
    if (w == 0) {
        int x = (lane < 8) ? sa[lane] : 0;
        int y = (lane < 8) ? sb[lane] : 0;
        x = warp_sum_i(x); y = warp_sum_i(y);
        if (lane == 0) {
            atomicAdd(&g_nzc[0], (unsigned long long)x);
            atomicAdd(&g_nzc[1], (unsigned long long)y);
        }
    }
}

// topology: one block per row i of the 100x100 sample
__global__ void topo_kernel(const float* __restrict__ Ho, const float* __restrict__ Hp) {
    __shared__ float hoi[128], hpi[128];
    __shared__ float sm[32];
    int i = blockIdx.x;
    int tid = threadIdx.x;
    if (tid < SAMP_) { hoi[tid] = Ho[i * E_ + tid]; hpi[tid] = Hp[i * E_ + tid]; }
    else             { hoi[tid] = 0.f; hpi[tid] = 0.f; }
    __syncthreads();
    int w = tid >> 5, lane = tid & 31;
    float dn2 = 0.f, on2 = 0.f;
    for (int j = w; j < SAMP_; j += 4) {
        float as = 0.f, aps = 0.f;
#pragma unroll
        for (int t = 0; t < 4; t++) {
            int k = lane + 32 * t;
            if (k < SAMP_) {
                as  += hoi[k] * Ho[j * E_ + k];
                aps += hpi[k] * Hp[j * E_ + k];
            }
        }
        as = warp_sum(as);
        aps = warp_sum(aps);
        if (lane == 0) {
            float d = as - aps;
            dn2 += d * d;
            on2 += as * as;
        }
    }
    float D2 = block_sum(dn2, sm);
    float O2 = block_sum(on2, sm);
    if (tid == 0) { g_topo[i * 2] = D2; g_topo[i * 2 + 1] = O2; }
}

// node MLP GEMM: BM=128, BN=64, BK=16, 8x4 microtile, 256 threads
template <bool RELU>
__global__ void gemm_nk_kernel(const float* __restrict__ A, const float* __restrict__ B,
                               const float* __restrict__ bias, float* __restrict__ C) {
    __shared__ float As[16][132];
    __shared__ float Bs[16][68];
    const int bm = blockIdx.x * 128, bn = blockIdx.y * 64;
    const int tid = threadIdx.x;
    const int tx = tid & 15, ty = tid >> 4;
    float acc[8][4] = {};
    for (int k0 = 0; k0 < D_; k0 += 16) {
#pragma unroll
        for (int l = 0; l < 2; l++) {
            int id = tid * 2 + l;
            int r = id >> 2, c4 = id & 3;
            float4 v = *(const float4*)&A[(bm + r) * D_ + k0 + c4 * 4];
            As[c4 * 4 + 0][r] = v.x;
            As[c4 * 4 + 1][r] = v.y;
            As[c4 * 4 + 2][r] = v.z;
            As[c4 * 4 + 3][r] = v.w;
        }
        {
            int r = tid >> 4, c4 = tid & 15;
            float4 v = *(const float4*)&B[(k0 + r) * D_ + bn + c4 * 4];
            *(float4*)&Bs[r][c4 * 4] = v;
        }
        __syncthreads();
#pragma unroll
        for (int kk = 0; kk < 16; kk++) {
            float a[8], b[4];
#pragma unroll
            for (int u = 0; u < 8; u++) a[u] = As[kk][ty * 8 + u];
#pragma unroll
            for (int u = 0; u < 4; u++) b[u] = Bs[kk][tx * 4 + u];
#pragma unroll
            for (int i = 0; i < 8; i++)
#pragma unroll
                for (int j = 0; j < 4; j++) acc[i][j] += a[i] * b[j];
        }
        __syncthreads();
    }
#pragma unroll
    for (int i = 0; i < 8; i++) {
        int row = bm + ty * 8 + i;
#pragma unroll
        for (int j = 0; j < 4; j++) {
            int col = bn + tx * 4 + j;
            float v = acc[i][j] + bias[col];
            if (RELU) v = fmaxf(v, 0.f);
            C[row * D_ + col] = v;
        }
    }
}

// small-M GEMM: BM=BN=64, BK=16, 4x4 microtile, 256 threads, row guards
template <bool RELU>
__global__ void gemm64_kernel(const float* __restrict__ A, const float* __restrict__ B,
                              const float* __restrict__ bias, float* __restrict__ C, int M) {
    __shared__ float As[16][68];
    __shared__ float Bs[16][68];
    const int bm = blockIdx.x * 64, bn = blockIdx.y * 64;
    const int tid = threadIdx.x;
    const int tx = tid & 15, ty = tid >> 4;
    float acc[4][4] = {};
    for (int k0 = 0; k0 < D_; k0 += 16) {
        {
            int r = tid >> 2, c4 = tid & 3;
            int row = bm + r;
            float4 v = make_float4(0.f, 0.f, 0.f, 0.f);
            if (row < M) v = *(const float4*)&A[row * D_ + k0 + c4 * 4];
            As[c4 * 4 + 0][r] = v.x;
            As[c4 * 4 + 1][r] = v.y;
            As[c4 * 4 + 2][r] = v.z;
            As[c4 * 4 + 3][r] = v.w;
        }
        {
            int r = tid >> 4, c4 = tid & 15;
            float4 v = *(const float4*)&B[(k0 + r) * D_ + bn + c4 * 4];
            *(float4*)&Bs[r][c4 * 4] = v;
        }
        __syncthreads();
#pragma unroll
        for (int kk = 0; kk < 16; kk++) {
            float a[4], b[4];
#pragma unroll
            for (int u = 0; u < 4; u++) a[u] = As[kk][ty * 4 + u];
#pragma unroll
            for (int u = 0; u < 4; u++) b[u] = Bs[kk][tx * 4 + u];
#pragma unroll
            for (int i = 0; i < 4; i++)
#pragma unroll
                for (int j = 0; j < 4; j++) acc[i][j] += a[i] * b[j];
        }
        __syncthreads();
    }
#pragma unroll
    for (int i = 0; i < 4; i++) {
        int row = bm + ty * 4 + i;
        if (row >= M) continue;
#pragma unroll
        for (int j = 0; j < 4; j++) {
            int col = bn + tx * 4 + j;
            float v = acc[i][j] + bias[col];
            if (RELU) v = fmaxf(v, 0.f);
            C[row * D_ + col] = v;
        }
    }
}

// per-row L2 norms (warp per row)
__global__ void rownorm_kernel(const float* __restrict__ X, float* __restrict__ nrm, int rows) {
    int r = blockIdx.x * 8 + (threadIdx.x >> 5);
    int lane = threadIdx.x & 31;
    if (r >= rows) return;
    float s = 0.f;
#pragma unroll
    for (int t = 0; t < 8; t++) { float v = X[r * D_ + lane + 32 * t]; s += v * v; }
    s = warp_sum(s);
    if (lane == 0) nrm[r] = fmaxf(sqrtf(s), 1e-8f);
}

// Sparse edge aggregation partials: grid (125 edge-groups, 8 i-splits).
// Each block: 4 edges, 1024 rows. Deterministic ascending-i order within split.
__global__ void edge_part_kernel(const float* __restrict__ Hp, const float* __restrict__ z) {
    __shared__ short slist[256];
    __shared__ unsigned char smask[256];
    __shared__ int scnt[8];
    const int tid = threadIdx.x;
    const int lane = tid & 31, w = tid >> 5;
    const int e0 = blockIdx.x * 4, sp = blockIdx.y;
    float a0 = 0.f, a1 = 0.f, a2 = 0.f, a3 = 0.f;
    int c0 = 0, c1 = 0, c2 = 0, c3 = 0;
    const int ibase = sp * 1024;
    for (int ic = 0; ic < 1024; ic += 256) {
        int i0 = ibase + ic;
        float4 v = *(const float4*)&Hp[(size_t)(i0 + tid) * E_ + e0];
        int m = (v.x > 0.f) | ((v.y > 0.f) << 1) | ((v.z > 0.f) << 2) | ((v.w > 0.f) << 3);
        unsigned b = __ballot_sync(0xffffffffu, m != 0);
        int pre = __popc(b & ((1u << lane) - 1u));
        if (m) { slist[w * 32 + pre] = (short)tid; smask[w * 32 + pre] = (unsigned char)m; }
        if (lane == 0) scnt[w] = __popc(b);
        __syncthreads();
#pragma unroll 1
        for (int w2 = 0; w2 < 8; w2++) {
            int n = scnt[w2];
            for (int k = 0; k < n; k++) {
                int t = slist[w2 * 32 + k];
                int mm = smask[w2 * 32 + k];
                float zv = z[(size_t)(i0 + t) * D_ + tid];
                if (mm & 1) { a0 += zv; c0++; }
                if (mm & 2) { a1 += zv; c1++; }
                if (mm & 4) { a2 += zv; c2++; }
                if (mm & 8) { a3 += zv; c3++; }
            }
        }
        __syncthreads();
    }
    g_edge_part[sp][(e0 + 0) * D_ + tid] = a0;
    g_edge_part[sp][(e0 + 1) * D_ + tid] = a1;
    g_edge_part[sp][(e0 + 2) * D_ + tid] = a2;
    g_edge_part[sp][(e0 + 3) * D_ + tid] = a3;
    if (tid == 0) {
        g_cntp[sp][e0 + 0] = c0;
        g_cntp[sp][e0 + 1] = c1;
        g_cntp[sp][e0 + 2] = c2;
        g_cntp[sp][e0 + 3] = c3;
    }
}

// deterministic fixed-order reduce of split partials -> mean
__global__ void edge_reduce_kernel() {
    int e = blockIdx.x, d = threadIdx.x;
    float s = 0.f;
#pragma unroll
    for (int p = 0; p < 8; p++) s += g_edge_part[p][e * D_ + d];
    int c = 0;
#pragma unroll
    for (int p = 0; p < 8; p++) c += g_cntp[p][e];
    g_emean[e * D_ + d] = (c > 0) ? s / (float)c : 0.f;
}

// Fused att/sim/lse over j: grid (25 rowgroups, 8 j-splits)
__global__ void attlse_kernel() {
    __shared__ float zi[8][256];
    __shared__ float inv_i[8];
    __shared__ float smm[8][8], sms[8][8];
    __shared__ float smm2[8][8], sms2[8][8];
    const int rg = blockIdx.x, sp = blockIdx.y;
    const int tid = threadIdx.x;
    const int row0 = rg * 8;
#pragma unroll
    for (int r = 0; r < 8; r++) zi[r][tid] = g_z[(row0 + r) * D_ + tid];
    if (tid < 8) inv_i[tid] = 1.f / g_znorm[row0 + tid];
    __syncthreads();
    const int w = tid >> 5, lane = tid & 31;
    const bool anylse = (row0 < MFN_);
    float m[8], s[8], m2[8], s2[8];
#pragma unroll
    for (int r = 0; r < 8; r++) { m[r] = -FLT_MAX; s[r] = 0.f; m2[r] = -FLT_MAX; s2[r] = 0.f; }
    const int j0 = sp * 1024;
    for (int jj = w; jj < 1024; jj += 8) {
        int j = j0 + jj;
        float d[8];
#pragma unroll
        for (int r = 0; r < 8; r++) d[r] = 0.f;
#pragma unroll
        for (int t = 0; t < 8; t++) {
            int k = lane + 32 * t;
            float zj = g_z[j * D_ + k];
#pragma unroll
            for (int r = 0; r < 8; r++) d[r] += zi[r][k] * zj;
        }
#pragma unroll
        for (int r = 0; r < 8; r++) d[r] = warp_sum(d[r]);
        float invj = 1.f / g_znorm[j];
        if (sp == 0 && j < MHN_ && lane == 0) {
#pragma unroll
            for (int r = 0; r < 8; r++) {
                g_attdot[(row0 + r) * MHN_ + j] = d[r];
                g_sim[(row0 + r) * MHN_ + j] = d[r] * inv_i[r] * invj;
            }
        }
#pragma unroll
        for (int r = 0; r < 8; r++) {
            float x = d[r];
            if (x <= m[r]) s[r] += __expf(x - m[r]);
            else { s[r] = s[r] * __expf(m[r] - x) + 1.f; m[r] = x; }
        }
        if (anylse) {
            float sc = invj * (1.f / TAU_F);
#pragma unroll
            for (int r = 0; r < 8; r++) {
                if (row0 + r < MFN_) {
                    float v = d[r] * inv_i[r] * sc;
                    if (v <= m2[r]) s2[r] += __expf(v - m2[r]);
                    else { s2[r] = s2[r] * __expf(m2[r] - v) + 1.f; m2[r] = v; }
                }
            }
        }
    }
    if (lane == 0) {
#pragma unroll
        for (int r = 0; r < 8; r++) { smm[w][r] = m[r]; sms[w][r] = s[r]; smm2[w][r] = m2[r]; sms2[w][r] = s2[r]; }
    }
    __syncthreads();
    if (tid < 8) {
        float M = -FLT_MAX;
        for (int q = 0; q < 8; q++) M = fmaxf(M, smm[q][tid]);
        float S = 0.f;
        for (int q = 0; q < 8; q++) S += sms[q][tid] * __expf(smm[q][tid] - M);
        g_attm[(row0 + tid) * 8 + sp] = M;
        g_atts[(row0 + tid) * 8 + sp] = S;
        if (row0 + tid < MFN_) {
            float M2 = -FLT_MAX;
            for (int q = 0; q < 8; q++) M2 = fmaxf(M2, smm2[q][tid]);
            float S2 = 0.f;
            for (int q = 0; q < 8; q++) S2 += sms2[q][tid] * __expf(smm2[q][tid] - M2);
            g_lsem[(row0 + tid) * 8 + sp] = M2;
            g_lses[(row0 + tid) * 8 + sp] = S2;
        }
    }
}

// merged att softmax finalize (blocks 0..199) + lse finalize (block 200)
__global__ void merge_kernel() {
    int b = blockIdx.x;
    if (b < MHN_) {
        int i = b;
        __shared__ float Ms, Ss;
        if (threadIdx.x == 0) {
            float M = -FLT_MAX;
            for (int p = 0; p < 8; p++) M = fmaxf(M, g_attm[i * 8 + p]);
            float S = 0.f;
            for (int p = 0; p < 8; p++) S += g_atts[i * 8 + p] * __expf(g_attm[i * 8 + p] - M);
            Ms = M; Ss = S;
        }
        __syncthreads();
        for (int j = threadIdx.x; j < MHN_; j += blockDim.x)
            g_att[i * MHN_ + j] = __expf(g_attdot[i * MHN_ + j] - Ms) / Ss;
    } else {
        int i = threadIdx.x;
        if (i < MFN_) {
            float M = -FLT_MAX;
            for (int p = 0; p < 8; p++) M = fmaxf(M, g_lsem[i * 8 + p]);
            float S = 0.f;
            for (int p = 0; p < 8; p++) S += g_lses[i * 8 + p] * __expf(g_lsem[i * 8 + p] - M);
            g_lse[i] = M + logf(S);
        }
    }
}

// contrastive loss per row
__global__ void cl_kernel() {
    __shared__ float zi[256];
    __shared__ float logit[500];
    __shared__ float sm[32];
    int i = blockIdx.x, tid = threadIdx.x;
    zi[tid] = g_z[i * D_ + tid] / g_znorm[i];
    __syncthreads();
    int w = tid >> 5, lane = tid & 31;
    for (int j = w; j < ECAP_; j += 8) {
        float s = 0.f;
#pragma unroll
        for (int t = 0; t < 8; t++) { int k = lane + 32 * t; s += zi[k] * g_hedges[j * D_ + k]; }
        s = warp_sum(s);
        if (lane == 0) logit[j] = s / (g_hnorm[j] * TAU_F);
    }
    __syncthreads();
    float lm = -FLT_MAX;
    for (int j = tid; j < ECAP_; j += 256) lm = fmaxf(lm, logit[j]);
    float M = block_max(lm, sm);
    float ls = 0.f;
    for (int j = tid; j < ECAP_; j += 256) ls += __expf(logit[j] - M);
    float S = block_sum(ls, sm);
    if (tid == 0) g_clrow[i] = logit[i] - (M + logf(S));
}

// false-negative pairs
__global__ void fn_kernel(const float* __restrict__ Ho, const float* __restrict__ Hp) {
    int j = blockIdx.x, i = blockIdx.y;
    if (j <= i) return;
    float simv = g_sim[i * MHN_ + j];
    float attv = g_att[i * MHN_ + j];
    if (!(simv > GAMMA_F && attv > DELTA_F)) return;
    __shared__ float sm[32];
    float ao = 0.f, ap = 0.f;
    for (int k = threadIdx.x; k < E_; k += 256) {
        ao += Ho[i * E_ + k] * Ho[j * E_ + k];
        ap += Hp[i * E_ + k] * Hp[j * E_ + k];
    }
    ao = block_sum(ao, sm);
    ap = block_sum(ap, sm);
    if (threadIdx.x == 0 && ap == 0.f && ao > 0.f) {
        g_fnval[i * MFN_ + j] = -(simv / TAU_F - g_lse[i]);
        g_fnflag[i * MFN_ + j] = 1.f;
    }
}

// hard-negative loss per row
__global__ void hn_kernel() {
    __shared__ float sm[32];
    int i = blockIdx.x;
    int j = threadIdx.x;
    bool act = j < MHN_;
    float simv = act ? g_sim[i * MHN_ + j] : 0.f;
    float attv = act ? g_att[i * MHN_ + j] : 1.f;
    bool mask = act && (j != i) && (simv > MU_F) && (attv < NU_F);
    float neg = -simv / TAU_F;
    float m = block_max(mask ? neg : -FLT_MAX, sm);
    if (m == -FLT_MAX) {
        if (threadIdx.x == 0) { g_hnsum[i] = 0.f; g_hncnt[i] = 0.f; }
        return;
    }
    float s = block_sum(mask ? expf(neg - m) : 0.f, sm);
    float lse = m + logf(s);
    float wgt = fminf(simv / MU_F, 1.f);
    float pair = -wgt * (neg - lse);
    float ps = block_sum(mask ? pair : 0.f, sm);
    float pc = block_sum(mask ? 1.f : 0.f, sm);
    if (threadIdx.x == 0) { g_hnsum[i] = ps; g_hncnt[i] = pc; }
}

// final combine (single block, deterministic)
__global__ void final_kernel(const float* __restrict__ bw, float* __restrict__ out) {
    __shared__ float sm[32];
    int tid = threadIdx.x;
    float v = 0.f;
    for (int i = tid; i < ECAP_; i += 512) v += g_clrow[i];
    float clsum = block_sum(v, sm);
    v = 0.f; float c = 0.f;
    for (int p = tid; p < MFN_ * MFN_; p += 512) { v += g_fnval[p]; c += g_fnflag[p]; }
    float fnsum = block_sum(v, sm);
    float fncnt = block_sum(c, sm);
    v = 0.f; c = 0.f;
    for (int i = tid; i < MHN_; i += 512) { v += g_hnsum[i]; c += g_hncnt[i]; }
    float hnsum = block_sum(v, sm);
    float hncnt = block_sum(c, sm);
    float d2 = 0.f, o2 = 0.f;
    for (int i = tid; i < SAMP_; i += 512) { d2 += g_topo[i * 2]; o2 += g_topo[i * 2 + 1]; }
    float D2 = block_sum(d2, sm);
    float O2 = block_sum(o2, sm);
    if (tid == 0) {
        float cl_loss = -clsum / (float)ECAP_;
        float fn_loss = (fncnt > 0.f) ? fnsum / fmaxf(fncnt, 1.f) : 0.f;
        float hard_loss = (hncnt > 0.f) ? hnsum / fmaxf(hncnt, 1.f) : 0.f;
        float nz = (float)g_nzc[0], nzp = (float)g_nzc[1];
        float sparsity = (nz > 0.f) ? nzp / fmaxf(nz, 1.f) : 1.f;
        float dn = sqrtf(D2), on = sqrtf(O2);
        float topo = (on > 0.f) ? expf(-ALPHA_F * dn / fmaxf(on, 1e-12f)) : 1.f;
        float retention = sparsity * topo;
        out[0] = bw[0] * (retention * cl_loss + fn_loss + hard_loss);
    }
}

// ---------------- launch ----------------
extern "C" void kernel_launch(void* const* d_in, const int* in_sizes, int n_in,
                              void* d_out, int out_size) {
    (void)in_sizes; (void)n_in; (void)out_size;
    const float* Ho  = (const float*)d_in[0];
    const float* Hp  = (const float*)d_in[1];
    const float* ne  = (const float*)d_in[2];
    const float* bw  = (const float*)d_in[3];
    const float* Wn1 = (const float*)d_in[4];
    const float* bn1 = (const float*)d_in[5];
    const float* Wn2 = (const float*)d_in[6];
    const float* bn2 = (const float*)d_in[7];
    const float* We1 = (const float*)d_in[8];
    const float* be1 = (const float*)d_in[9];
    const float* We2 = (const float*)d_in[10];
    const float* be2 = (const float*)d_in[11];
    float* out = (float*)d_out;

    void *p;
    float *p_tmp, *p_z, *p_znorm, *p_emean, *p_etmp, *p_hedges, *p_hnorm;
    cudaGetSymbolAddress(&p, g_tmp);    p_tmp    = (float*)p;
    cudaGetSymbolAddress(&p, g_z);      p_z      = (float*)p;
    cudaGetSymbolAddress(&p, g_znorm);  p_znorm  = (float*)p;
    cudaGetSymbolAddress(&p, g_emean);  p_emean  = (float*)p;
    cudaGetSymbolAddress(&p, g_etmp);   p_etmp   = (float*)p;
    cudaGetSymbolAddress(&p, g_hedges); p_hedges = (float*)p;
    cudaGetSymbolAddress(&p, g_hnorm);  p_hnorm  = (float*)p;

    // node MLP first (launch idx 0,1,2)
    gemm_nk_kernel<true ><<<dim3(64, 4), 256>>>(ne,    Wn1, bn1, p_tmp);
    gemm_nk_kernel<false><<<dim3(64, 4), 256>>>(p_tmp, Wn2, bn2, p_z);
    rownorm_kernel<<<N_ / 8, 256>>>(p_z, p_znorm, N_);

    // edge aggregation (idx 3 = profiled by ncu)
    edge_part_kernel<<<dim3(ECAP_ / 4, 8), 256>>>(Hp, p_z);
    edge_reduce_kernel<<<ECAP_, 256>>>();

    // edge MLP
    gemm64_kernel<true ><<<dim3(8, 4), 256>>>(p_emean, We1, be1, p_etmp,   ECAP_);
    gemm64_kernel<false><<<dim3(8, 4), 256>>>(p_etmp,  We2, be2, p_hedges, ECAP_);
    rownorm_kernel<<<(ECAP_ + 7) / 8, 256>>>(p_hedges, p_hnorm, ECAP_);

    // fused attention / sim / lse
    attlse_kernel<<<dim3(25, 8), 256>>>();
    merge_kernel<<<MHN_ + 1, 256>>>();

    // independent scalar paths
    init_kernel<<<40, 256>>>();
    count_nz_kernel<<<2048, 256>>>((const float4*)Ho, (const float4*)Hp);
    topo_kernel<<<SAMP_, 128>>>(Ho, Hp);

    // losses
    cl_kernel<<<ECAP_, 256>>>();
    fn_kernel<<<dim3(MFN_, MFN_), 256>>>(Ho, Hp);
    hn_kernel<<<MHN_, 256>>>();

    final_kernel<<<1, 512>>>(bw, out);
}

// round 5
// speedup vs baseline: 2.7212x; 1.0227x over previous
#include <cuda_runtime.h>
#include <math.h>
#include <cfloat>

// ---------------- constants ----------------
#define TAU_F   0.4f
#define ALPHA_F 1.0f
#define GAMMA_F 0.7f
#define DELTA_F 0.6f
#define MU_F    0.6f
#define NU_F    0.3f

#define N_  8192
#define E_  2048
#define D_  256
#define SAMP_ 100
#define MFN_  100
#define MHN_  200
#define ECAP_ 500

// ---------------- scratch (device globals) ----------------
__device__ float g_tmp[N_ * D_];
__device__ float g_z[N_ * D_];
__device__ float g_znorm[N_];
__device__ float g_edge_part[8][512 * D_];
__device__ int   g_cntp[8][512];
__device__ float g_etmp[512 * D_];
__device__ float g_hedges[512 * D_];
__device__ float g_hnpart[4][512];
__device__ float g_hnorm[ECAP_];
__device__ float g_sim[MHN_ * MHN_];
__device__ float g_attdot[MHN_ * MHN_];
__device__ float g_attm[MHN_ * 8], g_atts[MHN_ * 8];
__device__ float g_att[MHN_ * MHN_];
__device__ float g_lsem[MFN_ * 8], g_lses[MFN_ * 8];
__device__ float g_lse[MFN_];
__device__ float g_clrow[ECAP_];
__device__ float g_fnrow[MFN_], g_fncnt[MFN_];
__device__ float g_hnsum[MHN_], g_hncnt[MHN_];
__device__ int   g_nza[2048], g_nzb[2048];
__device__ float g_topo[SAMP_ * 2];

// ---------------- reduction helpers ----------------
__device__ __forceinline__ float warp_sum(float v) {
#pragma unroll
    for (int o = 16; o > 0; o >>= 1) v += __shfl_xor_sync(0xffffffffu, v, o);
    return v;
}
__device__ __forceinline__ float warp_max(float v) {
#pragma unroll
    for (int o = 16; o > 0; o >>= 1) v = fmaxf(v, __shfl_xor_sync(0xffffffffu, v, o));
    return v;
}
__device__ __forceinline__ int warp_sum_i(int v) {
#pragma unroll
    for (int o = 16; o > 0; o >>= 1) v += __shfl_xor_sync(0xffffffffu, v, o);
    return v;
}
__device__ float block_sum(float v, float* sm) {
    int w = threadIdx.x >> 5, lane = threadIdx.x & 31, nw = blockDim.x >> 5;
    v = warp_sum(v);
    if (lane == 0) sm[w] = v;
    __syncthreads();
    float r = (threadIdx.x < nw) ? sm[threadIdx.x] : 0.f;
    if (w == 0) r = warp_sum(r);
    if (threadIdx.x == 0) sm[0] = r;
    __syncthreads();
    r = sm[0];
    __syncthreads();
    return r;
}
__device__ float block_max(float v, float* sm) {
    int w = threadIdx.x >> 5, lane = threadIdx.x & 31, nw = blockDim.x >> 5;
    v = warp_max(v);
    if (lane == 0) sm[w] = v;
    __syncthreads();
    float r = (threadIdx.x < nw) ? sm[threadIdx.x] : -FLT_MAX;
    if (w == 0) r = warp_max(r);
    if (threadIdx.x == 0) sm[0] = r;
    __syncthreads();
    r = sm[0];
    __syncthreads();
    return r;
}

// ---------------- kernels ----------------

// nonzero counts: per-block partials, no atomics, no init required
__global__ void count_nz_kernel(const float4* __restrict__ a, const float4* __restrict__ b) {
    const int n4 = N_ * E_ / 4;
    int ca = 0, cb = 0;
    for (int i = blockIdx.x * blockDim.x + threadIdx.x; i < n4; i += gridDim.x * blockDim.x) {
        float4 x = a[i];
        ca += (x.x != 0.f) + (x.y != 0.f) + (x.z != 0.f) + (x.w != 0.f);
        float4 y = b[i];
        cb += (y.x != 0.f) + (y.y != 0.f) + (y.z != 0.f) + (y.w != 0.f);
    }
    __shared__ int sa[32], sb[32];
    int w = threadIdx.x >> 5, lane = threadIdx.x & 31;
    ca = warp_sum_i(ca); cb = warp_sum_i(cb);
    if (lane == 0) { sa[w] = ca; sb[w] = cb; }
    __syncthreads();
    if (w == 0) {
        int x = (lane < 8) ? sa[lane] : 0;
        int y = (lane < 8) ? sb[lane] : 0;
        x = warp_sum_i(x); y = warp_sum_i(y);
        if (lane == 0) { g_nza[blockIdx.x] = x; g_nzb[blockIdx.x] = y; }
    }
}

// topology: one block per row i of the 100x100 sample
__global__ void topo_kernel(const float* __restrict__ Ho, const float* __restrict__ Hp) {
    __shared__ float hoi[128], hpi[128];
    __shared__ float sm[32];
    int i = blockIdx.x;
    int tid = threadIdx.x;
    if (tid < SAMP_) { hoi[tid] = Ho[i * E_ + tid]; hpi[tid] = Hp[i * E_ + tid]; }
    else             { hoi[tid] = 0.f; hpi[tid] = 0.f; }
    __syncthreads();
    int w = tid >> 5, lane = tid & 31;
    float dn2 = 0.f, on2 = 0.f;
    for (int j = w; j < SAMP_; j += 4) {
        float as = 0.f, aps = 0.f;
#pragma unroll
        for (int t = 0; t < 4; t++) {
            int k = lane + 32 * t;
            if (k < SAMP_) {
                as  += hoi[k] * Ho[j * E_ + k];
                aps += hpi[k] * Hp[j * E_ + k];
            }
        }
        as = warp_sum(as);
        aps = warp_sum(aps);
        if (lane == 0) {
            float d = as - aps;
            dn2 += d * d;
            on2 += as * as;
        }
    }
    float D2 = block_sum(dn2, sm);
    float O2 = block_sum(on2, sm);
    if (tid == 0) { g_topo[i * 2] = D2; g_topo[i * 2 + 1] = O2; }
}

// node MLP GEMM: BM=128, BN=64, BK=16, 8x4 microtile, 256 threads (near FFMA floor)
template <bool RELU>
__global__ void gemm_nk_kernel(const float* __restrict__ A, const float* __restrict__ B,
                               const float* __restrict__ bias, float* __restrict__ C) {
    __shared__ float As[16][132];
    __shared__ float Bs[16][68];
    const int bm = blockIdx.x * 128, bn = blockIdx.y * 64;
    const int tid = threadIdx.x;
    const int tx = tid & 15, ty = tid >> 4;
    float acc[8][4] = {};
    for (int k0 = 0; k0 < D_; k0 += 16) {
#pragma unroll
        for (int l = 0; l < 2; l++) {
            int id = tid * 2 + l;
            int r = id >> 2, c4 = id & 3;
            float4 v = *(const float4*)&A[(bm + r) * D_ + k0 + c4 * 4];
            As[c4 * 4 + 0][r] = v.x;
            As[c4 * 4 + 1][r] = v.y;
            As[c4 * 4 + 2][r] = v.z;
            As[c4 * 4 + 3][r] = v.w;
        }
        {
            int r = tid >> 4, c4 = tid & 15;
            float4 v = *(const float4*)&B[(k0 + r) * D_ + bn + c4 * 4];
            *(float4*)&Bs[r][c4 * 4] = v;
        }
        __syncthreads();
#pragma unroll
        for (int kk = 0; kk < 16; kk++) {
            float a[8], b[4];
#pragma unroll
            for (int u = 0; u < 8; u++) a[u] = As[kk][ty * 8 + u];
#pragma unroll
            for (int u = 0; u < 4; u++) b[u] = Bs[kk][tx * 4 + u];
#pragma unroll
            for (int i = 0; i < 8; i++)
#pragma unroll
                for (int j = 0; j < 4; j++) acc[i][j] += a[i] * b[j];
        }
        __syncthreads();
    }
#pragma unroll
    for (int i = 0; i < 8; i++) {
        int row = bm + ty * 8 + i;
#pragma unroll
        for (int j = 0; j < 4; j++) {
            int col = bn + tx * 4 + j;
            float v = acc[i][j] + bias[col];
            if (RELU) v = fmaxf(v, 0.f);
            C[row * D_ + col] = v;
        }
    }
}

// per-row L2 norms (warp per row)
__global__ void rownorm_kernel(const float* __restrict__ X, float* __restrict__ nrm, int rows) {
    int r = blockIdx.x * 8 + (threadIdx.x >> 5);
    int lane = threadIdx.x & 31;
    if (r >= rows) return;
    float s = 0.f;
#pragma unroll
    for (int t = 0; t < 8; t++) { float v = X[r * D_ + lane + 32 * t]; s += v * v; }
    s = warp_sum(s);
    if (lane == 0) nrm[r] = fmaxf(sqrtf(s), 1e-8f);
}

// Sparse edge aggregation partials: grid (125 edge-groups, 8 i-splits)
__global__ void edge_part_kernel(const float* __restrict__ Hp, const float* __restrict__ z) {
    __shared__ short slist[256];
    __shared__ unsigned char smask[256];
    __shared__ int scnt[8];
    const int tid = threadIdx.x;
    const int lane = tid & 31, w = tid >> 5;
    const int e0 = blockIdx.x * 4, sp = blockIdx.y;
    float a0 = 0.f, a1 = 0.f, a2 = 0.f, a3 = 0.f;
    int c0 = 0, c1 = 0, c2 = 0, c3 = 0;
    const int ibase = sp * 1024;
    for (int ic = 0; ic < 1024; ic += 256) {
        int i0 = ibase + ic;
        float4 v = *(const float4*)&Hp[(size_t)(i0 + tid) * E_ + e0];
        int m = (v.x > 0.f) | ((v.y > 0.f) << 1) | ((v.z > 0.f) << 2) | ((v.w > 0.f) << 3);
        unsigned b = __ballot_sync(0xffffffffu, m != 0);
        int pre = __popc(b & ((1u << lane) - 1u));
        if (m) { slist[w * 32 + pre] = (short)tid; smask[w * 32 + pre] = (unsigned char)m; }
        if (lane == 0) scnt[w] = __popc(b);
        __syncthreads();
#pragma unroll 1
        for (int w2 = 0; w2 < 8; w2++) {
            int n = scnt[w2];
            for (int k = 0; k < n; k++) {
                int t = slist[w2 * 32 + k];
                int mm = smask[w2 * 32 + k];
                float zv = z[(size_t)(i0 + t) * D_ + tid];
                if (mm & 1) { a0 += zv; c0++; }
                if (mm & 2) { a1 += zv; c1++; }
                if (mm & 4) { a2 += zv; c2++; }
                if (mm & 8) { a3 += zv; c3++; }
            }
        }
        __syncthreads();
    }
    g_edge_part[sp][(e0 + 0) * D_ + tid] = a0;
    g_edge_part[sp][(e0 + 1) * D_ + tid] = a1;
    g_edge_part[sp][(e0 + 2) * D_ + tid] = a2;
    g_edge_part[sp][(e0 + 3) * D_ + tid] = a3;
    if (tid == 0) {
        g_cntp[sp][e0 + 0] = c0;
        g_cntp[sp][e0 + 1] = c1;
        g_cntp[sp][e0 + 2] = c2;
        g_cntp[sp][e0 + 3] = c3;
    }
}

// edge MLP layer 1: A = mean(edge partials) computed on the fly. BM=BN=64, BK=16.
__global__ void gemm64_e1_kernel(const float* __restrict__ B, const float* __restrict__ bias,
                                 float* __restrict__ C) {
    __shared__ float As[16][68];
    __shared__ float Bs[16][68];
    const int bm = blockIdx.x * 64, bn = blockIdx.y * 64;
    const int tid = threadIdx.x;
    const int tx = tid & 15, ty = tid >> 4;
    // per-thread A-load row fixed: r = tid>>2
    const int arow = bm + (tid >> 2);
    float cinv = 0.f;
    {
        int c = 0;
#pragma unroll
        for (int p = 0; p < 8; p++) c += g_cntp[p][arow];
        cinv = (c > 0 && arow < ECAP_) ? 1.f / (float)c : 0.f;
    }
    float acc[4][4] = {};
    for (int k0 = 0; k0 < D_; k0 += 16) {
        {
            int r = tid >> 2, c4 = tid & 3;
            float4 s = make_float4(0.f, 0.f, 0.f, 0.f);
#pragma unroll
            for (int p = 0; p < 8; p++) {
                float4 t = *(const float4*)&g_edge_part[p][arow * D_ + k0 + c4 * 4];
                s.x += t.x; s.y += t.y; s.z += t.z; s.w += t.w;
            }
            As[c4 * 4 + 0][r] = s.x * cinv;
            As[c4 * 4 + 1][r] = s.y * cinv;
            As[c4 * 4 + 2][r] = s.z * cinv;
            As[c4 * 4 + 3][r] = s.w * cinv;
        }
        {
            int r = tid >> 4, c4 = tid & 15;
            float4 v = *(const float4*)&B[(k0 + r) * D_ + bn + c4 * 4];
            *(float4*)&Bs[r][c4 * 4] = v;
        }
        __syncthreads();
#pragma unroll
        for (int kk = 0; kk < 16; kk++) {
            float a[4], b[4];
#pragma unroll
            for (int u = 0; u < 4; u++) a[u] = As[kk][ty * 4 + u];
#pragma unroll
            for (int u = 0; u < 4; u++) b[u] = Bs[kk][tx * 4 + u];
#pragma unroll
            for (int i = 0; i < 4; i++)
#pragma unroll
                for (int j = 0; j < 4; j++) acc[i][j] += a[i] * b[j];
        }
        __syncthreads();
    }
#pragma unroll
    for (int i = 0; i < 4; i++) {
        int row = bm + ty * 4 + i;
#pragma unroll
        for (int j = 0; j < 4; j++) {
            int col = bn + tx * 4 + j;
            C[row * D_ + col] = fmaxf(acc[i][j] + bias[col], 0.f);
        }
    }
}

// edge MLP layer 2: writes hedges + per-block row sumsq partials for hnorm
__global__ void gemm64_e2_kernel(const float* __restrict__ A, const float* __restrict__ B,
                                 const float* __restrict__ bias, float* __restrict__ C) {
    __shared__ float As[16][68];
    __shared__ float Bs[16][68];
    __shared__ float ssq[64][17];
    const int bm = blockIdx.x * 64, bn = blockIdx.y * 64;
    const int tid = threadIdx.x;
    const int tx = tid & 15, ty = tid >> 4;
    float acc[4][4] = {};
    for (int k0 = 0; k0 < D_; k0 += 16) {
        {
            int r = tid >> 2, c4 = tid & 3;
            float4 v = *(const float4*)&A[(bm + r) * D_ + k0 + c4 * 4];
            As[c4 * 4 + 0][r] = v.x;
            As[c4 * 4 + 1][r] = v.y;
            As[c4 * 4 + 2][r] = v.z;
            As[c4 * 4 + 3][r] = v.w;
        }
        {
            int r = tid >> 4, c4 = tid & 15;
            float4 v = *(const float4*)&B[(k0 + r) * D_ + bn + c4 * 4];
            *(float4*)&Bs[r][c4 * 4] = v;
        }
        __syncthreads();
#pragma unroll
        for (int kk = 0; kk < 16; kk++) {
            float a[4], b[4];
#pragma unroll
            for (int u = 0; u < 4; u++) a[u] = As[kk][ty * 4 + u];
#pragma unroll
            for (int u = 0; u < 4; u++) b[u] = Bs[kk][tx * 4 + u];
#pragma unroll
            for (int i = 0; i < 4; i++)
#pragma unroll
                for (int j = 0; j < 4; j++) acc[i][j] += a[i] * b[j];
        }
        __syncthreads();
    }
#pragma unroll
    for (int i = 0; i < 4; i++) {
        int row = bm + ty * 4 + i;
        float sq = 0.f;
#pragma unroll
        for (int j = 0; j < 4; j++) {
            int col = bn + tx * 4 + j;
            float v = acc[i][j] + bias[col];
            C[row * D_ + col] = v;
            sq += v * v;
        }
        ssq[ty * 4 + i][tx] = sq;
    }
    __syncthreads();
    if (tid < 64) {
        float s = 0.f;
#pragma unroll
        for (int q = 0; q < 16; q++) s += ssq[tid][q];
        g_hnpart[blockIdx.y][bm + tid] = s;
    }
}

// Fused att/sim/lse over j: grid (25 rowgroups, 8 j-splits)
__global__ void attlse_kernel() {
    __shared__ float zi[8][256];
    __shared__ float inv_i[8];
    __shared__ float smm[8][8], sms[8][8];
    __shared__ float smm2[8][8], sms2[8][8];
    const int rg = blockIdx.x, sp = blockIdx.y;
    const int tid = threadIdx.x;
    const int row0 = rg * 8;
#pragma unroll
    for (int r = 0; r < 8; r++) zi[r][tid] = g_z[(row0 + r) * D_ + tid];
    if (tid < 8) inv_i[tid] = 1.f / g_znorm[row0 + tid];
    __syncthreads();
    const int w = tid >> 5, lane = tid & 31;
    const bool anylse = (row0 < MFN_);
    float m[8], s[8], m2[8], s2[8];
#pragma unroll
    for (int r = 0; r < 8; r++) { m[r] = -FLT_MAX; s[r] = 0.f; m2[r] = -FLT_MAX; s2[r] = 0.f; }
    const int j0 = sp * 1024;
    for (int jj = w; jj < 1024; jj += 8) {
        int j = j0 + jj;
        float d[8];
#pragma unroll
        for (int r = 0; r < 8; r++) d[r] = 0.f;
#pragma unroll
        for (int t = 0; t < 8; t++) {
            int k = lane + 32 * t;
            float zj = g_z[j * D_ + k];
#pragma unroll
            for (int r = 0; r < 8; r++) d[r] += zi[r][k] * zj;
        }
#pragma unroll
        for (int r = 0; r < 8; r++) d[r] = warp_sum(d[r]);
        float invj = 1.f / g_znorm[j];
        if (sp == 0 && j < MHN_ && lane == 0) {
#pragma unroll
            for (int r = 0; r < 8; r++) {
                g_attdot[(row0 + r) * MHN_ + j] = d[r];
                g_sim[(row0 + r) * MHN_ + j] = d[r] * inv_i[r] * invj;
            }
        }
#pragma unroll
        for (int r = 0; r < 8; r++) {
            float x = d[r];
            if (x <= m[r]) s[r] += __expf(x - m[r]);
            else { s[r] = s[r] * __expf(m[r] - x) + 1.f; m[r] = x; }
        }
        if (anylse) {
            float sc = invj * (1.f / TAU_F);
#pragma unroll
            for (int r = 0; r < 8; r++) {
                if (row0 + r < MFN_) {
                    float v = d[r] * inv_i[r] * sc;
                    if (v <= m2[r]) s2[r] += __expf(v - m2[r]);
                    else { s2[r] = s2[r] * __expf(m2[r] - v) + 1.f; m2[r] = v; }
                }
            }
        }
    }
    if (lane == 0) {
#pragma unroll
        for (int r = 0; r < 8; r++) { smm[w][r] = m[r]; sms[w][r] = s[r]; smm2[w][r] = m2[r]; sms2[w][r] = s2[r]; }
    }
    __syncthreads();
    if (tid < 8) {
        float M = -FLT_MAX;
        for (int q = 0; q < 8; q++) M = fmaxf(M, smm[q][tid]);
        float S = 0.f;
        for (int q = 0; q < 8; q++) S += sms[q][tid] * __expf(smm[q][tid] - M);
        g_attm[(row0 + tid) * 8 + sp] = M;
        g_atts[(row0 + tid) * 8 + sp] = S;
        if (row0 + tid < MFN_) {
            float M2 = -FLT_MAX;
            for (int q = 0; q < 8; q++) M2 = fmaxf(M2, smm2[q][tid]);
            float S2 = 0.f;
            for (int q = 0; q < 8; q++) S2 += sms2[q][tid] * __expf(smm2[q][tid] - M2);
            g_lsem[(row0 + tid) * 8 + sp] = M2;
            g_lses[(row0 + tid) * 8 + sp] = S2;
        }
    }
}

// merged finalize: att rows (0..199), lse (200), hnorm (201)
__global__ void merge_kernel() {
    int b = blockIdx.x;
    if (b < MHN_) {
        int i = b;
        __shared__ float Ms, Ss;
        if (threadIdx.x == 0) {
            float M = -FLT_MAX;
            for (int p = 0; p < 8; p++) M = fmaxf(M, g_attm[i * 8 + p]);
            float S = 0.f;
            for (int p = 0; p < 8; p++) S += g_atts[i * 8 + p] * __expf(g_attm[i * 8 + p] - M);
            Ms = M; Ss = S;
        }
        __syncthreads();
        for (int j = threadIdx.x; j < MHN_; j += blockDim.x)
            g_att[i * MHN_ + j] = __expf(g_attdot[i * MHN_ + j] - Ms) / Ss;
    } else if (b == MHN_) {
        int i = threadIdx.x;
        if (i < MFN_) {
            float M = -FLT_MAX;
            for (int p = 0; p < 8; p++) M = fmaxf(M, g_lsem[i * 8 + p]);
            float S = 0.f;
            for (int p = 0; p < 8; p++) S += g_lses[i * 8 + p] * __expf(g_lsem[i * 8 + p] - M);
            g_lse[i] = M + logf(S);
        }
    } else {
        for (int j = threadIdx.x; j < ECAP_; j += blockDim.x) {
            float s = g_hnpart[0][j] + g_hnpart[1][j] + g_hnpart[2][j] + g_hnpart[3][j];
            g_hnorm[j] = fmaxf(sqrtf(s), 1e-8f);
        }
    }
}

// fused losses: blocks [0,500) = cl rows; [500,700) = hn rows (+ fn for i<100)
__global__ void losses_kernel(const float* __restrict__ Ho, const float* __restrict__ Hp) {
    __shared__ float sm[32];
    int b = blockIdx.x;
    int tid = threadIdx.x;
    if (b < ECAP_) {
        // contrastive row
        __shared__ float zi[256];
        __shared__ float logit[500];
        int i = b;
        zi[tid] = g_z[i * D_ + tid] / g_znorm[i];
        __syncthreads();
        int w = tid >> 5, lane = tid & 31;
        for (int j = w; j < ECAP_; j += 8) {
            float s = 0.f;
#pragma unroll
            for (int t = 0; t < 8; t++) { int k = lane + 32 * t; s += zi[k] * g_hedges[j * D_ + k]; }
            s = warp_sum(s);
            if (lane == 0) logit[j] = s / (g_hnorm[j] * TAU_F);
        }
        __syncthreads();
        float lm = -FLT_MAX;
        for (int j = tid; j < ECAP_; j += 256) lm = fmaxf(lm, logit[j]);
        float M = block_max(lm, sm);
        float ls = 0.f;
        for (int j = tid; j < ECAP_; j += 256) ls += __expf(logit[j] - M);
        float S = block_sum(ls, sm);
        if (tid == 0) g_clrow[i] = logit[i] - (M + logf(S));
    } else {
        int i = b - ECAP_;   // 0..199
        // hard-negative row
        {
            int j = tid;
            bool act = j < MHN_;
            float simv = act ? g_sim[i * MHN_ + j] : 0.f;
            float attv = act ? g_att[i * MHN_ + j] : 1.f;
            bool mask = act && (j != i) && (simv > MU_F) && (attv < NU_F);
            float neg = -simv / TAU_F;
            float m = block_max(mask ? neg : -FLT_MAX, sm);
            if (m == -FLT_MAX) {
                if (tid == 0) { g_hnsum[i] = 0.f; g_hncnt[i] = 0.f; }
            } else {
                float s = block_sum(mask ? expf(neg - m) : 0.f, sm);
                float lse = m + logf(s);
                float wgt = fminf(simv / MU_F, 1.f);
                float pair = -wgt * (neg - lse);
                float ps = block_sum(mask ? pair : 0.f, sm);
                float pc = block_sum(mask ? 1.f : 0.f, sm);
                if (tid == 0) { g_hnsum[i] = ps; g_hncnt[i] = pc; }
            }
        }
        // false-negative candidates for rows i < 100
        if (i < MFN_) {
            __shared__ unsigned char cand[128];
            __shared__ short clist[MFN_];
            __shared__ int ncand;
            if (tid < 128) cand[tid] = 0;
            __syncthreads();
            if (tid < MFN_) {
                bool g = (tid > i) && (g_sim[i * MHN_ + tid] > GAMMA_F)
                                   && (g_att[i * MHN_ + tid] > DELTA_F);
                cand[tid] = g ? 1 : 0;
            }
            __syncthreads();
            if (tid == 0) {
                int n = 0;
                for (int j = i + 1; j < MFN_; j++) if (cand[j]) clist[n++] = (short)j;
                ncand = n;
            }
            __syncthreads();
            int nc = ncand;
            float fsum = 0.f, fcnt = 0.f;
            for (int k = 0; k < nc; k++) {
                int j = clist[k];
                float ao = 0.f, ap = 0.f;
                for (int t = tid; t < E_; t += 256) {
                    ao += Ho[i * E_ + t] * Ho[j * E_ + t];
                    ap += Hp[i * E_ + t] * Hp[j * E_ + t];
                }
                ao = block_sum(ao, sm);
                ap = block_sum(ap, sm);
                if (ap == 0.f && ao > 0.f) {
                    fsum += -(g_sim[i * MHN_ + j] / TAU_F - g_lse[i]);
                    fcnt += 1.f;
                }
            }
            if (tid == 0) { g_fnrow[i] = fsum; g_fncnt[i] = fcnt; }
        }
    }
}

// final combine (single block, deterministic)
__global__ void final_kernel(const float* __restrict__ bw, float* __restrict__ out) {
    __shared__ float sm[32];
    int tid = threadIdx.x;
    float v = 0.f;
    for (int i = tid; i < ECAP_; i += 512) v += g_clrow[i];
    float clsum = block_sum(v, sm);
    v = 0.f; float c = 0.f;
    for (int i = tid; i < MFN_; i += 512) { v += g_fnrow[i]; c += g_fncnt[i]; }
    float fnsum = block_sum(v, sm);
    float fncnt = block_sum(c, sm);
    v = 0.f; c = 0.f;
    for (int i = tid; i < MHN_; i += 512) { v += g_hnsum[i]; c += g_hncnt[i]; }
    float hnsum = block_sum(v, sm);
    float hncnt = block_sum(c, sm);
    float d2 = 0.f, o2 = 0.f;
    for (int i = tid; i < SAMP_; i += 512) { d2 += g_topo[i * 2]; o2 += g_topo[i * 2 + 1]; }
    float D2 = block_sum(d2, sm);
    float O2 = block_sum(o2, sm);
    float za = 0.f, zb = 0.f;
    for (int i = tid; i < 2048; i += 512) { za += (float)g_nza[i]; zb += (float)g_nzb[i]; }
    float NZ = block_sum(za, sm);
    float NZP = block_sum(zb, sm);
    if (tid == 0) {
        float cl_loss = -clsum / (float)ECAP_;
        float fn_loss = (fncnt > 0.f) ? fnsum / fmaxf(fncnt, 1.f) : 0.f;
        float hard_loss = (hncnt > 0.f) ? hnsum / fmaxf(hncnt, 1.f) : 0.f;
        float sparsity = (NZ > 0.f) ? NZP / fmaxf(NZ, 1.f) : 1.f;
        float dn = sqrtf(D2), on = sqrtf(O2);
        float topo = (on > 0.f) ? expf(-ALPHA_F * dn / fmaxf(on, 1e-12f)) : 1.f;
        float retention = sparsity * topo;
        out[0] = bw[0] * (retention * cl_loss + fn_loss + hard_loss);
    }
}

// ---------------- launch ----------------
extern "C" void kernel_launch(void* const* d_in, const int* in_sizes, int n_in,
                              void* d_out, int out_size) {
    (void)in_sizes; (void)n_in; (void)out_size;
    const float* Ho  = (const float*)d_in[0];
    const float* Hp  = (const float*)d_in[1];
    const float* ne  = (const float*)d_in[2];
    const float* bw  = (const float*)d_in[3];
    const float* Wn1 = (const float*)d_in[4];
    const float* bn1 = (const float*)d_in[5];
    const float* Wn2 = (const float*)d_in[6];
    const float* bn2 = (const float*)d_in[7];
    const float* We1 = (const float*)d_in[8];
    const float* be1 = (const float*)d_in[9];
    const float* We2 = (const float*)d_in[10];
    const float* be2 = (const float*)d_in[11];
    float* out = (float*)d_out;

    void *p;
    float *p_tmp, *p_z, *p_znorm, *p_etmp, *p_hedges;
    cudaGetSymbolAddress(&p, g_tmp);    p_tmp    = (float*)p;
    cudaGetSymbolAddress(&p, g_z);      p_z      = (float*)p;
    cudaGetSymbolAddress(&p, g_znorm);  p_znorm  = (float*)p;
    cudaGetSymbolAddress(&p, g_etmp);   p_etmp   = (float*)p;
    cudaGetSymbolAddress(&p, g_hedges); p_hedges = (float*)p;

    // idx 0-2: node MLP
    gemm_nk_kernel<true ><<<dim3(64, 4), 256>>>(ne,    Wn1, bn1, p_tmp);
    gemm_nk_kernel<false><<<dim3(64, 4), 256>>>(p_tmp, Wn2, bn2, p_z);
    rownorm_kernel<<<N_ / 8, 256>>>(p_z, p_znorm, N_);

    // idx 3: count_nz (PROFILED this round)
    count_nz_kernel<<<2048, 256>>>((const float4*)Ho, (const float4*)Hp);

    // idx 4: topo
    topo_kernel<<<SAMP_, 128>>>(Ho, Hp);

    // idx 5: edge aggregation partials
    edge_part_kernel<<<dim3(ECAP_ / 4, 8), 256>>>(Hp, p_z);

    // idx 6-7: edge MLP (layer1 fuses mean, layer2 fuses hnorm partials)
    gemm64_e1_kernel<<<dim3(8, 4), 256>>>(We1, be1, p_etmp);
    gemm64_e2_kernel<<<dim3(8, 4), 256>>>(p_etmp, We2, be2, p_hedges);

    // idx 8-9: fused attention/sim/lse + finalize
    attlse_kernel<<<dim3(25, 8), 256>>>();
    merge_kernel<<<MHN_ + 2, 256>>>();

    // idx 10: fused losses (cl + hn + fn)
    losses_kernel<<<ECAP_ + MHN_, 256>>>(Ho, Hp);

    // idx 11: final combine
    final_kernel<<<1, 512>>>(bw, out);
}

// round 6
// speedup vs baseline: 3.2218x; 1.1840x over previous
#include <cuda_runtime.h>
#include <math.h>
#include <cfloat>

// ---------------- constants ----------------
#define TAU_F   0.4f
#define ALPHA_F 1.0f
#define GAMMA_F 0.7f
#define DELTA_F 0.6f
#define MU_F    0.6f
#define NU_F    0.3f

#define N_  8192
#define E_  2048
#define D_  256
#define SAMP_ 100
#define MFN_  100
#define MHN_  200
#define ECAP_ 500
#define NSPL_ 16

// ---------------- scratch (device globals) ----------------
__device__ float g_tmp[N_ * D_];
__device__ float g_z[N_ * D_];
__device__ float g_znpart[4][N_];
__device__ float g_znorm[N_];
__device__ float g_edge_part[8][512 * D_];
__device__ int   g_cntp[8][512];
__device__ float g_etmp[512 * D_];
__device__ float g_hedges[512 * D_];
__device__ float g_hnpart[4][512];
__device__ float g_hnorm[ECAP_];
__device__ float g_sim[MHN_ * MHN_];
__device__ float g_attdot[MHN_ * MHN_];
__device__ float g_attm[MHN_ * NSPL_], g_atts[MHN_ * NSPL_];
__device__ float g_att[MHN_ * MHN_];
__device__ float g_lsem[MFN_ * NSPL_], g_lses[MFN_ * NSPL_];
__device__ float g_lse[MFN_];
__device__ float g_clrow[ECAP_];
__device__ float g_fnrow[MFN_], g_fncnt[MFN_];
__device__ float g_hnsum[MHN_], g_hncnt[MHN_];
__device__ int   g_nza[2048], g_nzb[2048];
__device__ float g_topo[SAMP_ * 2];

// ---------------- reduction helpers ----------------
__device__ __forceinline__ float warp_sum(float v) {
#pragma unroll
    for (int o = 16; o > 0; o >>= 1) v += __shfl_xor_sync(0xffffffffu, v, o);
    return v;
}
__device__ __forceinline__ float warp_max(float v) {
#pragma unroll
    for (int o = 16; o > 0; o >>= 1) v = fmaxf(v, __shfl_xor_sync(0xffffffffu, v, o));
    return v;
}
__device__ __forceinline__ int warp_sum_i(int v) {
#pragma unroll
    for (int o = 16; o > 0; o >>= 1) v += __shfl_xor_sync(0xffffffffu, v, o);
    return v;
}
__device__ float block_sum(float v, float* sm) {
    int w = threadIdx.x >> 5, lane = threadIdx.x & 31, nw = blockDim.x >> 5;
    v = warp_sum(v);
    if (lane == 0) sm[w] = v;
    __syncthreads();
    float r = (threadIdx.x < nw) ? sm[threadIdx.x] : 0.f;
    if (w == 0) r = warp_sum(r);
    if (threadIdx.x == 0) sm[0] = r;
    __syncthreads();
    r = sm[0];
    __syncthreads();
    return r;
}
__device__ float block_max(float v, float* sm) {
    int w = threadIdx.x >> 5, lane = threadIdx.x & 31, nw = blockDim.x >> 5;
    v = warp_max(v);
    if (lane == 0) sm[w] = v;
    __syncthreads();
    float r = (threadIdx.x < nw) ? sm[threadIdx.x] : -FLT_MAX;
    if (w == 0) r = warp_max(r);
    if (threadIdx.x == 0) sm[0] = r;
    __syncthreads();
    r = sm[0];
    __syncthreads();
    return r;
}

// ---------------- kernels ----------------

// nonzero counts: per-block partials, no atomics
__global__ void count_nz_kernel(const float4* __restrict__ a, const float4* __restrict__ b) {
    const int n4 = N_ * E_ / 4;
    int ca = 0, cb = 0;
    for (int i = blockIdx.x * blockDim.x + threadIdx.x; i < n4; i += gridDim.x * blockDim.x) {
        float4 x = a[i];
        ca += (x.x != 0.f) + (x.y != 0.f) + (x.z != 0.f) + (x.w != 0.f);
        float4 y = b[i];
        cb += (y.x != 0.f) + (y.y != 0.f) + (y.z != 0.f) + (y.w != 0.f);
    }
    __shared__ int sa[32], sb[32];
    int w = threadIdx.x >> 5, lane = threadIdx.x & 31;
    ca = warp_sum_i(ca); cb = warp_sum_i(cb);
    if (lane == 0) { sa[w] = ca; sb[w] = cb; }
    __syncthreads();
    if (w == 0) {
        int x = (lane < 8) ? sa[lane] : 0;
        int y = (lane < 8) ? sb[lane] : 0;
        x = warp_sum_i(x); y = warp_sum_i(y);
        if (lane == 0) { g_nza[blockIdx.x] = x; g_nzb[blockIdx.x] = y; }
    }
}

// topology: one block per row i of the 100x100 sample
__global__ void topo_kernel(const float* __restrict__ Ho, const float* __restrict__ Hp) {
    __shared__ float hoi[128], hpi[128];
    __shared__ float sm[32];
    int i = blockIdx.x;
    int tid = threadIdx.x;
    if (tid < SAMP_) { hoi[tid] = Ho[i * E_ + tid]; hpi[tid] = Hp[i * E_ + tid]; }
    else             { hoi[tid] = 0.f; hpi[tid] = 0.f; }
    __syncthreads();
    int w = tid >> 5, lane = tid & 31;
    float dn2 = 0.f, on2 = 0.f;
    for (int j = w; j < SAMP_; j += 4) {
        float as = 0.f, aps = 0.f;
#pragma unroll
        for (int t = 0; t < 4; t++) {
            int k = lane + 32 * t;
            if (k < SAMP_) {
                as  += hoi[k] * Ho[j * E_ + k];
                aps += hpi[k] * Hp[j * E_ + k];
            }
        }
        as = warp_sum(as);
        aps = warp_sum(aps);
        if (lane == 0) {
            float d = as - aps;
            dn2 += d * d;
            on2 += as * as;
        }
    }
    float D2 = block_sum(dn2, sm);
    float O2 = block_sum(on2, sm);
    if (tid == 0) { g_topo[i * 2] = D2; g_topo[i * 2 + 1] = O2; }
}

// node MLP GEMM: BM=128, BN=64, BK=16, 8x4 microtile, 256 threads.
// NORM: also emit per-(row, BN-block) sumsq partials of the output (pre-relu path unused).
template <bool RELU, bool NORM>
__global__ void gemm_nk_kernel(const float* __restrict__ A, const float* __restrict__ B,
                               const float* __restrict__ bias, float* __restrict__ C) {
    __shared__ float As[16][132];
    __shared__ float Bs[16][68];
    __shared__ float ssq[128][17];
    const int bm = blockIdx.x * 128, bn = blockIdx.y * 64;
    const int tid = threadIdx.x;
    const int tx = tid & 15, ty = tid >> 4;
    float acc[8][4] = {};
    for (int k0 = 0; k0 < D_; k0 += 16) {
#pragma unroll
        for (int l = 0; l < 2; l++) {
            int id = tid * 2 + l;
            int r = id >> 2, c4 = id & 3;
            float4 v = *(const float4*)&A[(bm + r) * D_ + k0 + c4 * 4];
            As[c4 * 4 + 0][r] = v.x;
            As[c4 * 4 + 1][r] = v.y;
            As[c4 * 4 + 2][r] = v.z;
            As[c4 * 4 + 3][r] = v.w;
        }
        {
            int r = tid >> 4, c4 = tid & 15;
            float4 v = *(const float4*)&B[(k0 + r) * D_ + bn + c4 * 4];
            *(float4*)&Bs[r][c4 * 4] = v;
        }
        __syncthreads();
#pragma unroll
        for (int kk = 0; kk < 16; kk++) {
            float a[8], b[4];
#pragma unroll
            for (int u = 0; u < 8; u++) a[u] = As[kk][ty * 8 + u];
#pragma unroll
            for (int u = 0; u < 4; u++) b[u] = Bs[kk][tx * 4 + u];
#pragma unroll
            for (int i = 0; i < 8; i++)
#pragma unroll
                for (int j = 0; j < 4; j++) acc[i][j] += a[i] * b[j];
        }
        __syncthreads();
    }
#pragma unroll
    for (int i = 0; i < 8; i++) {
        int row = bm + ty * 8 + i;
        float sq = 0.f;
#pragma unroll
        for (int j = 0; j < 4; j++) {
            int col = bn + tx * 4 + j;
            float v = acc[i][j] + bias[col];
            if (RELU) v = fmaxf(v, 0.f);
            C[row * D_ + col] = v;
            sq += v * v;
        }
        if (NORM) ssq[ty * 8 + i][tx] = sq;
    }
    if (NORM) {
        __syncthreads();
        if (tid < 128) {
            float s = 0.f;
#pragma unroll
            for (int q = 0; q < 16; q++) s += ssq[tid][q];
            g_znpart[blockIdx.y][bm + tid] = s;
        }
    }
}

// finalize z norms from 4 BN-block partials
__global__ void znorm_fin_kernel() {
    int r = blockIdx.x * 256 + threadIdx.x;
    float s = g_znpart[0][r] + g_znpart[1][r] + g_znpart[2][r] + g_znpart[3][r];
    g_znorm[r] = fmaxf(sqrtf(s), 1e-8f);
}

// Sparse edge aggregation: grid (125 edge-groups, 8 i-splits).
// Each warp processes rows it discovered via its own ballot; per-warp partials;
// fixed-order block reduce => deterministic.
__global__ void edge_part_kernel(const float* __restrict__ Hp, const float* __restrict__ z) {
    __shared__ float racc[8][4][256];  // [warp][edge][col] 32 KB
    __shared__ int rcnt[8][4];
    const int tid = threadIdx.x;
    const int lane = tid & 31, w = tid >> 5;
    const int e0 = blockIdx.x * 4, sp = blockIdx.y;
    float acc[4][8] = {};
    int cnt[4] = {0, 0, 0, 0};
    const int ibase = sp * 1024;
#pragma unroll 1
    for (int ic = 0; ic < 1024; ic += 256) {
        int i0 = ibase + ic;
        float4 v = *(const float4*)&Hp[(size_t)(i0 + tid) * E_ + e0];
        int m = (v.x > 0.f) | ((v.y > 0.f) << 1) | ((v.z > 0.f) << 2) | ((v.w > 0.f) << 3);
        unsigned b = __ballot_sync(0xffffffffu, m != 0);
        int rowbase = i0 + w * 32;
        while (b) {
            int src = __ffs(b) - 1;
            b &= b - 1;
            int mm = __shfl_sync(0xffffffffu, m, src);
            const float* zr = &z[(size_t)(rowbase + src) * D_];
            float zv[8];
#pragma unroll
            for (int t = 0; t < 8; t++) zv[t] = zr[lane + 32 * t];
            switch (mm) {
                case 1:
#pragma unroll
                    for (int t = 0; t < 8; t++) acc[0][t] += zv[t];
                    cnt[0]++; break;
                case 2:
#pragma unroll
                    for (int t = 0; t < 8; t++) acc[1][t] += zv[t];
                    cnt[1]++; break;
                case 4:
#pragma unroll
                    for (int t = 0; t < 8; t++) acc[2][t] += zv[t];
                    cnt[2]++; break;
                case 8:
#pragma unroll
                    for (int t = 0; t < 8; t++) acc[3][t] += zv[t];
                    cnt[3]++; break;
                default:
                    if (mm & 1) {
#pragma unroll
                        for (int t = 0; t < 8; t++) acc[0][t] += zv[t];
                        cnt[0]++;
                    }
                    if (mm & 2) {
#pragma unroll
                        for (int t = 0; t < 8; t++) acc[1][t] += zv[t];
                        cnt[1]++;
                    }
                    if (mm & 4) {
#pragma unroll
                        for (int t = 0; t < 8; t++) acc[2][t] += zv[t];
                        cnt[2]++;
                    }
                    if (mm & 8) {
#pragma unroll
                        for (int t = 0; t < 8; t++) acc[3][t] += zv[t];
                        cnt[3]++;
                    }
            }
        }
    }
#pragma unroll
    for (int e = 0; e < 4; e++)
#pragma unroll
        for (int t = 0; t < 8; t++) racc[w][e][lane + 32 * t] = acc[e][t];
    if (lane == 0) {
#pragma unroll
        for (int e = 0; e < 4; e++) rcnt[w][e] = cnt[e];
    }
    __syncthreads();
#pragma unroll
    for (int e = 0; e < 4; e++) {
        float s = 0.f;
#pragma unroll
        for (int q = 0; q < 8; q++) s += racc[q][e][tid];
        g_edge_part[sp][(e0 + e) * D_ + tid] = s;
    }
    if (tid < 4) {
        int c = 0;
#pragma unroll
        for (int q = 0; q < 8; q++) c += rcnt[q][tid];
        g_cntp[sp][e0 + tid] = c;
    }
}

// edge MLP layer 1: A = mean(edge partials) computed on the fly. BM=BN=64, BK=16.
__global__ void gemm64_e1_kernel(const float* __restrict__ B, const float* __restrict__ bias,
                                 float* __restrict__ C) {
    __shared__ float As[16][68];
    __shared__ float Bs[16][68];
    const int bm = blockIdx.x * 64, bn = blockIdx.y * 64;
    const int tid = threadIdx.x;
    const int tx = tid & 15, ty = tid >> 4;
    const int arow = bm + (tid >> 2);
    float cinv = 0.f;
    {
        int c = 0;
#pragma unroll
        for (int p = 0; p < 8; p++) c += g_cntp[p][arow];
        cinv = (c > 0 && arow < ECAP_) ? 1.f / (float)c : 0.f;
    }
    float acc[4][4] = {};
    for (int k0 = 0; k0 < D_; k0 += 16) {
        {
            int r = tid >> 2, c4 = tid & 3;
            float4 s = make_float4(0.f, 0.f, 0.f, 0.f);
#pragma unroll
            for (int p = 0; p < 8; p++) {
                float4 t = *(const float4*)&g_edge_part[p][arow * D_ + k0 + c4 * 4];
                s.x += t.x; s.y += t.y; s.z += t.z; s.w += t.w;
            }
            As[c4 * 4 + 0][r] = s.x * cinv;
            As[c4 * 4 + 1][r] = s.y * cinv;
            As[c4 * 4 + 2][r] = s.z * cinv;
            As[c4 * 4 + 3][r] = s.w * cinv;
        }
        {
            int r = tid >> 4, c4 = tid & 15;
            float4 v = *(const float4*)&B[(k0 + r) * D_ + bn + c4 * 4];
            *(float4*)&Bs[r][c4 * 4] = v;
        }
        __syncthreads();
#pragma unroll
        for (int kk = 0; kk < 16; kk++) {
            float a[4], b[4];
#pragma unroll
            for (int u = 0; u < 4; u++) a[u] = As[kk][ty * 4 + u];
#pragma unroll
            for (int u = 0; u < 4; u++) b[u] = Bs[kk][tx * 4 + u];
#pragma unroll
            for (int i = 0; i < 4; i++)
#pragma unroll
                for (int j = 0; j < 4; j++) acc[i][j] += a[i] * b[j];
        }
        __syncthreads();
    }
#pragma unroll
    for (int i = 0; i < 4; i++) {
        int row = bm + ty * 4 + i;
#pragma unroll
        for (int j = 0; j < 4; j++) {
            int col = bn + tx * 4 + j;
            C[row * D_ + col] = fmaxf(acc[i][j] + bias[col], 0.f);
        }
    }
}

// edge MLP layer 2: writes hedges + per-block row sumsq partials for hnorm
__global__ void gemm64_e2_kernel(const float* __restrict__ A, const float* __restrict__ B,
                                 const float* __restrict__ bias, float* __restrict__ C) {
    __shared__ float As[16][68];
    __shared__ float Bs[16][68];
    __shared__ float ssq[64][17];
    const int bm = blockIdx.x * 64, bn = blockIdx.y * 64;
    const int tid = threadIdx.x;
    const int tx = tid & 15, ty = tid >> 4;
    float acc[4][4] = {};
    for (int k0 = 0; k0 < D_; k0 += 16) {
        {
            int r = tid >> 2, c4 = tid & 3;
            float4 v = *(const float4*)&A[(bm + r) * D_ + k0 + c4 * 4];
            As[c4 * 4 + 0][r] = v.x;
            As[c4 * 4 + 1][r] = v.y;
            As[c4 * 4 + 2][r] = v.z;
            As[c4 * 4 + 3][r] = v.w;
        }
        {
            int r = tid >> 4, c4 = tid & 15;
            float4 v = *(const float4*)&B[(k0 + r) * D_ + bn + c4 * 4];
            *(float4*)&Bs[r][c4 * 4] = v;
        }
        __syncthreads();
#pragma unroll
        for (int kk = 0; kk < 16; kk++) {
            float a[4], b[4];
#pragma unroll
            for (int u = 0; u < 4; u++) a[u] = As[kk][ty * 4 + u];
#pragma unroll
            for (int u = 0; u < 4; u++) b[u] = Bs[kk][tx * 4 + u];
#pragma unroll
            for (int i = 0; i < 4; i++)
#pragma unroll
                for (int j = 0; j < 4; j++) acc[i][j] += a[i] * b[j];
        }
        __syncthreads();
    }
#pragma unroll
    for (int i = 0; i < 4; i++) {
        int row = bm + ty * 4 + i;
        float sq = 0.f;
#pragma unroll
        for (int j = 0; j < 4; j++) {
            int col = bn + tx * 4 + j;
            float v = acc[i][j] + bias[col];
            C[row * D_ + col] = v;
            sq += v * v;
        }
        ssq[ty * 4 + i][tx] = sq;
    }
    __syncthreads();
    if (tid < 64) {
        float s = 0.f;
#pragma unroll
        for (int q = 0; q < 16; q++) s += ssq[tid][q];
        g_hnpart[blockIdx.y][bm + tid] = s;
    }
}

// Fused att/sim/lse over j: grid (25 rowgroups, 16 j-splits of 512)
__global__ void attlse_kernel() {
    __shared__ float zi[8][256];
    __shared__ float inv_i[8];
    __shared__ float smm[8][8], sms[8][8];
    __shared__ float smm2[8][8], sms2[8][8];
    const int rg = blockIdx.x, sp = blockIdx.y;
    const int tid = threadIdx.x;
    const int row0 = rg * 8;
#pragma unroll
    for (int r = 0; r < 8; r++) zi[r][tid] = g_z[(row0 + r) * D_ + tid];
    if (tid < 8) inv_i[tid] = 1.f / g_znorm[row0 + tid];
    __syncthreads();
    const int w = tid >> 5, lane = tid & 31;
    const bool anylse = (row0 < MFN_);
    float m[8], s[8], m2[8], s2[8];
#pragma unroll
    for (int r = 0; r < 8; r++) { m[r] = -FLT_MAX; s[r] = 0.f; m2[r] = -FLT_MAX; s2[r] = 0.f; }
    const int j0 = sp * 512;
    for (int jj = w; jj < 512; jj += 8) {
        int j = j0 + jj;
        float d[8];
#pragma unroll
        for (int r = 0; r < 8; r++) d[r] = 0.f;
#pragma unroll
        for (int t = 0; t < 8; t++) {
            int k = lane + 32 * t;
            float zj = g_z[j * D_ + k];
#pragma unroll
            for (int r = 0; r < 8; r++) d[r] += zi[r][k] * zj;
        }
#pragma unroll
        for (int r = 0; r < 8; r++) d[r] = warp_sum(d[r]);
        float invj = 1.f / g_znorm[j];
        if (sp == 0 && j < MHN_ && lane == 0) {
#pragma unroll
            for (int r = 0; r < 8; r++) {
                g_attdot[(row0 + r) * MHN_ + j] = d[r];
                g_sim[(row0 + r) * MHN_ + j] = d[r] * inv_i[r] * invj;
            }
        }
#pragma unroll
        for (int r = 0; r < 8; r++) {
            float x = d[r];
            if (x <= m[r]) s[r] += __expf(x - m[r]);
            else { s[r] = s[r] * __expf(m[r] - x) + 1.f; m[r] = x; }
        }
        if (anylse) {
            float sc = invj * (1.f / TAU_F);
#pragma unroll
            for (int r = 0; r < 8; r++) {
                if (row0 + r < MFN_) {
                    float v = d[r] * inv_i[r] * sc;
                    if (v <= m2[r]) s2[r] += __expf(v - m2[r]);
                    else { s2[r] = s2[r] * __expf(m2[r] - v) + 1.f; m2[r] = v; }
                }
            }
        }
    }
    if (lane == 0) {
#pragma unroll
        for (int r = 0; r < 8; r++) { smm[w][r] = m[r]; sms[w][r] = s[r]; smm2[w][r] = m2[r]; sms2[w][r] = s2[r]; }
    }
    __syncthreads();
    if (tid < 8) {
        float M = -FLT_MAX;
        for (int q = 0; q < 8; q++) M = fmaxf(M, smm[q][tid]);
        float S = 0.f;
        for (int q = 0; q < 8; q++) S += sms[q][tid] * __expf(smm[q][tid] - M);
        g_attm[(row0 + tid) * NSPL_ + sp] = M;
        g_atts[(row0 + tid) * NSPL_ + sp] = S;
        if (row0 + tid < MFN_) {
            float M2 = -FLT_MAX;
            for (int q = 0; q < 8; q++) M2 = fmaxf(M2, smm2[q][tid]);
            float S2 = 0.f;
            for (int q = 0; q < 8; q++) S2 += sms2[q][tid] * __expf(smm2[q][tid] - M2);
            g_lsem[(row0 + tid) * NSPL_ + sp] = M2;
            g_lses[(row0 + tid) * NSPL_ + sp] = S2;
        }
    }
}

// merged finalize: att rows (0..199), lse (200), hnorm (201)
__global__ void merge_kernel() {
    int b = blockIdx.x;
    if (b < MHN_) {
        int i = b;
        __shared__ float Ms, Ss;
        if (threadIdx.x == 0) {
            float M = -FLT_MAX;
            for (int p = 0; p < NSPL_; p++) M = fmaxf(M, g_attm[i * NSPL_ + p]);
            float S = 0.f;
            for (int p = 0; p < NSPL_; p++) S += g_atts[i * NSPL_ + p] * __expf(g_attm[i * NSPL_ + p] - M);
            Ms = M; Ss = S;
        }
        __syncthreads();
        for (int j = threadIdx.x; j < MHN_; j += blockDim.x)
            g_att[i * MHN_ + j] = __expf(g_attdot[i * MHN_ + j] - Ms) / Ss;
    } else if (b == MHN_) {
        int i = threadIdx.x;
        if (i < MFN_) {
            float M = -FLT_MAX;
            for (int p = 0; p < NSPL_; p++) M = fmaxf(M, g_lsem[i * NSPL_ + p]);
            float S = 0.f;
            for (int p = 0; p < NSPL_; p++) S += g_lses[i * NSPL_ + p] * __expf(g_lsem[i * NSPL_ + p] - M);
            g_lse[i] = M + logf(S);
        }
    } else {
        for (int j = threadIdx.x; j < ECAP_; j += blockDim.x) {
            float s = g_hnpart[0][j] + g_hnpart[1][j] + g_hnpart[2][j] + g_hnpart[3][j];
            g_hnorm[j] = fmaxf(sqrtf(s), 1e-8f);
        }
    }
}

// fused losses: blocks [0,500) = cl rows; [500,700) = hn rows (+ fn for i<100)
__global__ void losses_kernel(const float* __restrict__ Ho, const float* __restrict__ Hp) {
    __shared__ float sm[32];
    int b = blockIdx.x;
    int tid = threadIdx.x;
    if (b < ECAP_) {
        __shared__ float zi[256];
        __shared__ float logit[500];
        int i = b;
        zi[tid] = g_z[i * D_ + tid] / g_znorm[i];
        __syncthreads();
        int w = tid >> 5, lane = tid & 31;
        for (int j = w; j < ECAP_; j += 8) {
            float s = 0.f;
#pragma unroll
            for (int t = 0; t < 8; t++) { int k = lane + 32 * t; s += zi[k] * g_hedges[j * D_ + k]; }
            s = warp_sum(s);
            if (lane == 0) logit[j] = s / (g_hnorm[j] * TAU_F);
        }
        __syncthreads();
        float lm = -FLT_MAX;
        for (int j = tid; j < ECAP_; j += 256) lm = fmaxf(lm, logit[j]);
        float M = block_max(lm, sm);
        float ls = 0.f;
        for (int j = tid; j < ECAP_; j += 256) ls += __expf(logit[j] - M);
        float S = block_sum(ls, sm);
        if (tid == 0) g_clrow[i] = logit[i] - (M + logf(S));
    } else {
        int i = b - ECAP_;   // 0..199
        {
            int j = tid;
            bool act = j < MHN_;
            float simv = act ? g_sim[i * MHN_ + j] : 0.f;
            float attv = act ? g_att[i * MHN_ + j] : 1.f;
            bool mask = act && (j != i) && (simv > MU_F) && (attv < NU_F);
            float neg = -simv / TAU_F;
            float m = block_max(mask ? neg : -FLT_MAX, sm);
            if (m == -FLT_MAX) {
                if (tid == 0) { g_hnsum[i] = 0.f; g_hncnt[i] = 0.f; }
            } else {
                float s = block_sum(mask ? expf(neg - m) : 0.f, sm);
                float lse = m + logf(s);
                float wgt = fminf(simv / MU_F, 1.f);
                float pair = -wgt * (neg - lse);
                float ps = block_sum(mask ? pair : 0.f, sm);
                float pc = block_sum(mask ? 1.f : 0.f, sm);
                if (tid == 0) { g_hnsum[i] = ps; g_hncnt[i] = pc; }
            }
        }
        if (i < MFN_) {
            __shared__ unsigned char cand[128];
            __shared__ short clist[MFN_];
            __shared__ int ncand;
            if (tid < 128) cand[tid] = 0;
            __syncthreads();
            if (tid < MFN_) {
                bool g = (tid > i) && (g_sim[i * MHN_ + tid] > GAMMA_F)
                                   && (g_att[i * MHN_ + tid] > DELTA_F);
                cand[tid] = g ? 1 : 0;
            }
            __syncthreads();
            if (tid == 0) {
                int n = 0;
                for (int j = i + 1; j < MFN_; j++) if (cand[j]) clist[n++] = (short)j;
                ncand = n;
            }
            __syncthreads();
            int nc = ncand;
            float fsum = 0.f, fcnt = 0.f;
            for (int k = 0; k < nc; k++) {
                int j = clist[k];
                float ao = 0.f, ap = 0.f;
                for (int t = tid; t < E_; t += 256) {
                    ao += Ho[i * E_ + t] * Ho[j * E_ + t];
                    ap += Hp[i * E_ + t] * Hp[j * E_ + t];
                }
                ao = block_sum(ao, sm);
                ap = block_sum(ap, sm);
                if (ap == 0.f && ao > 0.f) {
                    fsum += -(g_sim[i * MHN_ + j] / TAU_F - g_lse[i]);
                    fcnt += 1.f;
                }
            }
            if (tid == 0) { g_fnrow[i] = fsum; g_fncnt[i] = fcnt; }
        }
    }
}

// final combine (single block, deterministic)
__global__ void final_kernel(const float* __restrict__ bw, float* __restrict__ out) {
    __shared__ float sm[32];
    int tid = threadIdx.x;
    float v = 0.f;
    for (int i = tid; i < ECAP_; i += 512) v += g_clrow[i];
    float clsum = block_sum(v, sm);
    v = 0.f; float c = 0.f;
    for (int i = tid; i < MFN_; i += 512) { v += g_fnrow[i]; c += g_fncnt[i]; }
    float fnsum = block_sum(v, sm);
    float fncnt = block_sum(c, sm);
    v = 0.f; c = 0.f;
    for (int i = tid; i < MHN_; i += 512) { v += g_hnsum[i]; c += g_hncnt[i]; }
    float hnsum = block_sum(v, sm);
    float hncnt = block_sum(c, sm);
    float d2 = 0.f, o2 = 0.f;
    for (int i = tid; i < SAMP_; i += 512) { d2 += g_topo[i * 2]; o2 += g_topo[i * 2 + 1]; }
    float D2 = block_sum(d2, sm);
    float O2 = block_sum(o2, sm);
    float za = 0.f, zb = 0.f;
    for (int i = tid; i < 2048; i += 512) { za += (float)g_nza[i]; zb += (float)g_nzb[i]; }
    float NZ = block_sum(za, sm);
    float NZP = block_sum(zb, sm);
    if (tid == 0) {
        float cl_loss = -clsum / (float)ECAP_;
        float fn_loss = (fncnt > 0.f) ? fnsum / fmaxf(fncnt, 1.f) : 0.f;
        float hard_loss = (hncnt > 0.f) ? hnsum / fmaxf(hncnt, 1.f) : 0.f;
        float sparsity = (NZ > 0.f) ? NZP / fmaxf(NZ, 1.f) : 1.f;
        float dn = sqrtf(D2), on = sqrtf(O2);
        float topo = (on > 0.f) ? expf(-ALPHA_F * dn / fmaxf(on, 1e-12f)) : 1.f;
        float retention = sparsity * topo;
        out[0] = bw[0] * (retention * cl_loss + fn_loss + hard_loss);
    }
}

// ---------------- launch ----------------
extern "C" void kernel_launch(void* const* d_in, const int* in_sizes, int n_in,
                              void* d_out, int out_size) {
    (void)in_sizes; (void)n_in; (void)out_size;
    const float* Ho  = (const float*)d_in[0];
    const float* Hp  = (const float*)d_in[1];
    const float* ne  = (const float*)d_in[2];
    const float* bw  = (const float*)d_in[3];
    const float* Wn1 = (const float*)d_in[4];
    const float* bn1 = (const float*)d_in[5];
    const float* Wn2 = (const float*)d_in[6];
    const float* bn2 = (const float*)d_in[7];
    const float* We1 = (const float*)d_in[8];
    const float* be1 = (const float*)d_in[9];
    const float* We2 = (const float*)d_in[10];
    const float* be2 = (const float*)d_in[11];
    float* out = (float*)d_out;

    void *p;
    float *p_tmp, *p_z, *p_etmp, *p_hedges;
    cudaGetSymbolAddress(&p, g_tmp);    p_tmp    = (float*)p;
    cudaGetSymbolAddress(&p, g_z);      p_z      = (float*)p;
    cudaGetSymbolAddress(&p, g_etmp);   p_etmp   = (float*)p;
    cudaGetSymbolAddress(&p, g_hedges); p_hedges = (float*)p;

    // idx 0-2: node MLP (+fused znorm partials) + finalize
    gemm_nk_kernel<true,  false><<<dim3(64, 4), 256>>>(ne,    Wn1, bn1, p_tmp);
    gemm_nk_kernel<false, true ><<<dim3(64, 4), 256>>>(p_tmp, Wn2, bn2, p_z);
    znorm_fin_kernel<<<32, 256>>>();

    // idx 3: attlse (PROFILED this round)
    attlse_kernel<<<dim3(25, NSPL_), 256>>>();

    // idx 4: edge aggregation partials (reworked warp-local path)
    edge_part_kernel<<<dim3(ECAP_ / 4, 8), 256>>>(Hp, p_z);

    // idx 5-6: edge MLP
    gemm64_e1_kernel<<<dim3(8, 4), 256>>>(We1, be1, p_etmp);
    gemm64_e2_kernel<<<dim3(8, 4), 256>>>(p_etmp, We2, be2, p_hedges);

    // idx 7: merge finalizers (att softmax, lse, hnorm)
    merge_kernel<<<MHN_ + 2, 256>>>();

    // idx 8-9: independent scans
    count_nz_kernel<<<2048, 256>>>((const float4*)Ho, (const float4*)Hp);
    topo_kernel<<<SAMP_, 128>>>(Ho, Hp);

    // idx 10: fused losses
    losses_kernel<<<ECAP_ + MHN_, 256>>>(Ho, Hp);

    // idx 11: final combine
    final_kernel<<<1, 512>>>(bw, out);
}

// round 7
// speedup vs baseline: 5.2380x; 1.6258x over previous
#include <cuda_runtime.h>
#include <math.h>
#include <cfloat>

// ---------------- constants ----------------
#define TAU_F   0.4f
#define ALPHA_F 1.0f
#define GAMMA_F 0.7f
#define DELTA_F 0.6f
#define MU_F    0.6f
#define NU_F    0.3f

#define N_  8192
#define E_  2048
#define D_  256
#define SAMP_ 100
#define MFN_  100
#define MHN_  200
#define ECAP_ 500
#define NSPL_ 64

// ---------------- scratch (device globals) ----------------
__device__ float g_tmp[N_ * D_];
__device__ float g_z[N_ * D_];
__device__ float g_znpart[4][N_];
__device__ float g_znorm[N_];
__device__ float g_edge_part[8][512 * D_];
__device__ int   g_cntp[8][512];
__device__ float g_etmp[512 * D_];
__device__ float g_hedges[512 * D_];
__device__ float g_hnpart[4][512];
__device__ float g_hnorm[ECAP_];
__device__ float g_sim[MHN_ * MHN_];
__device__ float g_attdot[MHN_ * MHN_];
__device__ float g_attm[MHN_ * NSPL_], g_atts[MHN_ * NSPL_];
__device__ float g_att[MHN_ * MHN_];
__device__ float g_lsem[MFN_ * NSPL_], g_lses[MFN_ * NSPL_];
__device__ float g_lse[MFN_];
__device__ float g_clrow[ECAP_];
__device__ float g_fnrow[MFN_], g_fncnt[MFN_];
__device__ float g_hnsum[MHN_], g_hncnt[MHN_];
__device__ int   g_nza[2048], g_nzb[2048];
__device__ float g_topo[SAMP_ * 2];

// ---------------- reduction helpers ----------------
__device__ __forceinline__ float warp_sum(float v) {
#pragma unroll
    for (int o = 16; o > 0; o >>= 1) v += __shfl_xor_sync(0xffffffffu, v, o);
    return v;
}
__device__ __forceinline__ float warp_max(float v) {
#pragma unroll
    for (int o = 16; o > 0; o >>= 1) v = fmaxf(v, __shfl_xor_sync(0xffffffffu, v, o));
    return v;
}
__device__ __forceinline__ int warp_sum_i(int v) {
#pragma unroll
    for (int o = 16; o > 0; o >>= 1) v += __shfl_xor_sync(0xffffffffu, v, o);
    return v;
}
__device__ float block_sum(float v, float* sm) {
    int w = threadIdx.x >> 5, lane = threadIdx.x & 31, nw = blockDim.x >> 5;
    v = warp_sum(v);
    if (lane == 0) sm[w] = v;
    __syncthreads();
    float r = (threadIdx.x < nw) ? sm[threadIdx.x] : 0.f;
    if (w == 0) r = warp_sum(r);
    if (threadIdx.x == 0) sm[0] = r;
    __syncthreads();
    r = sm[0];
    __syncthreads();
    return r;
}
__device__ float block_max(float v, float* sm) {
    int w = threadIdx.x >> 5, lane = threadIdx.x & 31, nw = blockDim.x >> 5;
    v = warp_max(v);
    if (lane == 0) sm[w] = v;
    __syncthreads();
    float r = (threadIdx.x < nw) ? sm[threadIdx.x] : -FLT_MAX;
    if (w == 0) r = warp_max(r);
    if (threadIdx.x == 0) sm[0] = r;
    __syncthreads();
    r = sm[0];
    __syncthreads();
    return r;
}

// ---------------- kernels ----------------

// nonzero counts: per-block partials, no atomics
__global__ void count_nz_kernel(const float4* __restrict__ a, const float4* __restrict__ b) {
    const int n4 = N_ * E_ / 4;
    int ca = 0, cb = 0;
    for (int i = blockIdx.x * blockDim.x + threadIdx.x; i < n4; i += gridDim.x * blockDim.x) {
        float4 x = a[i];
        ca += (x.x != 0.f) + (x.y != 0.f) + (x.z != 0.f) + (x.w != 0.f);
        float4 y = b[i];
        cb += (y.x != 0.f) + (y.y != 0.f) + (y.z != 0.f) + (y.w != 0.f);
    }
    __shared__ int sa[32], sb[32];
    int w = threadIdx.x >> 5, lane = threadIdx.x & 31;
    ca = warp_sum_i(ca); cb = warp_sum_i(cb);
    if (lane == 0) { sa[w] = ca; sb[w] = cb; }
    __syncthreads();
    if (w == 0) {
        int x = (lane < 8) ? sa[lane] : 0;
        int y = (lane < 8) ? sb[lane] : 0;
        x = warp_sum_i(x); y = warp_sum_i(y);
        if (lane == 0) { g_nza[blockIdx.x] = x; g_nzb[blockIdx.x] = y; }
    }
}

// topology: one block per row i of the 100x100 sample
__global__ void topo_kernel(const float* __restrict__ Ho, const float* __restrict__ Hp) {
    __shared__ float hoi[128], hpi[128];
    __shared__ float sm[32];
    int i = blockIdx.x;
    int tid = threadIdx.x;
    if (tid < SAMP_) { hoi[tid] = Ho[i * E_ + tid]; hpi[tid] = Hp[i * E_ + tid]; }
    else             { hoi[tid] = 0.f; hpi[tid] = 0.f; }
    __syncthreads();
    int w = tid >> 5, lane = tid & 31;
    float dn2 = 0.f, on2 = 0.f;
    for (int j = w; j < SAMP_; j += 4) {
        float as = 0.f, aps = 0.f;
#pragma unroll
        for (int t = 0; t < 4; t++) {
            int k = lane + 32 * t;
            if (k < SAMP_) {
                as  += hoi[k] * Ho[j * E_ + k];
                aps += hpi[k] * Hp[j * E_ + k];
            }
        }
        as = warp_sum(as);
        aps = warp_sum(aps);
        if (lane == 0) {
            float d = as - aps;
            dn2 += d * d;
            on2 += as * as;
        }
    }
    float D2 = block_sum(dn2, sm);
    float O2 = block_sum(on2, sm);
    if (tid == 0) { g_topo[i * 2] = D2; g_topo[i * 2 + 1] = O2; }
}

// node MLP GEMM: BM=128, BN=64, BK=16, 8x4 microtile, 256 threads.
template <bool RELU, bool NORM>
__global__ void gemm_nk_kernel(const float* __restrict__ A, const float* __restrict__ B,
                               const float* __restrict__ bias, float* __restrict__ C) {
    __shared__ float As[16][132];
    __shared__ float Bs[16][68];
    __shared__ float ssq[128][17];
    const int bm = blockIdx.x * 128, bn = blockIdx.y * 64;
    const int tid = threadIdx.x;
    const int tx = tid & 15, ty = tid >> 4;
    float acc[8][4] = {};
    for (int k0 = 0; k0 < D_; k0 += 16) {
#pragma unroll
        for (int l = 0; l < 2; l++) {
            int id = tid * 2 + l;
            int r = id >> 2, c4 = id & 3;
            float4 v = *(const float4*)&A[(bm + r) * D_ + k0 + c4 * 4];
            As[c4 * 4 + 0][r] = v.x;
            As[c4 * 4 + 1][r] = v.y;
            As[c4 * 4 + 2][r] = v.z;
            As[c4 * 4 + 3][r] = v.w;
        }
        {
            int r = tid >> 4, c4 = tid & 15;
            float4 v = *(const float4*)&B[(k0 + r) * D_ + bn + c4 * 4];
            *(float4*)&Bs[r][c4 * 4] = v;
        }
        __syncthreads();
#pragma unroll
        for (int kk = 0; kk < 16; kk++) {
            float a[8], b[4];
#pragma unroll
            for (int u = 0; u < 8; u++) a[u] = As[kk][ty * 8 + u];
#pragma unroll
            for (int u = 0; u < 4; u++) b[u] = Bs[kk][tx * 4 + u];
#pragma unroll
            for (int i = 0; i < 8; i++)
#pragma unroll
                for (int j = 0; j < 4; j++) acc[i][j] += a[i] * b[j];
        }
        __syncthreads();
    }
#pragma unroll
    for (int i = 0; i < 8; i++) {
        int row = bm + ty * 8 + i;
        float sq = 0.f;
#pragma unroll
        for (int j = 0; j < 4; j++) {
            int col = bn + tx * 4 + j;
            float v = acc[i][j] + bias[col];
            if (RELU) v = fmaxf(v, 0.f);
            C[row * D_ + col] = v;
            sq += v * v;
        }
        if (NORM) ssq[ty * 8 + i][tx] = sq;
    }
    if (NORM) {
        __syncthreads();
        if (tid < 128) {
            float s = 0.f;
#pragma unroll
            for (int q = 0; q < 16; q++) s += ssq[tid][q];
            g_znpart[blockIdx.y][bm + tid] = s;
        }
    }
}

// finalize z norms from 4 BN-block partials
__global__ void znorm_fin_kernel() {
    int r = blockIdx.x * 256 + threadIdx.x;
    float s = g_znpart[0][r] + g_znpart[1][r] + g_znpart[2][r] + g_znpart[3][r];
    g_znorm[r] = fmaxf(sqrtf(s), 1e-8f);
}

// GEMM-style att/sim/lse: block = 64 rows x 128 j-cols, BK=16, 4x8 microtile.
// blockIdx.x = row tile (0..3 -> rows 0..255, stores guarded i<200),
// blockIdx.y = j split (0..63).
__global__ void attgemm_kernel() {
    __shared__ float As[16][68];
    __shared__ float Bs[16][132];
    __shared__ float redm[64][17], reds[64][17];
    __shared__ float s_invi[64], s_invj[128];
    const int bm = blockIdx.x * 64;
    const int sp = blockIdx.y;
    const int j0 = sp * 128;
    const int tid = threadIdx.x;
    const int tx = tid & 15, ty = tid >> 4;
    if (tid < 64)  s_invi[tid] = 1.f / g_znorm[bm + tid];
    else if (tid < 192) s_invj[tid - 64] = 1.f / g_znorm[j0 + tid - 64];
    float acc[4][8] = {};
    for (int k0 = 0; k0 < D_; k0 += 16) {
        {
            int r = tid >> 2, c4 = tid & 3;
            float4 v = *(const float4*)&g_z[(bm + r) * D_ + k0 + c4 * 4];
            As[c4 * 4 + 0][r] = v.x;
            As[c4 * 4 + 1][r] = v.y;
            As[c4 * 4 + 2][r] = v.z;
            As[c4 * 4 + 3][r] = v.w;
        }
#pragma unroll
        for (int l = 0; l < 2; l++) {
            int id = tid * 2 + l;
            int jr = id >> 2, c4 = id & 3;
            float4 v = *(const float4*)&g_z[(j0 + jr) * D_ + k0 + c4 * 4];
            Bs[c4 * 4 + 0][jr] = v.x;
            Bs[c4 * 4 + 1][jr] = v.y;
            Bs[c4 * 4 + 2][jr] = v.z;
            Bs[c4 * 4 + 3][jr] = v.w;
        }
        __syncthreads();
#pragma unroll
        for (int kk = 0; kk < 16; kk++) {
            float4 a4 = *(const float4*)&As[kk][ty * 4];
            float4 b4a = *(const float4*)&Bs[kk][tx * 8];
            float4 b4b = *(const float4*)&Bs[kk][tx * 8 + 4];
            float a[4] = {a4.x, a4.y, a4.z, a4.w};
            float b[8] = {b4a.x, b4a.y, b4a.z, b4a.w, b4b.x, b4b.y, b4b.z, b4b.w};
#pragma unroll
            for (int i = 0; i < 4; i++)
#pragma unroll
                for (int j = 0; j < 8; j++) acc[i][j] += a[i] * b[j];
        }
        __syncthreads();
    }
    // store raw dots + sim for (i<200, j<200)
    if (j0 < MHN_) {
#pragma unroll
        for (int r = 0; r < 4; r++) {
            int i = bm + ty * 4 + r;
            if (i >= MHN_) continue;
            float invi = s_invi[ty * 4 + r];
#pragma unroll
            for (int c = 0; c < 8; c++) {
                int j = j0 + tx * 8 + c;
                if (j < MHN_) {
                    g_attdot[i * MHN_ + j] = acc[r][c];
                    g_sim[i * MHN_ + j] = acc[r][c] * invi * s_invj[tx * 8 + c];
                }
            }
        }
    }
    // att softmax partials over this j tile (raw dots, all rows; store i<200)
#pragma unroll
    for (int r = 0; r < 4; r++) {
        float m = -FLT_MAX;
#pragma unroll
        for (int c = 0; c < 8; c++) m = fmaxf(m, acc[r][c]);
        float s = 0.f;
#pragma unroll
        for (int c = 0; c < 8; c++) s += __expf(acc[r][c] - m);
        redm[ty * 4 + r][tx] = m;
        reds[ty * 4 + r][tx] = s;
    }
    __syncthreads();
    if (tid < 64) {
        int i = bm + tid;
        if (i < MHN_) {
            float M = -FLT_MAX;
#pragma unroll
            for (int q = 0; q < 16; q++) M = fmaxf(M, redm[tid][q]);
            float S = 0.f;
#pragma unroll
            for (int q = 0; q < 16; q++) S += reds[tid][q] * __expf(redm[tid][q] - M);
            g_attm[i * NSPL_ + sp] = M;
            g_atts[i * NSPL_ + sp] = S;
        }
    }
    // lse partials (normalized dots / tau, rows i<100)
    if (bm < MFN_) {
        __syncthreads();
#pragma unroll
        for (int r = 0; r < 4; r++) {
            float vi = s_invi[ty * 4 + r] * (1.f / TAU_F);
            float m = -FLT_MAX;
            float vv[8];
#pragma unroll
            for (int c = 0; c < 8; c++) {
                vv[c] = acc[r][c] * vi * s_invj[tx * 8 + c];
                m = fmaxf(m, vv[c]);
            }
            float s = 0.f;
#pragma unroll
            for (int c = 0; c < 8; c++) s += __expf(vv[c] - m);
            redm[ty * 4 + r][tx] = m;
            reds[ty * 4 + r][tx] = s;
        }
        __syncthreads();
        if (tid < 64) {
            int i = bm + tid;
            if (i < MFN_) {
                float M = -FLT_MAX;
#pragma unroll
                for (int q = 0; q < 16; q++) M = fmaxf(M, redm[tid][q]);
                float S = 0.f;
#pragma unroll
                for (int q = 0; q < 16; q++) S += reds[tid][q] * __expf(redm[tid][q] - M);
                g_lsem[i * NSPL_ + sp] = M;
                g_lses[i * NSPL_ + sp] = S;
            }
        }
    }
}

// Sparse edge aggregation: grid (125 edge-groups, 8 i-splits), warp-local rows.
__global__ void edge_part_kernel(const float* __restrict__ Hp, const float* __restrict__ z) {
    __shared__ float racc[8][4][256];
    __shared__ int rcnt[8][4];
    const int tid = threadIdx.x;
    const int lane = tid & 31, w = tid >> 5;
    const int e0 = blockIdx.x * 4, sp = blockIdx.y;
    float acc[4][8] = {};
    int cnt[4] = {0, 0, 0, 0};
    const int ibase = sp * 1024;
#pragma unroll 1
    for (int ic = 0; ic < 1024; ic += 256) {
        int i0 = ibase + ic;
        float4 v = *(const float4*)&Hp[(size_t)(i0 + tid) * E_ + e0];
        int m = (v.x > 0.f) | ((v.y > 0.f) << 1) | ((v.z > 0.f) << 2) | ((v.w > 0.f) << 3);
        unsigned b = __ballot_sync(0xffffffffu, m != 0);
        int rowbase = i0 + w * 32;
        while (b) {
            int src = __ffs(b) - 1;
            b &= b - 1;
            int mm = __shfl_sync(0xffffffffu, m, src);
            const float* zr = &z[(size_t)(rowbase + src) * D_];
            float zv[8];
#pragma unroll
            for (int t = 0; t < 8; t++) zv[t] = zr[lane + 32 * t];
            switch (mm) {
                case 1:
#pragma unroll
                    for (int t = 0; t < 8; t++) acc[0][t] += zv[t];
                    cnt[0]++; break;
                case 2:
#pragma unroll
                    for (int t = 0; t < 8; t++) acc[1][t] += zv[t];
                    cnt[1]++; break;
                case 4:
#pragma unroll
                    for (int t = 0; t < 8; t++) acc[2][t] += zv[t];
                    cnt[2]++; break;
                case 8:
#pragma unroll
                    for (int t = 0; t < 8; t++) acc[3][t] += zv[t];
                    cnt[3]++; break;
                default:
                    if (mm & 1) {
#pragma unroll
                        for (int t = 0; t < 8; t++) acc[0][t] += zv[t];
                        cnt[0]++;
                    }
                    if (mm & 2) {
#pragma unroll
                        for (int t = 0; t < 8; t++) acc[1][t] += zv[t];
                        cnt[1]++;
                    }
                    if (mm & 4) {
#pragma unroll
                        for (int t = 0; t < 8; t++) acc[2][t] += zv[t];
                        cnt[2]++;
                    }
                    if (mm & 8) {
#pragma unroll
                        for (int t = 0; t < 8; t++) acc[3][t] += zv[t];
                        cnt[3]++;
                    }
            }
        }
    }
#pragma unroll
    for (int e = 0; e < 4; e++)
#pragma unroll
        for (int t = 0; t < 8; t++) racc[w][e][lane + 32 * t] = acc[e][t];
    if (lane == 0) {
#pragma unroll
        for (int e = 0; e < 4; e++) rcnt[w][e] = cnt[e];
    }
    __syncthreads();
#pragma unroll
    for (int e = 0; e < 4; e++) {
        float s = 0.f;
#pragma unroll
        for (int q = 0; q < 8; q++) s += racc[q][e][tid];
        g_edge_part[sp][(e0 + e) * D_ + tid] = s;
    }
    if (tid < 4) {
        int c = 0;
#pragma unroll
        for (int q = 0; q < 8; q++) c += rcnt[q][tid];
        g_cntp[sp][e0 + tid] = c;
    }
}

// edge MLP layer 1: A = mean(edge partials) computed on the fly
__global__ void gemm64_e1_kernel(const float* __restrict__ B, const float* __restrict__ bias,
                                 float* __restrict__ C) {
    __shared__ float As[16][68];
    __shared__ float Bs[16][68];
    const int bm = blockIdx.x * 64, bn = blockIdx.y * 64;
    const int tid = threadIdx.x;
    const int tx = tid & 15, ty = tid >> 4;
    const int arow = bm + (tid >> 2);
    float cinv = 0.f;
    {
        int c = 0;
#pragma unroll
        for (int p = 0; p < 8; p++) c += g_cntp[p][arow];
        cinv = (c > 0 && arow < ECAP_) ? 1.f / (float)c : 0.f;
    }
    float acc[4][4] = {};
    for (int k0 = 0; k0 < D_; k0 += 16) {
        {
            int r = tid >> 2, c4 = tid & 3;
            float4 s = make_float4(0.f, 0.f, 0.f, 0.f);
#pragma unroll
            for (int p = 0; p < 8; p++) {
                float4 t = *(const float4*)&g_edge_part[p][arow * D_ + k0 + c4 * 4];
                s.x += t.x; s.y += t.y; s.z += t.z; s.w += t.w;
            }
            As[c4 * 4 + 0][r] = s.x * cinv;
            As[c4 * 4 + 1][r] = s.y * cinv;
            As[c4 * 4 + 2][r] = s.z * cinv;
            As[c4 * 4 + 3][r] = s.w * cinv;
        }
        {
            int r = tid >> 4, c4 = tid & 15;
            float4 v = *(const float4*)&B[(k0 + r) * D_ + bn + c4 * 4];
            *(float4*)&Bs[r][c4 * 4] = v;
        }
        __syncthreads();
#pragma unroll
        for (int kk = 0; kk < 16; kk++) {
            float a[4], b[4];
#pragma unroll
            for (int u = 0; u < 4; u++) a[u] = As[kk][ty * 4 + u];
#pragma unroll
            for (int u = 0; u < 4; u++) b[u] = Bs[kk][tx * 4 + u];
#pragma unroll
            for (int i = 0; i < 4; i++)
#pragma unroll
                for (int j = 0; j < 4; j++) acc[i][j] += a[i] * b[j];
        }
        __syncthreads();
    }
#pragma unroll
    for (int i = 0; i < 4; i++) {
        int row = bm + ty * 4 + i;
#pragma unroll
        for (int j = 0; j < 4; j++) {
            int col = bn + tx * 4 + j;
            C[row * D_ + col] = fmaxf(acc[i][j] + bias[col], 0.f);
        }
    }
}

// edge MLP layer 2: writes hedges + per-block row sumsq partials for hnorm
__global__ void gemm64_e2_kernel(const float* __restrict__ A, const float* __restrict__ B,
                                 const float* __restrict__ bias, float* __restrict__ C) {
    __shared__ float As[16][68];
    __shared__ float Bs[16][68];
    __shared__ float ssq[64][17];
    const int bm = blockIdx.x * 64, bn = blockIdx.y * 64;
    const int tid = threadIdx.x;
    const int tx = tid & 15, ty = tid >> 4;
    float acc[4][4] = {};
    for (int k0 = 0; k0 < D_; k0 += 16) {
        {
            int r = tid >> 2, c4 = tid & 3;
            float4 v = *(const float4*)&A[(bm + r) * D_ + k0 + c4 * 4];
            As[c4 * 4 + 0][r] = v.x;
            As[c4 * 4 + 1][r] = v.y;
            As[c4 * 4 + 2][r] = v.z;
            As[c4 * 4 + 3][r] = v.w;
        }
        {
            int r = tid >> 4, c4 = tid & 15;
            float4 v = *(const float4*)&B[(k0 + r) * D_ + bn + c4 * 4];
            *(float4*)&Bs[r][c4 * 4] = v;
        }
        __syncthreads();
#pragma unroll
        for (int kk = 0; kk < 16; kk++) {
            float a[4], b[4];
#pragma unroll
            for (int u = 0; u < 4; u++) a[u] = As[kk][ty * 4 + u];
#pragma unroll
            for (int u = 0; u < 4; u++) b[u] = Bs[kk][tx * 4 + u];
#pragma unroll
            for (int i = 0; i < 4; i++)
#pragma unroll
                for (int j = 0; j < 4; j++) acc[i][j] += a[i] * b[j];
        }
        __syncthreads();
    }
#pragma unroll
    for (int i = 0; i < 4; i++) {
        int row = bm + ty * 4 + i;
        float sq = 0.f;
#pragma unroll
        for (int j = 0; j < 4; j++) {
            int col = bn + tx * 4 + j;
            float v = acc[i][j] + bias[col];
            C[row * D_ + col] = v;
            sq += v * v;
        }
        ssq[ty * 4 + i][tx] = sq;
    }
    __syncthreads();
    if (tid < 64) {
        float s = 0.f;
#pragma unroll
        for (int q = 0; q < 16; q++) s += ssq[tid][q];
        g_hnpart[blockIdx.y][bm + tid] = s;
    }
}

// merged finalize: att rows (0..199), lse (200), hnorm (201)
__global__ void merge_kernel() {
    int b = blockIdx.x;
    if (b < MHN_) {
        int i = b;
        __shared__ float Ms, Ss;
        if (threadIdx.x == 0) {
            float M = -FLT_MAX;
            for (int p = 0; p < NSPL_; p++) M = fmaxf(M, g_attm[i * NSPL_ + p]);
            float S = 0.f;
            for (int p = 0; p < NSPL_; p++) S += g_atts[i * NSPL_ + p] * __expf(g_attm[i * NSPL_ + p] - M);
            Ms = M; Ss = S;
        }
        __syncthreads();
        for (int j = threadIdx.x; j < MHN_; j += blockDim.x)
            g_att[i * MHN_ + j] = __expf(g_attdot[i * MHN_ + j] - Ms) / Ss;
    } else if (b == MHN_) {
        int i = threadIdx.x;
        if (i < MFN_) {
            float M = -FLT_MAX;
            for (int p = 0; p < NSPL_; p++) M = fmaxf(M, g_lsem[i * NSPL_ + p]);
            float S = 0.f;
            for (int p = 0; p < NSPL_; p++) S += g_lses[i * NSPL_ + p] * __expf(g_lsem[i * NSPL_ + p] - M);
            g_lse[i] = M + logf(S);
        }
    } else {
        for (int j = threadIdx.x; j < ECAP_; j += blockDim.x) {
            float s = g_hnpart[0][j] + g_hnpart[1][j] + g_hnpart[2][j] + g_hnpart[3][j];
            g_hnorm[j] = fmaxf(sqrtf(s), 1e-8f);
        }
    }
}

// fused losses: blocks [0,500) = cl rows; [500,700) = hn rows (+ fn for i<100)
__global__ void losses_kernel(const float* __restrict__ Ho, const float* __restrict__ Hp) {
    __shared__ float sm[32];
    int b = blockIdx.x;
    int tid = threadIdx.x;
    if (b < ECAP_) {
        __shared__ float zi[256];
        __shared__ float logit[500];
        int i = b;
        zi[tid] = g_z[i * D_ + tid] / g_znorm[i];
        __syncthreads();
        int w = tid >> 5, lane = tid & 31;
        for (int j = w; j < ECAP_; j += 8) {
            float s = 0.f;
#pragma unroll
            for (int t = 0; t < 8; t++) { int k = lane + 32 * t; s += zi[k] * g_hedges[j * D_ + k]; }
            s = warp_sum(s);
            if (lane == 0) logit[j] = s / (g_hnorm[j] * TAU_F);
        }
        __syncthreads();
        float lm = -FLT_MAX;
        for (int j = tid; j < ECAP_; j += 256) lm = fmaxf(lm, logit[j]);
        float M = block_max(lm, sm);
        float ls = 0.f;
        for (int j = tid; j < ECAP_; j += 256) ls += __expf(logit[j] - M);
        float S = block_sum(ls, sm);
        if (tid == 0) g_clrow[i] = logit[i] - (M + logf(S));
    } else {
        int i = b - ECAP_;   // 0..199
        {
            int j = tid;
            bool act = j < MHN_;
            float simv = act ? g_sim[i * MHN_ + j] : 0.f;
            float attv = act ? g_att[i * MHN_ + j] : 1.f;
            bool mask = act && (j != i) && (simv > MU_F) && (attv < NU_F);
            float neg = -simv / TAU_F;
            float m = block_max(mask ? neg : -FLT_MAX, sm);
            if (m == -FLT_MAX) {
                if (tid == 0) { g_hnsum[i] = 0.f; g_hncnt[i] = 0.f; }
            } else {
                float s = block_sum(mask ? expf(neg - m) : 0.f, sm);
                float lse = m + logf(s);
                float wgt = fminf(simv / MU_F, 1.f);
                float pair = -wgt * (neg - lse);
                float ps = block_sum(mask ? pair : 0.f, sm);
                float pc = block_sum(mask ? 1.f : 0.f, sm);
                if (tid == 0) { g_hnsum[i] = ps; g_hncnt[i] = pc; }
            }
        }
        if (i < MFN_) {
            __shared__ unsigned char cand[128];
            __shared__ short clist[MFN_];
            __shared__ int ncand;
            if (tid < 128) cand[tid] = 0;
            __syncthreads();
            if (tid < MFN_) {
                bool g = (tid > i) && (g_sim[i * MHN_ + tid] > GAMMA_F)
                                   && (g_att[i * MHN_ + tid] > DELTA_F);
                cand[tid] = g ? 1 : 0;
            }
            __syncthreads();
            if (tid == 0) {
                int n = 0;
                for (int j = i + 1; j < MFN_; j++) if (cand[j]) clist[n++] = (short)j;
                ncand = n;
            }
            __syncthreads();
            int nc = ncand;
            float fsum = 0.f, fcnt = 0.f;
            for (int k = 0; k < nc; k++) {
                int j = clist[k];
                float ao = 0.f, ap = 0.f;
                for (int t = tid; t < E_; t += 256) {
                    ao += Ho[i * E_ + t] * Ho[j * E_ + t];
                    ap += Hp[i * E_ + t] * Hp[j * E_ + t];
                }
                ao = block_sum(ao, sm);
                ap = block_sum(ap, sm);
                if (ap == 0.f && ao > 0.f) {
                    fsum += -(g_sim[i * MHN_ + j] / TAU_F - g_lse[i]);
                    fcnt += 1.f;
                }
            }
            if (tid == 0) { g_fnrow[i] = fsum; g_fncnt[i] = fcnt; }
        }
    }
}

// final combine (single block, deterministic)
__global__ void final_kernel(const float* __restrict__ bw, float* __restrict__ out) {
    __shared__ float sm[32];
    int tid = threadIdx.x;
    float v = 0.f;
    for (int i = tid; i < ECAP_; i += 512) v += g_clrow[i];
    float clsum = block_sum(v, sm);
    v = 0.f; float c = 0.f;
    for (int i = tid; i < MFN_; i += 512) { v += g_fnrow[i]; c += g_fncnt[i]; }
    float fnsum = block_sum(v, sm);
    float fncnt = block_sum(c, sm);
    v = 0.f; c = 0.f;
    for (int i = tid; i < MHN_; i += 512) { v += g_hnsum[i]; c += g_hncnt[i]; }
    float hnsum = block_sum(v, sm);
    float hncnt = block_sum(c, sm);
    float d2 = 0.f, o2 = 0.f;
    for (int i = tid; i < SAMP_; i += 512) { d2 += g_topo[i * 2]; o2 += g_topo[i * 2 + 1]; }
    float D2 = block_sum(d2, sm);
    float O2 = block_sum(o2, sm);
    float za = 0.f, zb = 0.f;
    for (int i = tid; i < 2048; i += 512) { za += (float)g_nza[i]; zb += (float)g_nzb[i]; }
    float NZ = block_sum(za, sm);
    float NZP = block_sum(zb, sm);
    if (tid == 0) {
        float cl_loss = -clsum / (float)ECAP_;
        float fn_loss = (fncnt > 0.f) ? fnsum / fmaxf(fncnt, 1.f) : 0.f;
        float hard_loss = (hncnt > 0.f) ? hnsum / fmaxf(hncnt, 1.f) : 0.f;
        float sparsity = (NZ > 0.f) ? NZP / fmaxf(NZ, 1.f) : 1.f;
        float dn = sqrtf(D2), on = sqrtf(O2);
        float topo = (on > 0.f) ? expf(-ALPHA_F * dn / fmaxf(on, 1e-12f)) : 1.f;
        float retention = sparsity * topo;
        out[0] = bw[0] * (retention * cl_loss + fn_loss + hard_loss);
    }
}

// ---------------- launch ----------------
extern "C" void kernel_launch(void* const* d_in, const int* in_sizes, int n_in,
                              void* d_out, int out_size) {
    (void)in_sizes; (void)n_in; (void)out_size;
    const float* Ho  = (const float*)d_in[0];
    const float* Hp  = (const float*)d_in[1];
    const float* ne  = (const float*)d_in[2];
    const float* bw  = (const float*)d_in[3];
    const float* Wn1 = (const float*)d_in[4];
    const float* bn1 = (const float*)d_in[5];
    const float* Wn2 = (const float*)d_in[6];
    const float* bn2 = (const float*)d_in[7];
    const float* We1 = (const float*)d_in[8];
    const float* be1 = (const float*)d_in[9];
    const float* We2 = (const float*)d_in[10];
    const float* be2 = (const float*)d_in[11];
    float* out = (float*)d_out;

    void *p;
    float *p_tmp, *p_z, *p_etmp, *p_hedges;
    cudaGetSymbolAddress(&p, g_tmp);    p_tmp    = (float*)p;
    cudaGetSymbolAddress(&p, g_z);      p_z      = (float*)p;
    cudaGetSymbolAddress(&p, g_etmp);   p_etmp   = (float*)p;
    cudaGetSymbolAddress(&p, g_hedges); p_hedges = (float*)p;

    // idx 0-2: node MLP (+fused znorm partials) + finalize
    gemm_nk_kernel<true,  false><<<dim3(64, 4), 256>>>(ne,    Wn1, bn1, p_tmp);
    gemm_nk_kernel<false, true ><<<dim3(64, 4), 256>>>(p_tmp, Wn2, bn2, p_z);
    znorm_fin_kernel<<<32, 256>>>();

    // idx 3: att/sim/lse GEMM (PROFILED this round)
    attgemm_kernel<<<dim3(4, NSPL_), 256>>>();

    // idx 4: edge aggregation partials
    edge_part_kernel<<<dim3(ECAP_ / 4, 8), 256>>>(Hp, p_z);

    // idx 5-6: edge MLP
    gemm64_e1_kernel<<<dim3(8, 4), 256>>>(We1, be1, p_etmp);
    gemm64_e2_kernel<<<dim3(8, 4), 256>>>(p_etmp, We2, be2, p_hedges);

    // idx 7: merge finalizers (att softmax, lse, hnorm)
    merge_kernel<<<MHN_ + 2, 256>>>();

    // idx 8-9: independent scans
    count_nz_kernel<<<2048, 256>>>((const float4*)Ho, (const float4*)Hp);
    topo_kernel<<<SAMP_, 128>>>(Ho, Hp);

    // idx 10: fused losses
    losses_kernel<<<ECAP_ + MHN_, 256>>>(Ho, Hp);

    // idx 11: final combine
    final_kernel<<<1, 512>>>(bw, out);
}

// round 8
// speedup vs baseline: 5.7315x; 1.0942x over previous
#include <cuda_runtime.h>
#include <math.h>
#include <cfloat>
#include <stdint.h>

// ---------------- constants ----------------
#define TAU_F   0.4f
#define ALPHA_F 1.0f
#define GAMMA_F 0.7f
#define DELTA_F 0.6f
#define MU_F    0.6f
#define NU_F    0.3f

#define N_  8192
#define E_  2048
#define D_  256
#define SAMP_ 100
#define MFN_  100
#define MHN_  200
#define ECAP_ 500
#define NSPL_ 64

// ---------------- scratch (device globals) ----------------
__device__ float g_tmp[N_ * D_];
__device__ float g_z[N_ * D_];
__device__ float g_znpart[4][N_];
__device__ float g_znorm[N_];
__device__ float g_edge_part[8][512 * D_];
__device__ int   g_cntp[8][512];
__device__ float g_etmp[512 * D_];
__device__ float g_hedges[512 * D_];
__device__ float g_hnpart[4][512];
__device__ float g_hnorm[ECAP_];
__device__ float g_sim[MHN_ * MHN_];
__device__ float g_attdot[MHN_ * MHN_];
__device__ float g_attm[MHN_ * NSPL_], g_atts[MHN_ * NSPL_];
__device__ float g_att[MHN_ * MHN_];
__device__ float g_lsem[MFN_ * NSPL_], g_lses[MFN_ * NSPL_];
__device__ float g_lse[MFN_];
__device__ float g_clrow[ECAP_];
__device__ float g_fnrow[MFN_], g_fncnt[MFN_];
__device__ float g_hnsum[MHN_], g_hncnt[MHN_];
__device__ int   g_nza[2048], g_nzb[2048];
__device__ float g_topo[SAMP_ * 2];

// ---------------- helpers ----------------
__device__ __forceinline__ float warp_sum(float v) {
#pragma unroll
    for (int o = 16; o > 0; o >>= 1) v += __shfl_xor_sync(0xffffffffu, v, o);
    return v;
}
__device__ __forceinline__ float warp_max(float v) {
#pragma unroll
    for (int o = 16; o > 0; o >>= 1) v = fmaxf(v, __shfl_xor_sync(0xffffffffu, v, o));
    return v;
}
__device__ __forceinline__ int warp_sum_i(int v) {
#pragma unroll
    for (int o = 16; o > 0; o >>= 1) v += __shfl_xor_sync(0xffffffffu, v, o);
    return v;
}
__device__ float block_sum(float v, float* sm) {
    int w = threadIdx.x >> 5, lane = threadIdx.x & 31, nw = blockDim.x >> 5;
    v = warp_sum(v);
    if (lane == 0) sm[w] = v;
    __syncthreads();
    float r = (threadIdx.x < nw) ? sm[threadIdx.x] : 0.f;
    if (w == 0) r = warp_sum(r);
    if (threadIdx.x == 0) sm[0] = r;
    __syncthreads();
    r = sm[0];
    __syncthreads();
    return r;
}
__device__ float block_max(float v, float* sm) {
    int w = threadIdx.x >> 5, lane = threadIdx.x & 31, nw = blockDim.x >> 5;
    v = warp_max(v);
    if (lane == 0) sm[w] = v;
    __syncthreads();
    float r = (threadIdx.x < nw) ? sm[threadIdx.x] : -FLT_MAX;
    if (w == 0) r = warp_max(r);
    if (threadIdx.x == 0) sm[0] = r;
    __syncthreads();
    r = sm[0];
    __syncthreads();
    return r;
}

__device__ __forceinline__ uint32_t f2tf32(float x) {
    uint32_t r;
    asm("cvt.rna.tf32.f32 %0, %1;" : "=r"(r) : "f"(x));
    return r;
}
__device__ __forceinline__ void mma_tf32(float* c, const uint32_t* a, const uint32_t* b) {
    asm volatile(
        "mma.sync.aligned.m16n8k8.row.col.f32.tf32.tf32.f32 "
        "{%0,%1,%2,%3}, {%4,%5,%6,%7}, {%8,%9}, {%0,%1,%2,%3};"
        : "+f"(c[0]), "+f"(c[1]), "+f"(c[2]), "+f"(c[3])
        : "r"(a[0]), "r"(a[1]), "r"(a[2]), "r"(a[3]), "r"(b[0]), "r"(b[1]));
}

// ---------------- kernels ----------------

__global__ void count_nz_kernel(const float4* __restrict__ a, const float4* __restrict__ b) {
    const int n4 = N_ * E_ / 4;
    int ca = 0, cb = 0;
    for (int i = blockIdx.x * blockDim.x + threadIdx.x; i < n4; i += gridDim.x * blockDim.x) {
        float4 x = a[i];
        ca += (x.x != 0.f) + (x.y != 0.f) + (x.z != 0.f) + (x.w != 0.f);
        float4 y = b[i];
        cb += (y.x != 0.f) + (y.y != 0.f) + (y.z != 0.f) + (y.w != 0.f);
    }
    __shared__ int sa[32], sb[32];
    int w = threadIdx.x >> 5, lane = threadIdx.x & 31;
    ca = warp_sum_i(ca); cb = warp_sum_i(cb);
    if (lane == 0) { sa[w] = ca; sb[w] = cb; }
    __syncthreads();
    if (w == 0) {
        int x = (lane < 8) ? sa[lane] : 0;
        int y = (lane < 8) ? sb[lane] : 0;
        x = warp_sum_i(x); y = warp_sum_i(y);
        if (lane == 0) { g_nza[blockIdx.x] = x; g_nzb[blockIdx.x] = y; }
    }
}

__global__ void topo_kernel(const float* __restrict__ Ho, const float* __restrict__ Hp) {
    __shared__ float hoi[128], hpi[128];
    __shared__ float sm[32];
    int i = blockIdx.x;
    int tid = threadIdx.x;
    if (tid < SAMP_) { hoi[tid] = Ho[i * E_ + tid]; hpi[tid] = Hp[i * E_ + tid]; }
    else             { hoi[tid] = 0.f; hpi[tid] = 0.f; }
    __syncthreads();
    int w = tid >> 5, lane = tid & 31;
    float dn2 = 0.f, on2 = 0.f;
    for (int j = w; j < SAMP_; j += 4) {
        float as = 0.f, aps = 0.f;
#pragma unroll
        for (int t = 0; t < 4; t++) {
            int k = lane + 32 * t;
            if (k < SAMP_) {
                as  += hoi[k] * Ho[j * E_ + k];
                aps += hpi[k] * Hp[j * E_ + k];
            }
        }
        as = warp_sum(as);
        aps = warp_sum(aps);
        if (lane == 0) {
            float d = as - aps;
            dn2 += d * d;
            on2 += as * as;
        }
    }
    float D2 = block_sum(dn2, sm);
    float O2 = block_sum(on2, sm);
    if (tid == 0) { g_topo[i * 2] = D2; g_topo[i * 2 + 1] = O2; }
}

// TF32 tensor-core MLP GEMM, 3-term split for fp32 accuracy.
// C[M,256] = act(A @ B + bias). BM=128, BN=64, 256 threads (8 warps: 4 M x 2 N).
// Warp tile 32x32: 2 m-frags (m16) x 4 n-frags (n8), k-step 8.
template <bool RELU, bool NORM>
__global__ void gemm_tf32_kernel(const float* __restrict__ A, const float* __restrict__ B,
                                 const float* __restrict__ bias, float* __restrict__ C) {
    __shared__ float As[16][136];  // [k][row], stride 136 -> conflict-free frag loads
    __shared__ float Bs[16][72];   // [k][col],  stride 72
    __shared__ float ssq[128][9];
    const int bm = blockIdx.x * 128, bn = blockIdx.y * 64;
    const int tid = threadIdx.x;
    const int lane = tid & 31, wid = tid >> 5;
    const int wm = wid >> 1, wn = wid & 1;
    const int g = lane >> 2, t = lane & 3;
    float acc[2][4][4];
#pragma unroll
    for (int m = 0; m < 2; m++)
#pragma unroll
        for (int n = 0; n < 4; n++)
#pragma unroll
            for (int q = 0; q < 4; q++) acc[m][n][q] = 0.f;

    for (int k0 = 0; k0 < D_; k0 += 16) {
#pragma unroll
        for (int l = 0; l < 2; l++) {
            int id = tid * 2 + l;
            int r = id >> 2, c4 = id & 3;
            float4 v = *(const float4*)&A[(bm + r) * D_ + k0 + c4 * 4];
            As[c4 * 4 + 0][r] = v.x;
            As[c4 * 4 + 1][r] = v.y;
            As[c4 * 4 + 2][r] = v.z;
            As[c4 * 4 + 3][r] = v.w;
        }
        {
            int r = tid >> 4, c4 = tid & 15;
            float4 v = *(const float4*)&B[(k0 + r) * D_ + bn + c4 * 4];
            *(float4*)&Bs[r][c4 * 4] = v;
        }
        __syncthreads();
#pragma unroll
        for (int ks = 0; ks < 16; ks += 8) {
            uint32_t ah[2][4], al[2][4], bh[4][2], bl[4][2];
#pragma unroll
            for (int m = 0; m < 2; m++) {
                int rb = wm * 32 + m * 16;
                float x0 = As[ks + t][rb + g];
                float x1 = As[ks + t][rb + g + 8];
                float x2 = As[ks + t + 4][rb + g];
                float x3 = As[ks + t + 4][rb + g + 8];
                ah[m][0] = f2tf32(x0); al[m][0] = f2tf32(x0 - __uint_as_float(ah[m][0]));
                ah[m][1] = f2tf32(x1); al[m][1] = f2tf32(x1 - __uint_as_float(ah[m][1]));
                ah[m][2] = f2tf32(x2); al[m][2] = f2tf32(x2 - __uint_as_float(ah[m][2]));
                ah[m][3] = f2tf32(x3); al[m][3] = f2tf32(x3 - __uint_as_float(ah[m][3]));
            }
#pragma unroll
            for (int n = 0; n < 4; n++) {
                int cb = wn * 32 + n * 8;
                float y0 = Bs[ks + t][cb + g];
                float y1 = Bs[ks + t + 4][cb + g];
                bh[n][0] = f2tf32(y0); bl[n][0] = f2tf32(y0 - __uint_as_float(bh[n][0]));
                bh[n][1] = f2tf32(y1); bl[n][1] = f2tf32(y1 - __uint_as_float(bh[n][1]));
            }
#pragma unroll
            for (int m = 0; m < 2; m++)
#pragma unroll
                for (int n = 0; n < 4; n++) {
                    mma_tf32(acc[m][n], ah[m], bh[n]);
                    mma_tf32(acc[m][n], ah[m], bl[n]);
                    mma_tf32(acc[m][n], al[m], bh[n]);
                }
        }
        __syncthreads();
    }
    // epilogue
    float sq[2][2] = {};
#pragma unroll
    for (int m = 0; m < 2; m++) {
        int row0 = bm + wm * 32 + m * 16 + g;
        int row1 = row0 + 8;
#pragma unroll
        for (int n = 0; n < 4; n++) {
            int col = bn + wn * 32 + n * 8 + t * 2;
            float b0 = bias[col], b1 = bias[col + 1];
            float v00 = acc[m][n][0] + b0, v01 = acc[m][n][1] + b1;
            float v10 = acc[m][n][2] + b0, v11 = acc[m][n][3] + b1;
            if (RELU) {
                v00 = fmaxf(v00, 0.f); v01 = fmaxf(v01, 0.f);
                v10 = fmaxf(v10, 0.f); v11 = fmaxf(v11, 0.f);
            }
            *(float2*)&C[row0 * D_ + col] = make_float2(v00, v01);
            *(float2*)&C[row1 * D_ + col] = make_float2(v10, v11);
            if (NORM) {
                sq[m][0] += v00 * v00 + v01 * v01;
                sq[m][1] += v10 * v10 + v11 * v11;
            }
        }
    }
    if (NORM) {
#pragma unroll
        for (int m = 0; m < 2; m++) {
            ssq[wm * 32 + m * 16 + g][wn * 4 + t] = sq[m][0];
            ssq[wm * 32 + m * 16 + g + 8][wn * 4 + t] = sq[m][1];
        }
        __syncthreads();
        if (tid < 128) {
            float s = 0.f;
#pragma unroll
            for (int q = 0; q < 8; q++) s += ssq[tid][q];
            g_znpart[blockIdx.y][bm + tid] = s;
        }
    }
}

__global__ void znorm_fin_kernel() {
    int r = blockIdx.x * 256 + threadIdx.x;
    float s = g_znpart[0][r] + g_znpart[1][r] + g_znpart[2][r] + g_znpart[3][r];
    g_znorm[r] = fmaxf(sqrtf(s), 1e-8f);
}

// att/sim/lse GEMM: BM=64 rows x BN=128 j, 128 threads, 8x8 microtile.
__global__ void attgemm_kernel() {
    __shared__ float As[16][68];
    __shared__ float Bs[16][132];
    __shared__ float redm[64][17], reds[64][17];
    __shared__ float s_invi[64], s_invj[128];
    const int bm = blockIdx.x * 64;
    const int sp = blockIdx.y;
    const int j0 = sp * 128;
    const int tid = threadIdx.x;
    const int tx = tid & 15, ty = tid >> 4;
    if (tid < 64) s_invi[tid] = 1.f / g_znorm[bm + tid];
    s_invj[tid] = 1.f / g_znorm[j0 + tid];
    float acc[8][8];
#pragma unroll
    for (int r = 0; r < 8; r++)
#pragma unroll
        for (int c = 0; c < 8; c++) acc[r][c] = 0.f;

    for (int k0 = 0; k0 < D_; k0 += 16) {
#pragma unroll
        for (int l = 0; l < 2; l++) {
            int id = tid * 2 + l;       // 0..255
            int r = id >> 2, c4 = id & 3;
            float4 v = *(const float4*)&g_z[(bm + r) * D_ + k0 + c4 * 4];
            As[c4 * 4 + 0][r] = v.x;
            As[c4 * 4 + 1][r] = v.y;
            As[c4 * 4 + 2][r] = v.z;
            As[c4 * 4 + 3][r] = v.w;
        }
#pragma unroll
        for (int l = 0; l < 4; l++) {
            int id = tid + 128 * l;     // 0..511
            int jr = id >> 2, c4 = id & 3;
            float4 v = *(const float4*)&g_z[(j0 + jr) * D_ + k0 + c4 * 4];
            Bs[c4 * 4 + 0][jr] = v.x;
            Bs[c4 * 4 + 1][jr] = v.y;
            Bs[c4 * 4 + 2][jr] = v.z;
            Bs[c4 * 4 + 3][jr] = v.w;
        }
        __syncthreads();
#pragma unroll
        for (int kk = 0; kk < 16; kk++) {
            float4 a0 = *(const float4*)&As[kk][ty * 8];
            float4 a1 = *(const float4*)&As[kk][ty * 8 + 4];
            float4 b0 = *(const float4*)&Bs[kk][tx * 8];
            float4 b1 = *(const float4*)&Bs[kk][tx * 8 + 4];
            float a[8] = {a0.x, a0.y, a0.z, a0.w, a1.x, a1.y, a1.z, a1.w};
            float b[8] = {b0.x, b0.y, b0.z, b0.w, b1.x, b1.y, b1.z, b1.w};
#pragma unroll
            for (int r = 0; r < 8; r++)
#pragma unroll
                for (int c = 0; c < 8; c++) acc[r][c] += a[r] * b[c];
        }
        __syncthreads();
    }
    // sim / attdot stores
    if (j0 < MHN_) {
#pragma unroll
        for (int r = 0; r < 8; r++) {
            int i = bm + ty * 8 + r;
            if (i >= MHN_) continue;
            float invi = s_invi[ty * 8 + r];
#pragma unroll
            for (int c = 0; c < 8; c++) {
                int j = j0 + tx * 8 + c;
                if (j < MHN_) {
                    g_attdot[i * MHN_ + j] = acc[r][c];
                    g_sim[i * MHN_ + j] = acc[r][c] * invi * s_invj[tx * 8 + c];
                }
            }
        }
    }
    // att softmax partials
#pragma unroll
    for (int r = 0; r < 8; r++) {
        float m = -FLT_MAX;
#pragma unroll
        for (int c = 0; c < 8; c++) m = fmaxf(m, acc[r][c]);
        float s = 0.f;
#pragma unroll
        for (int c = 0; c < 8; c++) s += __expf(acc[r][c] - m);
        redm[ty * 8 + r][tx] = m;
        reds[ty * 8 + r][tx] = s;
    }
    __syncthreads();
    if (tid < 64) {
        int i = bm + tid;
        if (i < MHN_) {
            float M = -FLT_MAX;
#pragma unroll
            for (int q = 0; q < 16; q++) M = fmaxf(M, redm[tid][q]);
            float S = 0.f;
#pragma unroll
            for (int q = 0; q < 16; q++) S += reds[tid][q] * __expf(redm[tid][q] - M);
            g_attm[i * NSPL_ + sp] = M;
            g_atts[i * NSPL_ + sp] = S;
        }
    }
    // lse partials (rows < 100)
    if (bm < MFN_) {
        __syncthreads();
#pragma unroll
        for (int r = 0; r < 8; r++) {
            float vi = s_invi[ty * 8 + r] * (1.f / TAU_F);
            float m = -FLT_MAX;
            float vv[8];
#pragma unroll
            for (int c = 0; c < 8; c++) {
                vv[c] = acc[r][c] * vi * s_invj[tx * 8 + c];
                m = fmaxf(m, vv[c]);
            }
            float s = 0.f;
#pragma unroll
            for (int c = 0; c < 8; c++) s += __expf(vv[c] - m);
            redm[ty * 8 + r][tx] = m;
            reds[ty * 8 + r][tx] = s;
        }
        __syncthreads();
        if (tid < 64) {
            int i = bm + tid;
            if (i < MFN_) {
                float M = -FLT_MAX;
#pragma unroll
                for (int q = 0; q < 16; q++) M = fmaxf(M, redm[tid][q]);
                float S = 0.f;
#pragma unroll
                for (int q = 0; q < 16; q++) S += reds[tid][q] * __expf(redm[tid][q] - M);
                g_lsem[i * NSPL_ + sp] = M;
                g_lses[i * NSPL_ + sp] = S;
            }
        }
    }
}

// Sparse edge aggregation: grid (125 edge-groups, 8 i-splits), warp-local rows.
__global__ void edge_part_kernel(const float* __restrict__ Hp, const float* __restrict__ z) {
    __shared__ float racc[8][4][256];
    __shared__ int rcnt[8][4];
    const int tid = threadIdx.x;
    const int lane = tid & 31, w = tid >> 5;
    const int e0 = blockIdx.x * 4, sp = blockIdx.y;
    float acc[4][8] = {};
    int cnt[4] = {0, 0, 0, 0};
    const int ibase = sp * 1024;
#pragma unroll 1
    for (int ic = 0; ic < 1024; ic += 256) {
        int i0 = ibase + ic;
        float4 v = *(const float4*)&Hp[(size_t)(i0 + tid) * E_ + e0];
        int m = (v.x > 0.f) | ((v.y > 0.f) << 1) | ((v.z > 0.f) << 2) | ((v.w > 0.f) << 3);
        unsigned b = __ballot_sync(0xffffffffu, m != 0);
        int rowbase = i0 + w * 32;
        while (b) {
            int src = __ffs(b) - 1;
            b &= b - 1;
            int mm = __shfl_sync(0xffffffffu, m, src);
            const float* zr = &z[(size_t)(rowbase + src) * D_];
            float zv[8];
#pragma unroll
            for (int t = 0; t < 8; t++) zv[t] = zr[lane + 32 * t];
            switch (mm) {
                case 1:
#pragma unroll
                    for (int t = 0; t < 8; t++) acc[0][t] += zv[t];
                    cnt[0]++; break;
                case 2:
#pragma unroll
                    for (int t = 0; t < 8; t++) acc[1][t] += zv[t];
                    cnt[1]++; break;
                case 4:
#pragma unroll
                    for (int t = 0; t < 8; t++) acc[2][t] += zv[t];
                    cnt[2]++; break;
                case 8:
#pragma unroll
                    for (int t = 0; t < 8; t++) acc[3][t] += zv[t];
                    cnt[3]++; break;
                default:
                    if (mm & 1) {
#pragma unroll
                        for (int t = 0; t < 8; t++) acc[0][t] += zv[t];
                        cnt[0]++;
                    }
                    if (mm & 2) {
#pragma unroll
                        for (int t = 0; t < 8; t++) acc[1][t] += zv[t];
                        cnt[1]++;
                    }
                    if (mm & 4) {
#pragma unroll
                        for (int t = 0; t < 8; t++) acc[2][t] += zv[t];
                        cnt[2]++;
                    }
                    if (mm & 8) {
#pragma unroll
                        for (int t = 0; t < 8; t++) acc[3][t] += zv[t];
                        cnt[3]++;
                    }
            }
        }
    }
#pragma unroll
    for (int e = 0; e < 4; e++)
#pragma unroll
        for (int t = 0; t < 8; t++) racc[w][e][lane + 32 * t] = acc[e][t];
    if (lane == 0) {
#pragma unroll
        for (int e = 0; e < 4; e++) rcnt[w][e] = cnt[e];
    }
    __syncthreads();
#pragma unroll
    for (int e = 0; e < 4; e++) {
        float s = 0.f;
#pragma unroll
        for (int q = 0; q < 8; q++) s += racc[q][e][tid];
        g_edge_part[sp][(e0 + e) * D_ + tid] = s;
    }
    if (tid < 4) {
        int c = 0;
#pragma unroll
        for (int q = 0; q < 8; q++) c += rcnt[q][tid];
        g_cntp[sp][e0 + tid] = c;
    }
}

// edge MLP layer 1 (mean fused)
__global__ void gemm64_e1_kernel(const float* __restrict__ B, const float* __restrict__ bias,
                                 float* __restrict__ C) {
    __shared__ float As[16][68];
    __shared__ float Bs[16][68];
    const int bm = blockIdx.x * 64, bn = blockIdx.y * 64;
    const int tid = threadIdx.x;
    const int tx = tid & 15, ty = tid >> 4;
    const int arow = bm + (tid >> 2);
    float cinv = 0.f;
    {
        int c = 0;
#pragma unroll
        for (int p = 0; p < 8; p++) c += g_cntp[p][arow];
        cinv = (c > 0 && arow < ECAP_) ? 1.f / (float)c : 0.f;
    }
    float acc[4][4] = {};
    for (int k0 = 0; k0 < D_; k0 += 16) {
        {
            int r = tid >> 2, c4 = tid & 3;
            float4 s = make_float4(0.f, 0.f, 0.f, 0.f);
#pragma unroll
            for (int p = 0; p < 8; p++) {
                float4 t = *(const float4*)&g_edge_part[p][arow * D_ + k0 + c4 * 4];
                s.x += t.x; s.y += t.y; s.z += t.z; s.w += t.w;
            }
            As[c4 * 4 + 0][r] = s.x * cinv;
            As[c4 * 4 + 1][r] = s.y * cinv;
            As[c4 * 4 + 2][r] = s.z * cinv;
            As[c4 * 4 + 3][r] = s.w * cinv;
        }
        {
            int r = tid >> 4, c4 = tid & 15;
            float4 v = *(const float4*)&B[(k0 + r) * D_ + bn + c4 * 4];
            *(float4*)&Bs[r][c4 * 4] = v;
        }
        __syncthreads();
#pragma unroll
        for (int kk = 0; kk < 16; kk++) {
            float a[4], b[4];
#pragma unroll
            for (int u = 0; u < 4; u++) a[u] = As[kk][ty * 4 + u];
#pragma unroll
            for (int u = 0; u < 4; u++) b[u] = Bs[kk][tx * 4 + u];
#pragma unroll
            for (int i = 0; i < 4; i++)
#pragma unroll
                for (int j = 0; j < 4; j++) acc[i][j] += a[i] * b[j];
        }
        __syncthreads();
    }
#pragma unroll
    for (int i = 0; i < 4; i++) {
        int row = bm + ty * 4 + i;
#pragma unroll
        for (int j = 0; j < 4; j++) {
            int col = bn + tx * 4 + j;
            C[row * D_ + col] = fmaxf(acc[i][j] + bias[col], 0.f);
        }
    }
}

// edge MLP layer 2 (hnorm partials fused)
__global__ void gemm64_e2_kernel(const float* __restrict__ A, const float* __restrict__ B,
                                 const float* __restrict__ bias, float* __restrict__ C) {
    __shared__ float As[16][68];
    __shared__ float Bs[16][68];
    __shared__ float ssq[64][17];
    const int bm = blockIdx.x * 64, bn = blockIdx.y * 64;
    const int tid = threadIdx.x;
    const int tx = tid & 15, ty = tid >> 4;
    float acc[4][4] = {};
    for (int k0 = 0; k0 < D_; k0 += 16) {
        {
            int r = tid >> 2, c4 = tid & 3;
            float4 v = *(const float4*)&A[(bm + r) * D_ + k0 + c4 * 4];
            As[c4 * 4 + 0][r] = v.x;
            As[c4 * 4 + 1][r] = v.y;
            As[c4 * 4 + 2][r] = v.z;
            As[c4 * 4 + 3][r] = v.w;
        }
        {
            int r = tid >> 4, c4 = tid & 15;
            float4 v = *(const float4*)&B[(k0 + r) * D_ + bn + c4 * 4];
            *(float4*)&Bs[r][c4 * 4] = v;
        }
        __syncthreads();
#pragma unroll
        for (int kk = 0; kk < 16; kk++) {
            float a[4], b[4];
#pragma unroll
            for (int u = 0; u < 4; u++) a[u] = As[kk][ty * 4 + u];
#pragma unroll
            for (int u = 0; u < 4; u++) b[u] = Bs[kk][tx * 4 + u];
#pragma unroll
            for (int i = 0; i < 4; i++)
#pragma unroll
                for (int j = 0; j < 4; j++) acc[i][j] += a[i] * b[j];
        }
        __syncthreads();
    }
#pragma unroll
    for (int i = 0; i < 4; i++) {
        int row = bm + ty * 4 + i;
        float sq = 0.f;
#pragma unroll
        for (int j = 0; j < 4; j++) {
            int col = bn + tx * 4 + j;
            float v = acc[i][j] + bias[col];
            C[row * D_ + col] = v;
            sq += v * v;
        }
        ssq[ty * 4 + i][tx] = sq;
    }
    __syncthreads();
    if (tid < 64) {
        float s = 0.f;
#pragma unroll
        for (int q = 0; q < 16; q++) s += ssq[tid][q];
        g_hnpart[blockIdx.y][bm + tid] = s;
    }
}

// merged finalize: att rows (0..199), lse (200), hnorm (201)
__global__ void merge_kernel() {
    int b = blockIdx.x;
    if (b < MHN_) {
        int i = b;
        __shared__ float Ms, Ss;
        if (threadIdx.x == 0) {
            float M = -FLT_MAX;
            for (int p = 0; p < NSPL_; p++) M = fmaxf(M, g_attm[i * NSPL_ + p]);
            float S = 0.f;
            for (int p = 0; p < NSPL_; p++) S += g_atts[i * NSPL_ + p] * __expf(g_attm[i * NSPL_ + p] - M);
            Ms = M; Ss = S;
        }
        __syncthreads();
        for (int j = threadIdx.x; j < MHN_; j += blockDim.x)
            g_att[i * MHN_ + j] = __expf(g_attdot[i * MHN_ + j] - Ms) / Ss;
    } else if (b == MHN_) {
        int i = threadIdx.x;
        if (i < MFN_) {
            float M = -FLT_MAX;
            for (int p = 0; p < NSPL_; p++) M = fmaxf(M, g_lsem[i * NSPL_ + p]);
            float S = 0.f;
            for (int p = 0; p < NSPL_; p++) S += g_lses[i * NSPL_ + p] * __expf(g_lsem[i * NSPL_ + p] - M);
            g_lse[i] = M + logf(S);
        }
    } else {
        for (int j = threadIdx.x; j < ECAP_; j += blockDim.x) {
            float s = g_hnpart[0][j] + g_hnpart[1][j] + g_hnpart[2][j] + g_hnpart[3][j];
            g_hnorm[j] = fmaxf(sqrtf(s), 1e-8f);
        }
    }
}

// fused losses: blocks [0,500) = cl rows; [500,700) = hn rows (+ fn for i<100)
__global__ void losses_kernel(const float* __restrict__ Ho, const float* __restrict__ Hp) {
    __shared__ float sm[32];
    int b = blockIdx.x;
    int tid = threadIdx.x;
    if (b < ECAP_) {
        __shared__ float zi[256];
        __shared__ float logit[500];
        int i = b;
        zi[tid] = g_z[i * D_ + tid] / g_znorm[i];
        __syncthreads();
        int w = tid >> 5, lane = tid & 31;
        for (int j = w; j < ECAP_; j += 8) {
            float s = 0.f;
#pragma unroll
            for (int t = 0; t < 8; t++) { int k = lane + 32 * t; s += zi[k] * g_hedges[j * D_ + k]; }
            s = warp_sum(s);
            if (lane == 0) logit[j] = s / (g_hnorm[j] * TAU_F);
        }
        __syncthreads();
        float lm = -FLT_MAX;
        for (int j = tid; j < ECAP_; j += 256) lm = fmaxf(lm, logit[j]);
        float M = block_max(lm, sm);
        float ls = 0.f;
        for (int j = tid; j < ECAP_; j += 256) ls += __expf(logit[j] - M);
        float S = block_sum(ls, sm);
        if (tid == 0) g_clrow[i] = logit[i] - (M + logf(S));
    } else {
        int i = b - ECAP_;
        {
            int j = tid;
            bool act = j < MHN_;
            float simv = act ? g_sim[i * MHN_ + j] : 0.f;
            float attv = act ? g_att[i * MHN_ + j] : 1.f;
            bool mask = act && (j != i) && (simv > MU_F) && (attv < NU_F);
            float neg = -simv / TAU_F;
            float m = block_max(mask ? neg : -FLT_MAX, sm);
            if (m == -FLT_MAX) {
                if (tid == 0) { g_hnsum[i] = 0.f; g_hncnt[i] = 0.f; }
            } else {
                float s = block_sum(mask ? expf(neg - m) : 0.f, sm);
                float lse = m + logf(s);
                float wgt = fminf(simv / MU_F, 1.f);
                float pair = -wgt * (neg - lse);
                float ps = block_sum(mask ? pair : 0.f, sm);
                float pc = block_sum(mask ? 1.f : 0.f, sm);
                if (tid == 0) { g_hnsum[i] = ps; g_hncnt[i] = pc; }
            }
        }
        if (i < MFN_) {
            __shared__ unsigned char cand[128];
            __shared__ short clist[MFN_];
            __shared__ int ncand;
            if (tid < 128) cand[tid] = 0;
            __syncthreads();
            if (tid < MFN_) {
                bool g = (tid > i) && (g_sim[i * MHN_ + tid] > GAMMA_F)
                                   && (g_att[i * MHN_ + tid] > DELTA_F);
                cand[tid] = g ? 1 : 0;
            }
            __syncthreads();
            if (tid == 0) {
                int n = 0;
                for (int j = i + 1; j < MFN_; j++) if (cand[j]) clist[n++] = (short)j;
                ncand = n;
            }
            __syncthreads();
            int nc = ncand;
            float fsum = 0.f, fcnt = 0.f;
            for (int k = 0; k < nc; k++) {
                int j = clist[k];
                float ao = 0.f, ap = 0.f;
                for (int t = tid; t < E_; t += 256) {
                    ao += Ho[i * E_ + t] * Ho[j * E_ + t];
                    ap += Hp[i * E_ + t] * Hp[j * E_ + t];
                }
                ao = block_sum(ao, sm);
                ap = block_sum(ap, sm);
                if (ap == 0.f && ao > 0.f) {
                    fsum += -(g_sim[i * MHN_ + j] / TAU_F - g_lse[i]);
                    fcnt += 1.f;
                }
            }
            if (tid == 0) { g_fnrow[i] = fsum; g_fncnt[i] = fcnt; }
        }
    }
}

// final combine
__global__ void final_kernel(const float* __restrict__ bw, float* __restrict__ out) {
    __shared__ float sm[32];
    int tid = threadIdx.x;
    float v = 0.f;
    for (int i = tid; i < ECAP_; i += 512) v += g_clrow[i];
    float clsum = block_sum(v, sm);
    v = 0.f; float c = 0.f;
    for (int i = tid; i < MFN_; i += 512) { v += g_fnrow[i]; c += g_fncnt[i]; }
    float fnsum = block_sum(v, sm);
    float fncnt = block_sum(c, sm);
    v = 0.f; c = 0.f;
    for (int i = tid; i < MHN_; i += 512) { v += g_hnsum[i]; c += g_hncnt[i]; }
    float hnsum = block_sum(v, sm);
    float hncnt = block_sum(c, sm);
    float d2 = 0.f, o2 = 0.f;
    for (int i = tid; i < SAMP_; i += 512) { d2 += g_topo[i * 2]; o2 += g_topo[i * 2 + 1]; }
    float D2 = block_sum(d2, sm);
    float O2 = block_sum(o2, sm);
    float za = 0.f, zb = 0.f;
    for (int i = tid; i < 2048; i += 512) { za += (float)g_nza[i]; zb += (float)g_nzb[i]; }
    float NZ = block_sum(za, sm);
    float NZP = block_sum(zb, sm);
    if (tid == 0) {
        float cl_loss = -clsum / (float)ECAP_;
        float fn_loss = (fncnt > 0.f) ? fnsum / fmaxf(fncnt, 1.f) : 0.f;
        float hard_loss = (hncnt > 0.f) ? hnsum / fmaxf(hncnt, 1.f) : 0.f;
        float sparsity = (NZ > 0.f) ? NZP / fmaxf(NZ, 1.f) : 1.f;
        float dn = sqrtf(D2), on = sqrtf(O2);
        float topo = (on > 0.f) ? expf(-ALPHA_F * dn / fmaxf(on, 1e-12f)) : 1.f;
        float retention = sparsity * topo;
        out[0] = bw[0] * (retention * cl_loss + fn_loss + hard_loss);
    }
}

// ---------------- launch ----------------
extern "C" void kernel_launch(void* const* d_in, const int* in_sizes, int n_in,
                              void* d_out, int out_size) {
    (void)in_sizes; (void)n_in; (void)out_size;
    const float* Ho  = (const float*)d_in[0];
    const float* Hp  = (const float*)d_in[1];
    const float* ne  = (const float*)d_in[2];
    const float* bw  = (const float*)d_in[3];
    const float* Wn1 = (const float*)d_in[4];
    const float* bn1 = (const float*)d_in[5];
    const float* Wn2 = (const float*)d_in[6];
    const float* bn2 = (const float*)d_in[7];
    const float* We1 = (const float*)d_in[8];
    const float* be1 = (const float*)d_in[9];
    const float* We2 = (const float*)d_in[10];
    const float* be2 = (const float*)d_in[11];
    float* out = (float*)d_out;

    void *p;
    float *p_tmp, *p_z, *p_etmp, *p_hedges;
    cudaGetSymbolAddress(&p, g_tmp);    p_tmp    = (float*)p;
    cudaGetSymbolAddress(&p, g_z);      p_z      = (float*)p;
    cudaGetSymbolAddress(&p, g_etmp);   p_etmp   = (float*)p;
    cudaGetSymbolAddress(&p, g_hedges); p_hedges = (float*)p;

    // idx 0-1: independent scans
    count_nz_kernel<<<2048, 256>>>((const float4*)Ho, (const float4*)Hp);
    topo_kernel<<<SAMP_, 128>>>(Ho, Hp);

    // idx 2-3: node MLP via TF32 tensor cores (idx 3 PROFILED)
    gemm_tf32_kernel<true,  false><<<dim3(64, 4), 256>>>(ne,    Wn1, bn1, p_tmp);
    gemm_tf32_kernel<false, true ><<<dim3(64, 4), 256>>>(p_tmp, Wn2, bn2, p_z);

    // idx 4: znorm finalize
    znorm_fin_kernel<<<32, 256>>>();

    // idx 5: att/sim/lse GEMM (8x8 microtile)
    attgemm_kernel<<<dim3(4, NSPL_), 128>>>();

    // idx 6: edge aggregation partials
    edge_part_kernel<<<dim3(ECAP_ / 4, 8), 256>>>(Hp, p_z);

    // idx 7-8: edge MLP
    gemm64_e1_kernel<<<dim3(8, 4), 256>>>(We1, be1, p_etmp);
    gemm64_e2_kernel<<<dim3(8, 4), 256>>>(p_etmp, We2, be2, p_hedges);

    // idx 9: merge finalizers
    merge_kernel<<<MHN_ + 2, 256>>>();

    // idx 10: fused losses
    losses_kernel<<<ECAP_ + MHN_, 256>>>(Ho, Hp);

    // idx 11: final combine
    final_kernel<<<1, 512>>>(bw, out);
}

// round 9
// speedup vs baseline: 5.8192x; 1.0153x over previous
#include <cuda_runtime.h>
#include <math.h>
#include <cfloat>
#include <stdint.h>

// ---------------- constants ----------------
#define TAU_F   0.4f
#define ALPHA_F 1.0f
#define GAMMA_F 0.7f
#define DELTA_F 0.6f
#define MU_F    0.6f
#define NU_F    0.3f

#define N_  8192
#define E_  2048
#define D_  256
#define SAMP_ 100
#define MFN_  100
#define MHN_  200
#define ECAP_ 500
#define NSPL_ 64

// ---------------- scratch (device globals) ----------------
__device__ float g_tmp[N_ * D_];
__device__ float g_z[N_ * D_];
__device__ float g_znpart[4][N_];
__device__ float g_znorm[N_];
__device__ uint32_t g_w1h[D_ * D_], g_w1l[D_ * D_];
__device__ uint32_t g_w2h[D_ * D_], g_w2l[D_ * D_];
__device__ float g_edge_part[8][512 * D_];
__device__ int   g_cntp[8][512];
__device__ float g_etmp[512 * D_];
__device__ float g_hedges[512 * D_];
__device__ float g_hnpart[4][512];
__device__ float g_hnorm[512];
__device__ float g_logits[512 * 512];
__device__ float g_sim[MHN_ * MHN_];
__device__ float g_attdot[MHN_ * MHN_];
__device__ float g_attm[MHN_ * NSPL_], g_atts[MHN_ * NSPL_];
__device__ float g_att[MHN_ * MHN_];
__device__ float g_lsem[MFN_ * NSPL_], g_lses[MFN_ * NSPL_];
__device__ float g_lse[MFN_];
__device__ float g_clrow[ECAP_];
__device__ float g_fnrow[MFN_], g_fncnt[MFN_];
__device__ float g_hnsum[MHN_], g_hncnt[MHN_];
__device__ int   g_nza[2048], g_nzb[2048];
__device__ float g_topo[SAMP_ * 2];

// ---------------- helpers ----------------
__device__ __forceinline__ float warp_sum(float v) {
#pragma unroll
    for (int o = 16; o > 0; o >>= 1) v += __shfl_xor_sync(0xffffffffu, v, o);
    return v;
}
__device__ __forceinline__ float warp_max(float v) {
#pragma unroll
    for (int o = 16; o > 0; o >>= 1) v = fmaxf(v, __shfl_xor_sync(0xffffffffu, v, o));
    return v;
}
__device__ __forceinline__ int warp_sum_i(int v) {
#pragma unroll
    for (int o = 16; o > 0; o >>= 1) v += __shfl_xor_sync(0xffffffffu, v, o);
    return v;
}
__device__ float block_sum(float v, float* sm) {
    int w = threadIdx.x >> 5, lane = threadIdx.x & 31, nw = blockDim.x >> 5;
    v = warp_sum(v);
    if (lane == 0) sm[w] = v;
    __syncthreads();
    float r = (threadIdx.x < nw) ? sm[threadIdx.x] : 0.f;
    if (w == 0) r = warp_sum(r);
    if (threadIdx.x == 0) sm[0] = r;
    __syncthreads();
    r = sm[0];
    __syncthreads();
    return r;
}
__device__ float block_max(float v, float* sm) {
    int w = threadIdx.x >> 5, lane = threadIdx.x & 31, nw = blockDim.x >> 5;
    v = warp_max(v);
    if (lane == 0) sm[w] = v;
    __syncthreads();
    float r = (threadIdx.x < nw) ? sm[threadIdx.x] : -FLT_MAX;
    if (w == 0) r = warp_max(r);
    if (threadIdx.x == 0) sm[0] = r;
    __syncthreads();
    r = sm[0];
    __syncthreads();
    return r;
}
__device__ __forceinline__ uint32_t f2tf32(float x) {
    uint32_t r;
    asm("cvt.rna.tf32.f32 %0, %1;" : "=r"(r) : "f"(x));
    return r;
}
__device__ __forceinline__ void mma_tf32(float* c, const uint32_t* a, const uint32_t* b) {
    asm volatile(
        "mma.sync.aligned.m16n8k8.row.col.f32.tf32.tf32.f32 "
        "{%0,%1,%2,%3}, {%4,%5,%6,%7}, {%8,%9}, {%0,%1,%2,%3};"
        : "+f"(c[0]), "+f"(c[1]), "+f"(c[2]), "+f"(c[3])
        : "r"(a[0]), "r"(a[1]), "r"(a[2]), "r"(a[3]), "r"(b[0]), "r"(b[1]));
}

// ---------------- kernels ----------------

// pre-split MLP weights into tf32 hi/lo
__global__ void wsplit_kernel(const float* __restrict__ W1, const float* __restrict__ W2) {
    int i = blockIdx.x * 256 + threadIdx.x;   // grid 256 -> 65536
    float x = W1[i];
    uint32_t h = f2tf32(x);
    g_w1h[i] = h;
    g_w1l[i] = f2tf32(x - __uint_as_float(h));
    x = W2[i];
    h = f2tf32(x);
    g_w2h[i] = h;
    g_w2l[i] = f2tf32(x - __uint_as_float(h));
}

__global__ void count_nz_kernel(const float4* __restrict__ a, const float4* __restrict__ b) {
    const int n4 = N_ * E_ / 4;
    int ca = 0, cb = 0;
    for (int i = blockIdx.x * blockDim.x + threadIdx.x; i < n4; i += gridDim.x * blockDim.x) {
        float4 x = a[i];
        ca += (x.x != 0.f) + (x.y != 0.f) + (x.z != 0.f) + (x.w != 0.f);
        float4 y = b[i];
        cb += (y.x != 0.f) + (y.y != 0.f) + (y.z != 0.f) + (y.w != 0.f);
    }
    __shared__ int sa[32], sb[32];
    int w = threadIdx.x >> 5, lane = threadIdx.x & 31;
    ca = warp_sum_i(ca); cb = warp_sum_i(cb);
    if (lane == 0) { sa[w] = ca; sb[w] = cb; }
    __syncthreads();
    if (w == 0) {
        int x = (lane < 8) ? sa[lane] : 0;
        int y = (lane < 8) ? sb[lane] : 0;
        x = warp_sum_i(x); y = warp_sum_i(y);
        if (lane == 0) { g_nza[blockIdx.x] = x; g_nzb[blockIdx.x] = y; }
    }
}

__global__ void topo_kernel(const float* __restrict__ Ho, const float* __restrict__ Hp) {
    __shared__ float hoi[128], hpi[128];
    __shared__ float sm[32];
    int i = blockIdx.x;
    int tid = threadIdx.x;
    if (tid < SAMP_) { hoi[tid] = Ho[i * E_ + tid]; hpi[tid] = Hp[i * E_ + tid]; }
    else             { hoi[tid] = 0.f; hpi[tid] = 0.f; }
    __syncthreads();
    int w = tid >> 5, lane = tid & 31;
    float dn2 = 0.f, on2 = 0.f;
    for (int j = w; j < SAMP_; j += 4) {
        float as = 0.f, aps = 0.f;
#pragma unroll
        for (int t = 0; t < 4; t++) {
            int k = lane + 32 * t;
            if (k < SAMP_) {
                as  += hoi[k] * Ho[j * E_ + k];
                aps += hpi[k] * Hp[j * E_ + k];
            }
        }
        as = warp_sum(as);
        aps = warp_sum(aps);
        if (lane == 0) {
            float d = as - aps;
            dn2 += d * d;
            on2 += as * as;
        }
    }
    float D2 = block_sum(dn2, sm);
    float O2 = block_sum(on2, sm);
    if (tid == 0) { g_topo[i * 2] = D2; g_topo[i * 2 + 1] = O2; }
}

// TF32 tensor-core MLP GEMM with PRE-SPLIT operands (no cvt in mainloop).
// BM=128, BN=64, 256 threads (8 warps: 4M x 2N), warp tile 32x32.
template <bool RELU, bool NORM>
__global__ void gemm_tf32_kernel(const float* __restrict__ A,
                                 const uint32_t* __restrict__ Bh,
                                 const uint32_t* __restrict__ Bl,
                                 const float* __restrict__ bias, float* __restrict__ C) {
    __shared__ uint32_t Ah[16][136], Al[16][136];
    __shared__ uint32_t Bsh[16][72], Bsl[16][72];
    __shared__ float ssq[128][9];
    const int bm = blockIdx.x * 128, bn = blockIdx.y * 64;
    const int tid = threadIdx.x;
    const int lane = tid & 31, wid = tid >> 5;
    const int wm = wid >> 1, wn = wid & 1;
    const int g = lane >> 2, t = lane & 3;
    float acc[2][4][4];
#pragma unroll
    for (int m = 0; m < 2; m++)
#pragma unroll
        for (int n = 0; n < 4; n++)
#pragma unroll
            for (int q = 0; q < 4; q++) acc[m][n][q] = 0.f;

    for (int k0 = 0; k0 < D_; k0 += 16) {
#pragma unroll
        for (int l = 0; l < 2; l++) {
            int id = tid * 2 + l;
            int r = id >> 2, c4 = id & 3;
            float4 v = *(const float4*)&A[(bm + r) * D_ + k0 + c4 * 4];
            uint32_t h;
            h = f2tf32(v.x); Ah[c4 * 4 + 0][r] = h; Al[c4 * 4 + 0][r] = f2tf32(v.x - __uint_as_float(h));
            h = f2tf32(v.y); Ah[c4 * 4 + 1][r] = h; Al[c4 * 4 + 1][r] = f2tf32(v.y - __uint_as_float(h));
            h = f2tf32(v.z); Ah[c4 * 4 + 2][r] = h; Al[c4 * 4 + 2][r] = f2tf32(v.z - __uint_as_float(h));
            h = f2tf32(v.w); Ah[c4 * 4 + 3][r] = h; Al[c4 * 4 + 3][r] = f2tf32(v.w - __uint_as_float(h));
        }
        {
            int r = tid >> 4, c4 = tid & 15;
            uint4 vh = *(const uint4*)&Bh[(k0 + r) * D_ + bn + c4 * 4];
            *(uint4*)&Bsh[r][c4 * 4] = vh;
            uint4 vl = *(const uint4*)&Bl[(k0 + r) * D_ + bn + c4 * 4];
            *(uint4*)&Bsl[r][c4 * 4] = vl;
        }
        __syncthreads();
#pragma unroll
        for (int ks = 0; ks < 16; ks += 8) {
            uint32_t ah[2][4], al[2][4], bh[4][2], bl[4][2];
#pragma unroll
            for (int m = 0; m < 2; m++) {
                int rb = wm * 32 + m * 16;
                ah[m][0] = Ah[ks + t][rb + g];
                ah[m][1] = Ah[ks + t][rb + g + 8];
                ah[m][2] = Ah[ks + t + 4][rb + g];
                ah[m][3] = Ah[ks + t + 4][rb + g + 8];
                al[m][0] = Al[ks + t][rb + g];
                al[m][1] = Al[ks + t][rb + g + 8];
                al[m][2] = Al[ks + t + 4][rb + g];
                al[m][3] = Al[ks + t + 4][rb + g + 8];
            }
#pragma unroll
            for (int n = 0; n < 4; n++) {
                int cb = wn * 32 + n * 8;
                bh[n][0] = Bsh[ks + t][cb + g];
                bh[n][1] = Bsh[ks + t + 4][cb + g];
                bl[n][0] = Bsl[ks + t][cb + g];
                bl[n][1] = Bsl[ks + t + 4][cb + g];
            }
#pragma unroll
            for (int m = 0; m < 2; m++)
#pragma unroll
                for (int n = 0; n < 4; n++) {
                    mma_tf32(acc[m][n], ah[m], bh[n]);
                    mma_tf32(acc[m][n], ah[m], bl[n]);
                    mma_tf32(acc[m][n], al[m], bh[n]);
                }
        }
        __syncthreads();
    }
    float sq[2][2] = {};
#pragma unroll
    for (int m = 0; m < 2; m++) {
        int row0 = bm + wm * 32 + m * 16 + g;
        int row1 = row0 + 8;
#pragma unroll
        for (int n = 0; n < 4; n++) {
            int col = bn + wn * 32 + n * 8 + t * 2;
            float b0 = bias[col], b1 = bias[col + 1];
            float v00 = acc[m][n][0] + b0, v01 = acc[m][n][1] + b1;
            float v10 = acc[m][n][2] + b0, v11 = acc[m][n][3] + b1;
            if (RELU) {
                v00 = fmaxf(v00, 0.f); v01 = fmaxf(v01, 0.f);
                v10 = fmaxf(v10, 0.f); v11 = fmaxf(v11, 0.f);
            }
            *(float2*)&C[row0 * D_ + col] = make_float2(v00, v01);
            *(float2*)&C[row1 * D_ + col] = make_float2(v10, v11);
            if (NORM) {
                sq[m][0] += v00 * v00 + v01 * v01;
                sq[m][1] += v10 * v10 + v11 * v11;
            }
        }
    }
    if (NORM) {
#pragma unroll
        for (int m = 0; m < 2; m++) {
            ssq[wm * 32 + m * 16 + g][wn * 4 + t] = sq[m][0];
            ssq[wm * 32 + m * 16 + g + 8][wn * 4 + t] = sq[m][1];
        }
        __syncthreads();
        if (tid < 128) {
            float s = 0.f;
#pragma unroll
            for (int q = 0; q < 8; q++) s += ssq[tid][q];
            g_znpart[blockIdx.y][bm + tid] = s;
        }
    }
}

__global__ void znorm_fin_kernel() {
    int r = blockIdx.x * 256 + threadIdx.x;
    float s = g_znpart[0][r] + g_znpart[1][r] + g_znpart[2][r] + g_znpart[3][r];
    g_znorm[r] = fmaxf(sqrtf(s), 1e-8f);
}

// att/sim/lse GEMM: BM=64 rows x BN=128 j, 128 threads, 8x8 microtile.
__global__ void attgemm_kernel() {
    __shared__ float As[16][68];
    __shared__ float Bs[16][132];
    __shared__ float redm[64][17], reds[64][17];
    __shared__ float s_invi[64], s_invj[128];
    const int bm = blockIdx.x * 64;
    const int sp = blockIdx.y;
    const int j0 = sp * 128;
    const int tid = threadIdx.x;
    const int tx = tid & 15, ty = tid >> 4;
    if (tid < 64) s_invi[tid] = 1.f / g_znorm[bm + tid];
    s_invj[tid] = 1.f / g_znorm[j0 + tid];
    float acc[8][8];
#pragma unroll
    for (int r = 0; r < 8; r++)
#pragma unroll
        for (int c = 0; c < 8; c++) acc[r][c] = 0.f;

    for (int k0 = 0; k0 < D_; k0 += 16) {
#pragma unroll
        for (int l = 0; l < 2; l++) {
            int id = tid * 2 + l;
            int r = id >> 2, c4 = id & 3;
            float4 v = *(const float4*)&g_z[(bm + r) * D_ + k0 + c4 * 4];
            As[c4 * 4 + 0][r] = v.x;
            As[c4 * 4 + 1][r] = v.y;
            As[c4 * 4 + 2][r] = v.z;
            As[c4 * 4 + 3][r] = v.w;
        }
#pragma unroll
        for (int l = 0; l < 4; l++) {
            int id = tid + 128 * l;
            int jr = id >> 2, c4 = id & 3;
            float4 v = *(const float4*)&g_z[(j0 + jr) * D_ + k0 + c4 * 4];
            Bs[c4 * 4 + 0][jr] = v.x;
            Bs[c4 * 4 + 1][jr] = v.y;
            Bs[c4 * 4 + 2][jr] = v.z;
            Bs[c4 * 4 + 3][jr] = v.w;
        }
        __syncthreads();
#pragma unroll
        for (int kk = 0; kk < 16; kk++) {
            float4 a0 = *(const float4*)&As[kk][ty * 8];
            float4 a1 = *(const float4*)&As[kk][ty * 8 + 4];
            float4 b0 = *(const float4*)&Bs[kk][tx * 8];
            float4 b1 = *(const float4*)&Bs[kk][tx * 8 + 4];
            float a[8] = {a0.x, a0.y, a0.z, a0.w, a1.x, a1.y, a1.z, a1.w};
            float b[8] = {b0.x, b0.y, b0.z, b0.w, b1.x, b1.y, b1.z, b1.w};
#pragma unroll
            for (int r = 0; r < 8; r++)
#pragma unroll
                for (int c = 0; c < 8; c++) acc[r][c] += a[r] * b[c];
        }
        __syncthreads();
    }
    if (j0 < MHN_) {
#pragma unroll
        for (int r = 0; r < 8; r++) {
            int i = bm + ty * 8 + r;
            if (i >= MHN_) continue;
            float invi = s_invi[ty * 8 + r];
#pragma unroll
            for (int c = 0; c < 8; c++) {
                int j = j0 + tx * 8 + c;
                if (j < MHN_) {
                    g_attdot[i * MHN_ + j] = acc[r][c];
                    g_sim[i * MHN_ + j] = acc[r][c] * invi * s_invj[tx * 8 + c];
                }
            }
        }
    }
#pragma unroll
    for (int r = 0; r < 8; r++) {
        float m = -FLT_MAX;
#pragma unroll
        for (int c = 0; c < 8; c++) m = fmaxf(m, acc[r][c]);
        float s = 0.f;
#pragma unroll
        for (int c = 0; c < 8; c++) s += __expf(acc[r][c] - m);
        redm[ty * 8 + r][tx] = m;
        reds[ty * 8 + r][tx] = s;
    }
    __syncthreads();
    if (tid < 64) {
        int i = bm + tid;
        if (i < MHN_) {
            float M = -FLT_MAX;
#pragma unroll
            for (int q = 0; q < 16; q++) M = fmaxf(M, redm[tid][q]);
            float S = 0.f;
#pragma unroll
            for (int q = 0; q < 16; q++) S += reds[tid][q] * __expf(redm[tid][q] - M);
            g_attm[i * NSPL_ + sp] = M;
            g_atts[i * NSPL_ + sp] = S;
        }
    }
    if (bm < MFN_) {
        __syncthreads();
#pragma unroll
        for (int r = 0; r < 8; r++) {
            float vi = s_invi[ty * 8 + r] * (1.f / TAU_F);
            float m = -FLT_MAX;
            float vv[8];
#pragma unroll
            for (int c = 0; c < 8; c++) {
                vv[c] = acc[r][c] * vi * s_invj[tx * 8 + c];
                m = fmaxf(m, vv[c]);
            }
            float s = 0.f;
#pragma unroll
            for (int c = 0; c < 8; c++) s += __expf(vv[c] - m);
            redm[ty * 8 + r][tx] = m;
            reds[ty * 8 + r][tx] = s;
        }
        __syncthreads();
        if (tid < 64) {
            int i = bm + tid;
            if (i < MFN_) {
                float M = -FLT_MAX;
#pragma unroll
                for (int q = 0; q < 16; q++) M = fmaxf(M, redm[tid][q]);
                float S = 0.f;
#pragma unroll
                for (int q = 0; q < 16; q++) S += reds[tid][q] * __expf(redm[tid][q] - M);
                g_lsem[i * NSPL_ + sp] = M;
                g_lses[i * NSPL_ + sp] = S;
            }
        }
    }
}

// cl logits GEMM: z[0:512] @ hedges[0:512]^T, scaled by 1/(|zi||hj|tau)
__global__ void clgemm_kernel() {
    __shared__ float As[16][68];
    __shared__ float Bs[16][132];
    __shared__ float s_invi[64], s_invj[128];
    const int bm = blockIdx.x * 64;
    const int j0 = blockIdx.y * 128;
    const int tid = threadIdx.x;
    const int tx = tid & 15, ty = tid >> 4;
    if (tid < 64) s_invi[tid] = 1.f / g_znorm[bm + tid];
    s_invj[tid] = 1.f / g_hnorm[j0 + tid];
    float acc[8][8];
#pragma unroll
    for (int r = 0; r < 8; r++)
#pragma unroll
        for (int c = 0; c < 8; c++) acc[r][c] = 0.f;
    for (int k0 = 0; k0 < D_; k0 += 16) {
#pragma unroll
        for (int l = 0; l < 2; l++) {
            int id = tid * 2 + l;
            int r = id >> 2, c4 = id & 3;
            float4 v = *(const float4*)&g_z[(bm + r) * D_ + k0 + c4 * 4];
            As[c4 * 4 + 0][r] = v.x;
            As[c4 * 4 + 1][r] = v.y;
            As[c4 * 4 + 2][r] = v.z;
            As[c4 * 4 + 3][r] = v.w;
        }
#pragma unroll
        for (int l = 0; l < 4; l++) {
            int id = tid + 128 * l;
            int jr = id >> 2, c4 = id & 3;
            float4 v = *(const float4*)&g_hedges[(j0 + jr) * D_ + k0 + c4 * 4];
            Bs[c4 * 4 + 0][jr] = v.x;
            Bs[c4 * 4 + 1][jr] = v.y;
            Bs[c4 * 4 + 2][jr] = v.z;
            Bs[c4 * 4 + 3][jr] = v.w;
        }
        __syncthreads();
#pragma unroll
        for (int kk = 0; kk < 16; kk++) {
            float4 a0 = *(const float4*)&As[kk][ty * 8];
            float4 a1 = *(const float4*)&As[kk][ty * 8 + 4];
            float4 b0 = *(const float4*)&Bs[kk][tx * 8];
            float4 b1 = *(const float4*)&Bs[kk][tx * 8 + 4];
            float a[8] = {a0.x, a0.y, a0.z, a0.w, a1.x, a1.y, a1.z, a1.w};
            float b[8] = {b0.x, b0.y, b0.z, b0.w, b1.x, b1.y, b1.z, b1.w};
#pragma unroll
            for (int r = 0; r < 8; r++)
#pragma unroll
                for (int c = 0; c < 8; c++) acc[r][c] += a[r] * b[c];
        }
        __syncthreads();
    }
#pragma unroll
    for (int r = 0; r < 8; r++) {
        int i = bm + ty * 8 + r;
        if (i >= ECAP_) continue;
        float vi = s_invi[ty * 8 + r] * (1.f / TAU_F);
#pragma unroll
        for (int c = 0; c < 8; c += 2) {
            int j = j0 + tx * 8 + c;
            if (j < ECAP_ - 1) {
                *(float2*)&g_logits[i * 512 + j] =
                    make_float2(acc[r][c] * vi * s_invj[tx * 8 + c],
                                acc[r][c + 1] * vi * s_invj[tx * 8 + c + 1]);
            } else {
                if (j < ECAP_) g_logits[i * 512 + j] = acc[r][c] * vi * s_invj[tx * 8 + c];
                if (j + 1 < ECAP_) g_logits[i * 512 + j + 1] = acc[r][c + 1] * vi * s_invj[tx * 8 + c + 1];
            }
        }
    }
}

// Sparse edge aggregation: grid (125 edge-groups, 8 i-splits), warp-local rows.
__global__ void edge_part_kernel(const float* __restrict__ Hp, const float* __restrict__ z) {
    __shared__ float racc[8][4][256];
    __shared__ int rcnt[8][4];
    const int tid = threadIdx.x;
    const int lane = tid & 31, w = tid >> 5;
    const int e0 = blockIdx.x * 4, sp = blockIdx.y;
    float acc[4][8] = {};
    int cnt[4] = {0, 0, 0, 0};
    const int ibase = sp * 1024;
#pragma unroll 1
    for (int ic = 0; ic < 1024; ic += 256) {
        int i0 = ibase + ic;
        float4 v = *(const float4*)&Hp[(size_t)(i0 + tid) * E_ + e0];
        int m = (v.x > 0.f) | ((v.y > 0.f) << 1) | ((v.z > 0.f) << 2) | ((v.w > 0.f) << 3);
        unsigned b = __ballot_sync(0xffffffffu, m != 0);
        int rowbase = i0 + w * 32;
        while (b) {
            int src = __ffs(b) - 1;
            b &= b - 1;
            int mm = __shfl_sync(0xffffffffu, m, src);
            const float* zr = &z[(size_t)(rowbase + src) * D_];
            float zv[8];
#pragma unroll
            for (int t = 0; t < 8; t++) zv[t] = zr[lane + 32 * t];
            switch (mm) {
                case 1:
#pragma unroll
                    for (int t = 0; t < 8; t++) acc[0][t] += zv[t];
                    cnt[0]++; break;
                case 2:
#pragma unroll
                    for (int t = 0; t < 8; t++) acc[1][t] += zv[t];
                    cnt[1]++; break;
                case 4:
#pragma unroll
                    for (int t = 0; t < 8; t++) acc[2][t] += zv[t];
                    cnt[2]++; break;
                case 8:
#pragma unroll
                    for (int t = 0; t < 8; t++) acc[3][t] += zv[t];
                    cnt[3]++; break;
                default:
                    if (mm & 1) {
#pragma unroll
                        for (int t = 0; t < 8; t++) acc[0][t] += zv[t];
                        cnt[0]++;
                    }
                    if (mm & 2) {
#pragma unroll
                        for (int t = 0; t < 8; t++) acc[1][t] += zv[t];
                        cnt[1]++;
                    }
                    if (mm & 4) {
#pragma unroll
                        for (int t = 0; t < 8; t++) acc[2][t] += zv[t];
                        cnt[2]++;
                    }
                    if (mm & 8) {
#pragma unroll
                        for (int t = 0; t < 8; t++) acc[3][t] += zv[t];
                        cnt[3]++;
                    }
            }
        }
    }
#pragma unroll
    for (int e = 0; e < 4; e++)
#pragma unroll
        for (int t = 0; t < 8; t++) racc[w][e][lane + 32 * t] = acc[e][t];
    if (lane == 0) {
#pragma unroll
        for (int e = 0; e < 4; e++) rcnt[w][e] = cnt[e];
    }
    __syncthreads();
#pragma unroll
    for (int e = 0; e < 4; e++) {
        float s = 0.f;
#pragma unroll
        for (int q = 0; q < 8; q++) s += racc[q][e][tid];
        g_edge_part[sp][(e0 + e) * D_ + tid] = s;
    }
    if (tid < 4) {
        int c = 0;
#pragma unroll
        for (int q = 0; q < 8; q++) c += rcnt[q][tid];
        g_cntp[sp][e0 + tid] = c;
    }
}

// edge MLP layer 1 (mean fused)
__global__ void gemm64_e1_kernel(const float* __restrict__ B, const float* __restrict__ bias,
                                 float* __restrict__ C) {
    __shared__ float As[16][68];
    __shared__ float Bs[16][68];
    const int bm = blockIdx.x * 64, bn = blockIdx.y * 64;
    const int tid = threadIdx.x;
    const int tx = tid & 15, ty = tid >> 4;
    const int arow = bm + (tid >> 2);
    float cinv = 0.f;
    {
        int c = 0;
#pragma unroll
        for (int p = 0; p < 8; p++) c += g_cntp[p][arow];
        cinv = (c > 0 && arow < ECAP_) ? 1.f / (float)c : 0.f;
    }
    float acc[4][4] = {};
    for (int k0 = 0; k0 < D_; k0 += 16) {
        {
            int r = tid >> 2, c4 = tid & 3;
            float4 s = make_float4(0.f, 0.f, 0.f, 0.f);
#pragma unroll
            for (int p = 0; p < 8; p++) {
                float4 t = *(const float4*)&g_edge_part[p][arow * D_ + k0 + c4 * 4];
                s.x += t.x; s.y += t.y; s.z += t.z; s.w += t.w;
            }
            As[c4 * 4 + 0][r] = s.x * cinv;
            As[c4 * 4 + 1][r] = s.y * cinv;
            As[c4 * 4 + 2][r] = s.z * cinv;
            As[c4 * 4 + 3][r] = s.w * cinv;
        }
        {
            int r = tid >> 4, c4 = tid & 15;
            float4 v = *(const float4*)&B[(k0 + r) * D_ + bn + c4 * 4];
            *(float4*)&Bs[r][c4 * 4] = v;
        }
        __syncthreads();
#pragma unroll
        for (int kk = 0; kk < 16; kk++) {
            float a[4], b[4];
#pragma unroll
            for (int u = 0; u < 4; u++) a[u] = As[kk][ty * 4 + u];
#pragma unroll
            for (int u = 0; u < 4; u++) b[u] = Bs[kk][tx * 4 + u];
#pragma unroll
            for (int i = 0; i < 4; i++)
#pragma unroll
                for (int j = 0; j < 4; j++) acc[i][j] += a[i] * b[j];
        }
        __syncthreads();
    }
#pragma unroll
    for (int i = 0; i < 4; i++) {
        int row = bm + ty * 4 + i;
#pragma unroll
        for (int j = 0; j < 4; j++) {
            int col = bn + tx * 4 + j;
            C[row * D_ + col] = fmaxf(acc[i][j] + bias[col], 0.f);
        }
    }
}

// edge MLP layer 2 (hnorm partials fused)
__global__ void gemm64_e2_kernel(const float* __restrict__ A, const float* __restrict__ B,
                                 const float* __restrict__ bias, float* __restrict__ C) {
    __shared__ float As[16][68];
    __shared__ float Bs[16][68];
    __shared__ float ssq[64][17];
    const int bm = blockIdx.x * 64, bn = blockIdx.y * 64;
    const int tid = threadIdx.x;
    const int tx = tid & 15, ty = tid >> 4;
    float acc[4][4] = {};
    for (int k0 = 0; k0 < D_; k0 += 16) {
        {
            int r = tid >> 2, c4 = tid & 3;
            float4 v = *(const float4*)&A[(bm + r) * D_ + k0 + c4 * 4];
            As[c4 * 4 + 0][r] = v.x;
            As[c4 * 4 + 1][r] = v.y;
            As[c4 * 4 + 2][r] = v.z;
            As[c4 * 4 + 3][r] = v.w;
        }
        {
            int r = tid >> 4, c4 = tid & 15;
            float4 v = *(const float4*)&B[(k0 + r) * D_ + bn + c4 * 4];
            *(float4*)&Bs[r][c4 * 4] = v;
        }
        __syncthreads();
#pragma unroll
        for (int kk = 0; kk < 16; kk++) {
            float a[4], b[4];
#pragma unroll
            for (int u = 0; u < 4; u++) a[u] = As[kk][ty * 4 + u];
#pragma unroll
            for (int u = 0; u < 4; u++) b[u] = Bs[kk][tx * 4 + u];
#pragma unroll
            for (int i = 0; i < 4; i++)
#pragma unroll
                for (int j = 0; j < 4; j++) acc[i][j] += a[i] * b[j];
        }
        __syncthreads();
    }
#pragma unroll
    for (int i = 0; i < 4; i++) {
        int row = bm + ty * 4 + i;
        float sq = 0.f;
#pragma unroll
        for (int j = 0; j < 4; j++) {
            int col = bn + tx * 4 + j;
            float v = acc[i][j] + bias[col];
            C[row * D_ + col] = v;
            sq += v * v;
        }
        ssq[ty * 4 + i][tx] = sq;
    }
    __syncthreads();
    if (tid < 64) {
        float s = 0.f;
#pragma unroll
        for (int q = 0; q < 16; q++) s += ssq[tid][q];
        g_hnpart[blockIdx.y][bm + tid] = s;
    }
}

// merged finalize: att rows (0..199), lse (200), hnorm (201)
__global__ void merge_kernel() {
    int b = blockIdx.x;
    if (b < MHN_) {
        int i = b;
        __shared__ float Ms, Ss;
        if (threadIdx.x == 0) {
            float M = -FLT_MAX;
            for (int p = 0; p < NSPL_; p++) M = fmaxf(M, g_attm[i * NSPL_ + p]);
            float S = 0.f;
            for (int p = 0; p < NSPL_; p++) S += g_atts[i * NSPL_ + p] * __expf(g_attm[i * NSPL_ + p] - M);
            Ms = M; Ss = S;
        }
        __syncthreads();
        for (int j = threadIdx.x; j < MHN_; j += blockDim.x)
            g_att[i * MHN_ + j] = __expf(g_attdot[i * MHN_ + j] - Ms) / Ss;
    } else if (b == MHN_) {
        int i = threadIdx.x;
        if (i < MFN_) {
            float M = -FLT_MAX;
            for (int p = 0; p < NSPL_; p++) M = fmaxf(M, g_lsem[i * NSPL_ + p]);
            float S = 0.f;
            for (int p = 0; p < NSPL_; p++) S += g_lses[i * NSPL_ + p] * __expf(g_lsem[i * NSPL_ + p] - M);
            g_lse[i] = M + logf(S);
        }
    } else {
        for (int j = threadIdx.x; j < 512; j += blockDim.x) {
            if (j < ECAP_) {
                float s = g_hnpart[0][j] + g_hnpart[1][j] + g_hnpart[2][j] + g_hnpart[3][j];
                g_hnorm[j] = fmaxf(sqrtf(s), 1e-8f);
            } else {
                g_hnorm[j] = 1.f;
            }
        }
    }
}

// fused losses: blocks [0,500) = cl rows (softmax over precomputed logits);
// [500,700) = hn rows (+ fn for i<100)
__global__ void losses_kernel(const float* __restrict__ Ho, const float* __restrict__ Hp) {
    __shared__ float sm[32];
    int b = blockIdx.x;
    int tid = threadIdx.x;
    if (b < ECAP_) {
        int i = b;
        float lm = -FLT_MAX;
        for (int j = tid; j < ECAP_; j += 256) lm = fmaxf(lm, g_logits[i * 512 + j]);
        float M = block_max(lm, sm);
        float ls = 0.f;
        for (int j = tid; j < ECAP_; j += 256) ls += __expf(g_logits[i * 512 + j] - M);
        float S = block_sum(ls, sm);
        if (tid == 0) g_clrow[i] = g_logits[i * 512 + i] - (M + logf(S));
    } else {
        int i = b - ECAP_;
        {
            int j = tid;
            bool act = j < MHN_;
            float simv = act ? g_sim[i * MHN_ + j] : 0.f;
            float attv = act ? g_att[i * MHN_ + j] : 1.f;
            bool mask = act && (j != i) && (simv > MU_F) && (attv < NU_F);
            float neg = -simv / TAU_F;
            float m = block_max(mask ? neg : -FLT_MAX, sm);
            if (m == -FLT_MAX) {
                if (tid == 0) { g_hnsum[i] = 0.f; g_hncnt[i] = 0.f; }
            } else {
                float s = block_sum(mask ? expf(neg - m) : 0.f, sm);
                float lse = m + logf(s);
                float wgt = fminf(simv / MU_F, 1.f);
                float pair = -wgt * (neg - lse);
                float ps = block_sum(mask ? pair : 0.f, sm);
                float pc = block_sum(mask ? 1.f : 0.f, sm);
                if (tid == 0) { g_hnsum[i] = ps; g_hncnt[i] = pc; }
            }
        }
        if (i < MFN_) {
            __shared__ unsigned char cand[128];
            __shared__ short clist[MFN_];
            __shared__ int ncand;
            if (tid < 128) cand[tid] = 0;
            __syncthreads();
            if (tid < MFN_) {
                bool g = (tid > i) && (g_sim[i * MHN_ + tid] > GAMMA_F)
                                   && (g_att[i * MHN_ + tid] > DELTA_F);
                cand[tid] = g ? 1 : 0;
            }
            __syncthreads();
            if (tid == 0) {
                int n = 0;
                for (int j = i + 1; j < MFN_; j++) if (cand[j]) clist[n++] = (short)j;
                ncand = n;
            }
            __syncthreads();
            int nc = ncand;
            float fsum = 0.f, fcnt = 0.f;
            for (int k = 0; k < nc; k++) {
                int j = clist[k];
                float ao = 0.f, ap = 0.f;
                for (int t = tid; t < E_; t += 256) {
                    ao += Ho[i * E_ + t] * Ho[j * E_ + t];
                    ap += Hp[i * E_ + t] * Hp[j * E_ + t];
                }
                ao = block_sum(ao, sm);
                ap = block_sum(ap, sm);
                if (ap == 0.f && ao > 0.f) {
                    fsum += -(g_sim[i * MHN_ + j] / TAU_F - g_lse[i]);
                    fcnt += 1.f;
                }
            }
            if (tid == 0) { g_fnrow[i] = fsum; g_fncnt[i] = fcnt; }
        }
    }
}

// final combine
__global__ void final_kernel(const float* __restrict__ bw, float* __restrict__ out) {
    __shared__ float sm[32];
    int tid = threadIdx.x;
    float v = 0.f;
    for (int i = tid; i < ECAP_; i += 512) v += g_clrow[i];
    float clsum = block_sum(v, sm);
    v = 0.f; float c = 0.f;
    for (int i = tid; i < MFN_; i += 512) { v += g_fnrow[i]; c += g_fncnt[i]; }
    float fnsum = block_sum(v, sm);
    float fncnt = block_sum(c, sm);
    v = 0.f; c = 0.f;
    for (int i = tid; i < MHN_; i += 512) { v += g_hnsum[i]; c += g_hncnt[i]; }
    float hnsum = block_sum(v, sm);
    float hncnt = block_sum(c, sm);
    float d2 = 0.f, o2 = 0.f;
    for (int i = tid; i < SAMP_; i += 512) { d2 += g_topo[i * 2]; o2 += g_topo[i * 2 + 1]; }
    float D2 = block_sum(d2, sm);
    float O2 = block_sum(o2, sm);
    float za = 0.f, zb = 0.f;
    for (int i = tid; i < 2048; i += 512) { za += (float)g_nza[i]; zb += (float)g_nzb[i]; }
    float NZ = block_sum(za, sm);
    float NZP = block_sum(zb, sm);
    if (tid == 0) {
        float cl_loss = -clsum / (float)ECAP_;
        float fn_loss = (fncnt > 0.f) ? fnsum / fmaxf(fncnt, 1.f) : 0.f;
        float hard_loss = (hncnt > 0.f) ? hnsum / fmaxf(hncnt, 1.f) : 0.f;
        float sparsity = (NZ > 0.f) ? NZP / fmaxf(NZ, 1.f) : 1.f;
        float dn = sqrtf(D2), on = sqrtf(O2);
        float topo = (on > 0.f) ? expf(-ALPHA_F * dn / fmaxf(on, 1e-12f)) : 1.f;
        float retention = sparsity * topo;
        out[0] = bw[0] * (retention * cl_loss + fn_loss + hard_loss);
    }
}

// ---------------- launch ----------------
extern "C" void kernel_launch(void* const* d_in, const int* in_sizes, int n_in,
                              void* d_out, int out_size) {
    (void)in_sizes; (void)n_in; (void)out_size;
    const float* Ho  = (const float*)d_in[0];
    const float* Hp  = (const float*)d_in[1];
    const float* ne  = (const float*)d_in[2];
    const float* bw  = (const float*)d_in[3];
    const float* Wn1 = (const float*)d_in[4];
    const float* bn1 = (const float*)d_in[5];
    const float* Wn2 = (const float*)d_in[6];
    const float* bn2 = (const float*)d_in[7];
    const float* We1 = (const float*)d_in[8];
    const float* be1 = (const float*)d_in[9];
    const float* We2 = (const float*)d_in[10];
    const float* be2 = (const float*)d_in[11];
    float* out = (float*)d_out;

    void *p;
    float *p_tmp, *p_z, *p_etmp, *p_hedges;
    uint32_t *p_w1h, *p_w1l, *p_w2h, *p_w2l;
    cudaGetSymbolAddress(&p, g_tmp);    p_tmp    = (float*)p;
    cudaGetSymbolAddress(&p, g_z);      p_z      = (float*)p;
    cudaGetSymbolAddress(&p, g_etmp);   p_etmp   = (float*)p;
    cudaGetSymbolAddress(&p, g_hedges); p_hedges = (float*)p;
    cudaGetSymbolAddress(&p, g_w1h);    p_w1h    = (uint32_t*)p;
    cudaGetSymbolAddress(&p, g_w1l);    p_w1l    = (uint32_t*)p;
    cudaGetSymbolAddress(&p, g_w2h);    p_w2h    = (uint32_t*)p;
    cudaGetSymbolAddress(&p, g_w2l);    p_w2l    = (uint32_t*)p;

    // idx 0-1: weight pre-split + count
    wsplit_kernel<<<256, 256>>>(Wn1, Wn2);
    count_nz_kernel<<<2048, 256>>>((const float4*)Ho, (const float4*)Hp);

    // idx 2-3: node MLP via pre-split TF32 tensor cores (idx 3 PROFILED)
    gemm_tf32_kernel<true,  false><<<dim3(64, 4), 256>>>(ne,    p_w1h, p_w1l, bn1, p_tmp);
    gemm_tf32_kernel<false, true ><<<dim3(64, 4), 256>>>(p_tmp, p_w2h, p_w2l, bn2, p_z);

    // idx 4: znorm finalize
    znorm_fin_kernel<<<32, 256>>>();

    // idx 5: att/sim/lse GEMM
    attgemm_kernel<<<dim3(4, NSPL_), 128>>>();

    // idx 6: edge aggregation partials
    edge_part_kernel<<<dim3(ECAP_ / 4, 8), 256>>>(Hp, p_z);

    // idx 7-8: edge MLP
    gemm64_e1_kernel<<<dim3(8, 4), 256>>>(We1, be1, p_etmp);
    gemm64_e2_kernel<<<dim3(8, 4), 256>>>(p_etmp, We2, be2, p_hedges);

    // idx 9: merge finalizers (att softmax, lse, hnorm)
    merge_kernel<<<MHN_ + 2, 256>>>();

    // idx 10: cl logits GEMM
    clgemm_kernel<<<dim3(8, 4), 128>>>();

    // idx 11: topo
    topo_kernel<<<SAMP_, 128>>>(Ho, Hp);

    // idx 12: fused losses
    losses_kernel<<<ECAP_ + MHN_, 256>>>(Ho, Hp);

    // idx 13: final combine
    final_kernel<<<1, 512>>>(bw, out);
}

// round 10
// speedup vs baseline: 5.9868x; 1.0288x over previous
#include <cuda_runtime.h>
#include <math.h>
#include <cfloat>
#include <stdint.h>

// ---------------- constants ----------------
#define TAU_F   0.4f
#define ALPHA_F 1.0f
#define GAMMA_F 0.7f
#define DELTA_F 0.6f
#define MU_F    0.6f
#define NU_F    0.3f

#define N_  8192
#define E_  2048
#define D_  256
#define SAMP_ 100
#define MFN_  100
#define MHN_  200
#define ECAP_ 500
#define NSPL_ 64

// ---------------- scratch (device globals) ----------------
__device__ float g_tmp[N_ * D_];
__device__ float g_z[N_ * D_];
__device__ float g_znpart[4][N_];
__device__ float g_znorm[N_];
__device__ float g_edge_part[8][512 * D_];
__device__ int   g_cntp[8][512];
__device__ float g_etmp[512 * D_];
__device__ float g_hedges[512 * D_];
__device__ float g_hnpart[4][512];
__device__ float g_hnorm[512];
__device__ float g_logits[512 * 512];
__device__ float g_sim[MHN_ * MHN_];
__device__ float g_attdot[MHN_ * MHN_];
__device__ float g_attm[MHN_ * NSPL_], g_atts[MHN_ * NSPL_];
__device__ float g_att[MHN_ * MHN_];
__device__ float g_lsem[MFN_ * NSPL_], g_lses[MFN_ * NSPL_];
__device__ float g_lse[MFN_];
__device__ float g_clrow[ECAP_];
__device__ float g_fnrow[MFN_], g_fncnt[MFN_];
__device__ float g_hnsum[MHN_], g_hncnt[MHN_];
__device__ int   g_nza[2048], g_nzb[2048];
__device__ float g_topo[SAMP_ * 2];

// ---------------- helpers ----------------
__device__ __forceinline__ float warp_sum(float v) {
#pragma unroll
    for (int o = 16; o > 0; o >>= 1) v += __shfl_xor_sync(0xffffffffu, v, o);
    return v;
}
__device__ __forceinline__ float warp_max(float v) {
#pragma unroll
    for (int o = 16; o > 0; o >>= 1) v = fmaxf(v, __shfl_xor_sync(0xffffffffu, v, o));
    return v;
}
__device__ __forceinline__ int warp_sum_i(int v) {
#pragma unroll
    for (int o = 16; o > 0; o >>= 1) v += __shfl_xor_sync(0xffffffffu, v, o);
    return v;
}
__device__ float block_sum(float v, float* sm) {
    int w = threadIdx.x >> 5, lane = threadIdx.x & 31, nw = blockDim.x >> 5;
    v = warp_sum(v);
    if (lane == 0) sm[w] = v;
    __syncthreads();
    float r = (threadIdx.x < nw) ? sm[threadIdx.x] : 0.f;
    if (w == 0) r = warp_sum(r);
    if (threadIdx.x == 0) sm[0] = r;
    __syncthreads();
    r = sm[0];
    __syncthreads();
    return r;
}
__device__ float block_max(float v, float* sm) {
    int w = threadIdx.x >> 5, lane = threadIdx.x & 31, nw = blockDim.x >> 5;
    v = warp_max(v);
    if (lane == 0) sm[w] = v;
    __syncthreads();
    float r = (threadIdx.x < nw) ? sm[threadIdx.x] : -FLT_MAX;
    if (w == 0) r = warp_max(r);
    if (threadIdx.x == 0) sm[0] = r;
    __syncthreads();
    r = sm[0];
    __syncthreads();
    return r;
}
__device__ __forceinline__ uint32_t f2tf32(float x) {
    uint32_t r;
    asm("cvt.rna.tf32.f32 %0, %1;" : "=r"(r) : "f"(x));
    return r;
}
__device__ __forceinline__ void mma_tf32(float* c, const uint32_t* a, const uint32_t* b) {
    asm volatile(
        "mma.sync.aligned.m16n8k8.row.col.f32.tf32.tf32.f32 "
        "{%0,%1,%2,%3}, {%4,%5,%6,%7}, {%8,%9}, {%0,%1,%2,%3};"
        : "+f"(c[0]), "+f"(c[1]), "+f"(c[2]), "+f"(c[3])
        : "r"(a[0]), "r"(a[1]), "r"(a[2]), "r"(a[3]), "r"(b[0]), "r"(b[1]));
}
// online (m,s) merge
__device__ __forceinline__ void msmerge(float& m, float& s, float m2, float s2) {
    float M = fmaxf(m, m2);
    s = s * __expf(m - M) + s2 * __expf(m2 - M);
    m = M;
}
__device__ __forceinline__ void msadd(float& m, float& s, float v) {
    if (v <= m) s += __expf(v - m);
    else { s = s * __expf(m - v) + 1.f; m = v; }
}

// ---------------- kernels ----------------

__global__ void count_nz_kernel(const float4* __restrict__ a, const float4* __restrict__ b) {
    const int n4 = N_ * E_ / 4;
    int ca = 0, cb = 0;
    for (int i = blockIdx.x * blockDim.x + threadIdx.x; i < n4; i += gridDim.x * blockDim.x) {
        float4 x = a[i];
        ca += (x.x != 0.f) + (x.y != 0.f) + (x.z != 0.f) + (x.w != 0.f);
        float4 y = b[i];
        cb += (y.x != 0.f) + (y.y != 0.f) + (y.z != 0.f) + (y.w != 0.f);
    }
    __shared__ int sa[32], sb[32];
    int w = threadIdx.x >> 5, lane = threadIdx.x & 31;
    ca = warp_sum_i(ca); cb = warp_sum_i(cb);
    if (lane == 0) { sa[w] = ca; sb[w] = cb; }
    __syncthreads();
    if (w == 0) {
        int x = (lane < 8) ? sa[lane] : 0;
        int y = (lane < 8) ? sb[lane] : 0;
        x = warp_sum_i(x); y = warp_sum_i(y);
        if (lane == 0) { g_nza[blockIdx.x] = x; g_nzb[blockIdx.x] = y; }
    }
}

__global__ void topo_kernel(const float* __restrict__ Ho, const float* __restrict__ Hp) {
    __shared__ float hoi[128], hpi[128];
    __shared__ float sm[32];
    int i = blockIdx.x;
    int tid = threadIdx.x;
    if (tid < SAMP_) { hoi[tid] = Ho[i * E_ + tid]; hpi[tid] = Hp[i * E_ + tid]; }
    else             { hoi[tid] = 0.f; hpi[tid] = 0.f; }
    __syncthreads();
    int w = tid >> 5, lane = tid & 31;
    float dn2 = 0.f, on2 = 0.f;
    for (int j = w; j < SAMP_; j += 4) {
        float as = 0.f, aps = 0.f;
#pragma unroll
        for (int t = 0; t < 4; t++) {
            int k = lane + 32 * t;
            if (k < SAMP_) {
                as  += hoi[k] * Ho[j * E_ + k];
                aps += hpi[k] * Hp[j * E_ + k];
            }
        }
        as = warp_sum(as);
        aps = warp_sum(aps);
        if (lane == 0) {
            float d = as - aps;
            dn2 += d * d;
            on2 += as * as;
        }
    }
    float D2 = block_sum(dn2, sm);
    float O2 = block_sum(on2, sm);
    if (tid == 0) { g_topo[i * 2] = D2; g_topo[i * 2 + 1] = O2; }
}

// TF32 tensor-core MLP GEMM, split-at-smem-load for both operands.
// BM=128, BN=64, 256 threads (8 warps: 4M x 2N), warp tile 32x32.
template <bool RELU, bool NORM>
__global__ void gemm_tf32_kernel(const float* __restrict__ A, const float* __restrict__ B,
                                 const float* __restrict__ bias, float* __restrict__ C) {
    __shared__ uint32_t Ah[16][136], Al[16][136];
    __shared__ uint32_t Bsh[16][72], Bsl[16][72];
    __shared__ float ssq[128][9];
    const int bm = blockIdx.x * 128, bn = blockIdx.y * 64;
    const int tid = threadIdx.x;
    const int lane = tid & 31, wid = tid >> 5;
    const int wm = wid >> 1, wn = wid & 1;
    const int g = lane >> 2, t = lane & 3;
    float acc[2][4][4];
#pragma unroll
    for (int m = 0; m < 2; m++)
#pragma unroll
        for (int n = 0; n < 4; n++)
#pragma unroll
            for (int q = 0; q < 4; q++) acc[m][n][q] = 0.f;

    for (int k0 = 0; k0 < D_; k0 += 16) {
#pragma unroll
        for (int l = 0; l < 2; l++) {
            int id = tid * 2 + l;
            int r = id >> 2, c4 = id & 3;
            float4 v = *(const float4*)&A[(bm + r) * D_ + k0 + c4 * 4];
            uint32_t h;
            h = f2tf32(v.x); Ah[c4 * 4 + 0][r] = h; Al[c4 * 4 + 0][r] = f2tf32(v.x - __uint_as_float(h));
            h = f2tf32(v.y); Ah[c4 * 4 + 1][r] = h; Al[c4 * 4 + 1][r] = f2tf32(v.y - __uint_as_float(h));
            h = f2tf32(v.z); Ah[c4 * 4 + 2][r] = h; Al[c4 * 4 + 2][r] = f2tf32(v.z - __uint_as_float(h));
            h = f2tf32(v.w); Ah[c4 * 4 + 3][r] = h; Al[c4 * 4 + 3][r] = f2tf32(v.w - __uint_as_float(h));
        }
        {
            int r = tid >> 4, c4 = tid & 15;
            float4 v = *(const float4*)&B[(k0 + r) * D_ + bn + c4 * 4];
            uint32_t h;
            h = f2tf32(v.x); Bsh[r][c4 * 4 + 0] = h; Bsl[r][c4 * 4 + 0] = f2tf32(v.x - __uint_as_float(h));
            h = f2tf32(v.y); Bsh[r][c4 * 4 + 1] = h; Bsl[r][c4 * 4 + 1] = f2tf32(v.y - __uint_as_float(h));
            h = f2tf32(v.z); Bsh[r][c4 * 4 + 2] = h; Bsl[r][c4 * 4 + 2] = f2tf32(v.z - __uint_as_float(h));
            h = f2tf32(v.w); Bsh[r][c4 * 4 + 3] = h; Bsl[r][c4 * 4 + 3] = f2tf32(v.w - __uint_as_float(h));
        }
        __syncthreads();
#pragma unroll
        for (int ks = 0; ks < 16; ks += 8) {
            uint32_t ah[2][4], al[2][4], bh[4][2], bl[4][2];
#pragma unroll
            for (int m = 0; m < 2; m++) {
                int rb = wm * 32 + m * 16;
                ah[m][0] = Ah[ks + t][rb + g];
                ah[m][1] = Ah[ks + t][rb + g + 8];
                ah[m][2] = Ah[ks + t + 4][rb + g];
                ah[m][3] = Ah[ks + t + 4][rb + g + 8];
                al[m][0] = Al[ks + t][rb + g];
                al[m][1] = Al[ks + t][rb + g + 8];
                al[m][2] = Al[ks + t + 4][rb + g];
                al[m][3] = Al[ks + t + 4][rb + g + 8];
            }
#pragma unroll
            for (int n = 0; n < 4; n++) {
                int cb = wn * 32 + n * 8;
                bh[n][0] = Bsh[ks + t][cb + g];
                bh[n][1] = Bsh[ks + t + 4][cb + g];
                bl[n][0] = Bsl[ks + t][cb + g];
                bl[n][1] = Bsl[ks + t + 4][cb + g];
            }
#pragma unroll
            for (int m = 0; m < 2; m++)
#pragma unroll
                for (int n = 0; n < 4; n++) {
                    mma_tf32(acc[m][n], ah[m], bh[n]);
                    mma_tf32(acc[m][n], ah[m], bl[n]);
                    mma_tf32(acc[m][n], al[m], bh[n]);
                }
        }
        __syncthreads();
    }
    float sq[2][2] = {};
#pragma unroll
    for (int m = 0; m < 2; m++) {
        int row0 = bm + wm * 32 + m * 16 + g;
        int row1 = row0 + 8;
#pragma unroll
        for (int n = 0; n < 4; n++) {
            int col = bn + wn * 32 + n * 8 + t * 2;
            float b0 = bias[col], b1 = bias[col + 1];
            float v00 = acc[m][n][0] + b0, v01 = acc[m][n][1] + b1;
            float v10 = acc[m][n][2] + b0, v11 = acc[m][n][3] + b1;
            if (RELU) {
                v00 = fmaxf(v00, 0.f); v01 = fmaxf(v01, 0.f);
                v10 = fmaxf(v10, 0.f); v11 = fmaxf(v11, 0.f);
            }
            *(float2*)&C[row0 * D_ + col] = make_float2(v00, v01);
            *(float2*)&C[row1 * D_ + col] = make_float2(v10, v11);
            if (NORM) {
                sq[m][0] += v00 * v00 + v01 * v01;
                sq[m][1] += v10 * v10 + v11 * v11;
            }
        }
    }
    if (NORM) {
#pragma unroll
        for (int m = 0; m < 2; m++) {
            ssq[wm * 32 + m * 16 + g][wn * 4 + t] = sq[m][0];
            ssq[wm * 32 + m * 16 + g + 8][wn * 4 + t] = sq[m][1];
        }
        __syncthreads();
        if (tid < 128) {
            float s = 0.f;
#pragma unroll
            for (int q = 0; q < 8; q++) s += ssq[tid][q];
            g_znpart[blockIdx.y][bm + tid] = s;
        }
    }
}

__global__ void znorm_fin_kernel() {
    int r = blockIdx.x * 256 + threadIdx.x;
    float s = g_znpart[0][r] + g_znpart[1][r] + g_znpart[2][r] + g_znpart[3][r];
    g_znorm[r] = fmaxf(sqrtf(s), 1e-8f);
}

// TF32 att/sim/lse GEMM: block = 64 rows x 128 j, 256 threads (8 warps 4m x 2n),
// warp tile m16 x n64. 3-term split, split-at-smem-load.
__global__ void attgemm_kernel() {
    __shared__ uint32_t Ah[16][72], Al[16][72];
    __shared__ uint32_t Bh[16][136], Bl[16][136];
    __shared__ float redm[64][2], reds[64][2];
    __shared__ float redm2[64][2], reds2[64][2];
    __shared__ float s_invi[64], s_invj[128];
    const int bm = blockIdx.x * 64;
    const int sp = blockIdx.y;
    const int j0 = sp * 128;
    const int tid = threadIdx.x;
    const int lane = tid & 31, wid = tid >> 5;
    const int wm = wid >> 1, wn = wid & 1;
    const int g = lane >> 2, t = lane & 3;
    if (tid < 64) s_invi[tid] = 1.f / g_znorm[bm + tid];
    else if (tid < 192) s_invj[tid - 64] = 1.f / g_znorm[j0 + tid - 64];
    float acc[8][4];
#pragma unroll
    for (int n = 0; n < 8; n++)
#pragma unroll
        for (int q = 0; q < 4; q++) acc[n][q] = 0.f;

    for (int k0 = 0; k0 < D_; k0 += 16) {
        {
            int r = tid >> 2, c4 = tid & 3;
            float4 v = *(const float4*)&g_z[(bm + r) * D_ + k0 + c4 * 4];
            uint32_t h;
            h = f2tf32(v.x); Ah[c4 * 4 + 0][r] = h; Al[c4 * 4 + 0][r] = f2tf32(v.x - __uint_as_float(h));
            h = f2tf32(v.y); Ah[c4 * 4 + 1][r] = h; Al[c4 * 4 + 1][r] = f2tf32(v.y - __uint_as_float(h));
            h = f2tf32(v.z); Ah[c4 * 4 + 2][r] = h; Al[c4 * 4 + 2][r] = f2tf32(v.z - __uint_as_float(h));
            h = f2tf32(v.w); Ah[c4 * 4 + 3][r] = h; Al[c4 * 4 + 3][r] = f2tf32(v.w - __uint_as_float(h));
        }
#pragma unroll
        for (int l = 0; l < 2; l++) {
            int id = tid + 256 * l;
            int jr = id >> 2, c4 = id & 3;
            float4 v = *(const float4*)&g_z[(j0 + jr) * D_ + k0 + c4 * 4];
            uint32_t h;
            h = f2tf32(v.x); Bh[c4 * 4 + 0][jr] = h; Bl[c4 * 4 + 0][jr] = f2tf32(v.x - __uint_as_float(h));
            h = f2tf32(v.y); Bh[c4 * 4 + 1][jr] = h; Bl[c4 * 4 + 1][jr] = f2tf32(v.y - __uint_as_float(h));
            h = f2tf32(v.z); Bh[c4 * 4 + 2][jr] = h; Bl[c4 * 4 + 2][jr] = f2tf32(v.z - __uint_as_float(h));
            h = f2tf32(v.w); Bh[c4 * 4 + 3][jr] = h; Bl[c4 * 4 + 3][jr] = f2tf32(v.w - __uint_as_float(h));
        }
        __syncthreads();
#pragma unroll
        for (int ks = 0; ks < 16; ks += 8) {
            uint32_t ah[4], al[4];
            int rb = wm * 16;
            ah[0] = Ah[ks + t][rb + g];
            ah[1] = Ah[ks + t][rb + g + 8];
            ah[2] = Ah[ks + t + 4][rb + g];
            ah[3] = Ah[ks + t + 4][rb + g + 8];
            al[0] = Al[ks + t][rb + g];
            al[1] = Al[ks + t][rb + g + 8];
            al[2] = Al[ks + t + 4][rb + g];
            al[3] = Al[ks + t + 4][rb + g + 8];
#pragma unroll
            for (int n = 0; n < 8; n++) {
                int cb = wn * 64 + n * 8;
                uint32_t bh[2] = {Bh[ks + t][cb + g], Bh[ks + t + 4][cb + g]};
                uint32_t bl[2] = {Bl[ks + t][cb + g], Bl[ks + t + 4][cb + g]};
                mma_tf32(acc[n], ah, bh);
                mma_tf32(acc[n], ah, bl);
                mma_tf32(acc[n], al, bh);
            }
        }
        __syncthreads();
    }
    const int rbase = wm * 16 + g;
    const int r0 = bm + rbase, r1 = r0 + 8;
    // sim / attdot stores
    if (j0 < MHN_) {
        float i0v = s_invi[rbase], i1v = s_invi[rbase + 8];
#pragma unroll
        for (int n = 0; n < 8; n++) {
            int cl = wn * 64 + n * 8 + 2 * t;
            int j = j0 + cl;
            if (j < MHN_) {
                float jv = s_invj[cl];
                if (r0 < MHN_) { g_attdot[r0 * MHN_ + j] = acc[n][0]; g_sim[r0 * MHN_ + j] = acc[n][0] * i0v * jv; }
                if (r1 < MHN_) { g_attdot[r1 * MHN_ + j] = acc[n][2]; g_sim[r1 * MHN_ + j] = acc[n][2] * i1v * jv; }
            }
            if (j + 1 < MHN_) {
                float jv = s_invj[cl + 1];
                if (r0 < MHN_) { g_attdot[r0 * MHN_ + j + 1] = acc[n][1]; g_sim[r0 * MHN_ + j + 1] = acc[n][1] * i0v * jv; }
                if (r1 < MHN_) { g_attdot[r1 * MHN_ + j + 1] = acc[n][3]; g_sim[r1 * MHN_ + j + 1] = acc[n][3] * i1v * jv; }
            }
        }
    }
    // att softmax partials (raw dots) for both rows
    {
        float m0 = -FLT_MAX, m1 = -FLT_MAX;
#pragma unroll
        for (int n = 0; n < 8; n++) {
            m0 = fmaxf(m0, fmaxf(acc[n][0], acc[n][1]));
            m1 = fmaxf(m1, fmaxf(acc[n][2], acc[n][3]));
        }
        float s0 = 0.f, s1 = 0.f;
#pragma unroll
        for (int n = 0; n < 8; n++) {
            s0 += __expf(acc[n][0] - m0) + __expf(acc[n][1] - m0);
            s1 += __expf(acc[n][2] - m1) + __expf(acc[n][3] - m1);
        }
#pragma unroll
        for (int o = 1; o <= 2; o <<= 1) {
            float mo = __shfl_xor_sync(0xffffffffu, m0, o);
            float so = __shfl_xor_sync(0xffffffffu, s0, o);
            msmerge(m0, s0, mo, so);
            mo = __shfl_xor_sync(0xffffffffu, m1, o);
            so = __shfl_xor_sync(0xffffffffu, s1, o);
            msmerge(m1, s1, mo, so);
        }
        if (t == 0) {
            redm[rbase][wn] = m0; reds[rbase][wn] = s0;
            redm[rbase + 8][wn] = m1; reds[rbase + 8][wn] = s1;
        }
    }
    // lse partials (normalized / tau) for rows < 100
    if (bm < MFN_) {
        float vt0 = s_invi[rbase] * (1.f / TAU_F);
        float vt1 = s_invi[rbase + 8] * (1.f / TAU_F);
        float m2 = -FLT_MAX, s2 = 0.f, m3 = -FLT_MAX, s3 = 0.f;
#pragma unroll
        for (int n = 0; n < 8; n++) {
            int cl = wn * 64 + n * 8 + 2 * t;
            float j0v = s_invj[cl], j1v = s_invj[cl + 1];
            msadd(m2, s2, acc[n][0] * vt0 * j0v);
            msadd(m2, s2, acc[n][1] * vt0 * j1v);
            msadd(m3, s3, acc[n][2] * vt1 * j0v);
            msadd(m3, s3, acc[n][3] * vt1 * j1v);
        }
#pragma unroll
        for (int o = 1; o <= 2; o <<= 1) {
            float mo = __shfl_xor_sync(0xffffffffu, m2, o);
            float so = __shfl_xor_sync(0xffffffffu, s2, o);
            msmerge(m2, s2, mo, so);
            mo = __shfl_xor_sync(0xffffffffu, m3, o);
            so = __shfl_xor_sync(0xffffffffu, s3, o);
            msmerge(m3, s3, mo, so);
        }
        if (t == 0) {
            redm2[rbase][wn] = m2; reds2[rbase][wn] = s2;
            redm2[rbase + 8][wn] = m3; reds2[rbase + 8][wn] = s3;
        }
    }
    __syncthreads();
    if (tid < 64) {
        int i = bm + tid;
        if (i < MHN_) {
            float M = redm[tid][0], S = reds[tid][0];
            msmerge(M, S, redm[tid][1], reds[tid][1]);
            g_attm[i * NSPL_ + sp] = M;
            g_atts[i * NSPL_ + sp] = S;
        }
        if (i < MFN_) {
            float M = redm2[tid][0], S = reds2[tid][0];
            msmerge(M, S, redm2[tid][1], reds2[tid][1]);
            g_lsem[i * NSPL_ + sp] = M;
            g_lses[i * NSPL_ + sp] = S;
        }
    }
}

// cl logits GEMM: z[0:512] @ hedges[0:512]^T, scaled by 1/(|zi||hj|tau)
__global__ void clgemm_kernel() {
    __shared__ float As[16][68];
    __shared__ float Bs[16][132];
    __shared__ float s_invi[64], s_invj[128];
    const int bm = blockIdx.x * 64;
    const int j0 = blockIdx.y * 128;
    const int tid = threadIdx.x;
    const int tx = tid & 15, ty = tid >> 4;
    if (tid < 64) s_invi[tid] = 1.f / g_znorm[bm + tid];
    s_invj[tid] = 1.f / g_hnorm[j0 + tid];
    float acc[8][8];
#pragma unroll
    for (int r = 0; r < 8; r++)
#pragma unroll
        for (int c = 0; c < 8; c++) acc[r][c] = 0.f;
    for (int k0 = 0; k0 < D_; k0 += 16) {
#pragma unroll
        for (int l = 0; l < 2; l++) {
            int id = tid * 2 + l;
            int r = id >> 2, c4 = id & 3;
            float4 v = *(const float4*)&g_z[(bm + r) * D_ + k0 + c4 * 4];
            As[c4 * 4 + 0][r] = v.x;
            As[c4 * 4 + 1][r] = v.y;
            As[c4 * 4 + 2][r] = v.z;
            As[c4 * 4 + 3][r] = v.w;
        }
#pragma unroll
        for (int l = 0; l < 4; l++) {
            int id = tid + 128 * l;
            int jr = id >> 2, c4 = id & 3;
            float4 v = *(const float4*)&g_hedges[(j0 + jr) * D_ + k0 + c4 * 4];
            Bs[c4 * 4 + 0][jr] = v.x;
            Bs[c4 * 4 + 1][jr] = v.y;
            Bs[c4 * 4 + 2][jr] = v.z;
            Bs[c4 * 4 + 3][jr] = v.w;
        }
        __syncthreads();
#pragma unroll
        for (int kk = 0; kk < 16; kk++) {
            float4 a0 = *(const float4*)&As[kk][ty * 8];
            float4 a1 = *(const float4*)&As[kk][ty * 8 + 4];
            float4 b0 = *(const float4*)&Bs[kk][tx * 8];
            float4 b1 = *(const float4*)&Bs[kk][tx * 8 + 4];
            float a[8] = {a0.x, a0.y, a0.z, a0.w, a1.x, a1.y, a1.z, a1.w};
            float b[8] = {b0.x, b0.y, b0.z, b0.w, b1.x, b1.y, b1.z, b1.w};
#pragma unroll
            for (int r = 0; r < 8; r++)
#pragma unroll
                for (int c = 0; c < 8; c++) acc[r][c] += a[r] * b[c];
        }
        __syncthreads();
    }
#pragma unroll
    for (int r = 0; r < 8; r++) {
        int i = bm + ty * 8 + r;
        if (i >= ECAP_) continue;
        float vi = s_invi[ty * 8 + r] * (1.f / TAU_F);
#pragma unroll
        for (int c = 0; c < 8; c += 2) {
            int j = j0 + tx * 8 + c;
            if (j < ECAP_ - 1) {
                *(float2*)&g_logits[i * 512 + j] =
                    make_float2(acc[r][c] * vi * s_invj[tx * 8 + c],
                                acc[r][c + 1] * vi * s_invj[tx * 8 + c + 1]);
            } else {
                if (j < ECAP_) g_logits[i * 512 + j] = acc[r][c] * vi * s_invj[tx * 8 + c];
                if (j + 1 < ECAP_) g_logits[i * 512 + j + 1] = acc[r][c + 1] * vi * s_invj[tx * 8 + c + 1];
            }
        }
    }
}

// Sparse edge aggregation: grid (125 edge-groups, 8 i-splits), warp-local rows.
__global__ void edge_part_kernel(const float* __restrict__ Hp, const float* __restrict__ z) {
    __shared__ float racc[8][4][256];
    __shared__ int rcnt[8][4];
    const int tid = threadIdx.x;
    const int lane = tid & 31, w = tid >> 5;
    const int e0 = blockIdx.x * 4, sp = blockIdx.y;
    float acc[4][8] = {};
    int cnt[4] = {0, 0, 0, 0};
    const int ibase = sp * 1024;
#pragma unroll 1
    for (int ic = 0; ic < 1024; ic += 256) {
        int i0 = ibase + ic;
        float4 v = *(const float4*)&Hp[(size_t)(i0 + tid) * E_ + e0];
        int m = (v.x > 0.f) | ((v.y > 0.f) << 1) | ((v.z > 0.f) << 2) | ((v.w > 0.f) << 3);
        unsigned b = __ballot_sync(0xffffffffu, m != 0);
        int rowbase = i0 + w * 32;
        while (b) {
            int src = __ffs(b) - 1;
            b &= b - 1;
            int mm = __shfl_sync(0xffffffffu, m, src);
            const float* zr = &z[(size_t)(rowbase + src) * D_];
            float zv[8];
#pragma unroll
            for (int t = 0; t < 8; t++) zv[t] = zr[lane + 32 * t];
            switch (mm) {
                case 1:
#pragma unroll
                    for (int t = 0; t < 8; t++) acc[0][t] += zv[t];
                    cnt[0]++; break;
                case 2:
#pragma unroll
                    for (int t = 0; t < 8; t++) acc[1][t] += zv[t];
                    cnt[1]++; break;
                case 4:
#pragma unroll
                    for (int t = 0; t < 8; t++) acc[2][t] += zv[t];
                    cnt[2]++; break;
                case 8:
#pragma unroll
                    for (int t = 0; t < 8; t++) acc[3][t] += zv[t];
                    cnt[3]++; break;
                default:
                    if (mm & 1) {
#pragma unroll
                        for (int t = 0; t < 8; t++) acc[0][t] += zv[t];
                        cnt[0]++;
                    }
                    if (mm & 2) {
#pragma unroll
                        for (int t = 0; t < 8; t++) acc[1][t] += zv[t];
                        cnt[1]++;
                    }
                    if (mm & 4) {
#pragma unroll
                        for (int t = 0; t < 8; t++) acc[2][t] += zv[t];
                        cnt[2]++;
                    }
                    if (mm & 8) {
#pragma unroll
                        for (int t = 0; t < 8; t++) acc[3][t] += zv[t];
                        cnt[3]++;
                    }
            }
        }
    }
#pragma unroll
    for (int e = 0; e < 4; e++)
#pragma unroll
        for (int t = 0; t < 8; t++) racc[w][e][lane + 32 * t] = acc[e][t];
    if (lane == 0) {
#pragma unroll
        for (int e = 0; e < 4; e++) rcnt[w][e] = cnt[e];
    }
    __syncthreads();
#pragma unroll
    for (int e = 0; e < 4; e++) {
        float s = 0.f;
#pragma unroll
        for (int q = 0; q < 8; q++) s += racc[q][e][tid];
        g_edge_part[sp][(e0 + e) * D_ + tid] = s;
    }
    if (tid < 4) {
        int c = 0;
#pragma unroll
        for (int q = 0; q < 8; q++) c += rcnt[q][tid];
        g_cntp[sp][e0 + tid] = c;
    }
}

// edge MLP layer 1 (mean fused)
__global__ void gemm64_e1_kernel(const float* __restrict__ B, const float* __restrict__ bias,
                                 float* __restrict__ C) {
    __shared__ float As[16][68];
    __shared__ float Bs[16][68];
    const int bm = blockIdx.x * 64, bn = blockIdx.y * 64;
    const int tid = threadIdx.x;
    const int tx = tid & 15, ty = tid >> 4;
    const int arow = bm + (tid >> 2);
    float cinv = 0.f;
    {
        int c = 0;
#pragma unroll
        for (int p = 0; p < 8; p++) c += g_cntp[p][arow];
        cinv = (c > 0 && arow < ECAP_) ? 1.f / (float)c : 0.f;
    }
    float acc[4][4] = {};
    for (int k0 = 0; k0 < D_; k0 += 16) {
        {
            int r = tid >> 2, c4 = tid & 3;
            float4 s = make_float4(0.f, 0.f, 0.f, 0.f);
#pragma unroll
            for (int p = 0; p < 8; p++) {
                float4 t = *(const float4*)&g_edge_part[p][arow * D_ + k0 + c4 * 4];
                s.x += t.x; s.y += t.y; s.z += t.z; s.w += t.w;
            }
            As[c4 * 4 + 0][r] = s.x * cinv;
            As[c4 * 4 + 1][r] = s.y * cinv;
            As[c4 * 4 + 2][r] = s.z * cinv;
            As[c4 * 4 + 3][r] = s.w * cinv;
        }
        {
            int r = tid >> 4, c4 = tid & 15;
            float4 v = *(const float4*)&B[(k0 + r) * D_ + bn + c4 * 4];
            *(float4*)&Bs[r][c4 * 4] = v;
        }
        __syncthreads();
#pragma unroll
        for (int kk = 0; kk < 16; kk++) {
            float a[4], b[4];
#pragma unroll
            for (int u = 0; u < 4; u++) a[u] = As[kk][ty * 4 + u];
#pragma unroll
            for (int u = 0; u < 4; u++) b[u] = Bs[kk][tx * 4 + u];
#pragma unroll
            for (int i = 0; i < 4; i++)
#pragma unroll
                for (int j = 0; j < 4; j++) acc[i][j] += a[i] * b[j];
        }
        __syncthreads();
    }
#pragma unroll
    for (int i = 0; i < 4; i++) {
        int row = bm + ty * 4 + i;
#pragma unroll
        for (int j = 0; j < 4; j++) {
            int col = bn + tx * 4 + j;
            C[row * D_ + col] = fmaxf(acc[i][j] + bias[col], 0.f);
        }
    }
}

// edge MLP layer 2 (hnorm partials fused)
__global__ void gemm64_e2_kernel(const float* __restrict__ A, const float* __restrict__ B,
                                 const float* __restrict__ bias, float* __restrict__ C) {
    __shared__ float As[16][68];
    __shared__ float Bs[16][68];
    __shared__ float ssq[64][17];
    const int bm = blockIdx.x * 64, bn = blockIdx.y * 64;
    const int tid = threadIdx.x;
    const int tx = tid & 15, ty = tid >> 4;
    float acc[4][4] = {};
    for (int k0 = 0; k0 < D_; k0 += 16) {
        {
            int r = tid >> 2, c4 = tid & 3;
            float4 v = *(const float4*)&A[(bm + r) * D_ + k0 + c4 * 4];
            As[c4 * 4 + 0][r] = v.x;
            As[c4 * 4 + 1][r] = v.y;
            As[c4 * 4 + 2][r] = v.z;
            As[c4 * 4 + 3][r] = v.w;
        }
        {
            int r = tid >> 4, c4 = tid & 15;
            float4 v = *(const float4*)&B[(k0 + r) * D_ + bn + c4 * 4];
            *(float4*)&Bs[r][c4 * 4] = v;
        }
        __syncthreads();
#pragma unroll
        for (int kk = 0; kk < 16; kk++) {
            float a[4], b[4];
#pragma unroll
            for (int u = 0; u < 4; u++) a[u] = As[kk][ty * 4 + u];
#pragma unroll
            for (int u = 0; u < 4; u++) b[u] = Bs[kk][tx * 4 + u];
#pragma unroll
            for (int i = 0; i < 4; i++)
#pragma unroll
                for (int j = 0; j < 4; j++) acc[i][j] += a[i] * b[j];
        }
        __syncthreads();
    }
#pragma unroll
    for (int i = 0; i < 4; i++) {
        int row = bm + ty * 4 + i;
        float sq = 0.f;
#pragma unroll
        for (int j = 0; j < 4; j++) {
            int col = bn + tx * 4 + j;
            float v = acc[i][j] + bias[col];
            C[row * D_ + col] = v;
            sq += v * v;
        }
        ssq[ty * 4 + i][tx] = sq;
    }
    __syncthreads();
    if (tid < 64) {
        float s = 0.f;
#pragma unroll
        for (int q = 0; q < 16; q++) s += ssq[tid][q];
        g_hnpart[blockIdx.y][bm + tid] = s;
    }
}

// merged finalize: att rows (0..199), lse (200), hnorm (201)
__global__ void merge_kernel() {
    int b = blockIdx.x;
    if (b < MHN_) {
        int i = b;
        __shared__ float Ms, Ss;
        if (threadIdx.x == 0) {
            float M = -FLT_MAX;
            for (int p = 0; p < NSPL_; p++) M = fmaxf(M, g_attm[i * NSPL_ + p]);
            float S = 0.f;
            for (int p = 0; p < NSPL_; p++) S += g_atts[i * NSPL_ + p] * __expf(g_attm[i * NSPL_ + p] - M);
            Ms = M; Ss = S;
        }
        __syncthreads();
        for (int j = threadIdx.x; j < MHN_; j += blockDim.x)
            g_att[i * MHN_ + j] = __expf(g_attdot[i * MHN_ + j] - Ms) / Ss;
    } else if (b == MHN_) {
        int i = threadIdx.x;
        if (i < MFN_) {
            float M = -FLT_MAX;
            for (int p = 0; p < NSPL_; p++) M = fmaxf(M, g_lsem[i * NSPL_ + p]);
            float S = 0.f;
            for (int p = 0; p < NSPL_; p++) S += g_lses[i * NSPL_ + p] * __expf(g_lsem[i * NSPL_ + p] - M);
            g_lse[i] = M + logf(S);
        }
    } else {
        for (int j = threadIdx.x; j < 512; j += blockDim.x) {
            if (j < ECAP_) {
                float s = g_hnpart[0][j] + g_hnpart[1][j] + g_hnpart[2][j] + g_hnpart[3][j];
                g_hnorm[j] = fmaxf(sqrtf(s), 1e-8f);
            } else {
                g_hnorm[j] = 1.f;
            }
        }
    }
}

// fused losses: blocks [0,500) = cl rows (softmax over precomputed logits);
// [500,700) = hn rows (+ fn for i<100)
__global__ void losses_kernel(const float* __restrict__ Ho, const float* __restrict__ Hp) {
    __shared__ float sm[32];
    int b = blockIdx.x;
    int tid = threadIdx.x;
    if (b < ECAP_) {
        int i = b;
        float lm = -FLT_MAX;
        for (int j = tid; j < ECAP_; j += 256) lm = fmaxf(lm, g_logits[i * 512 + j]);
        float M = block_max(lm, sm);
        float ls = 0.f;
        for (int j = tid; j < ECAP_; j += 256) ls += __expf(g_logits[i * 512 + j] - M);
        float S = block_sum(ls, sm);
        if (tid == 0) g_clrow[i] = g_logits[i * 512 + i] - (M + logf(S));
    } else {
        int i = b - ECAP_;
        {
            int j = tid;
            bool act = j < MHN_;
            float simv = act ? g_sim[i * MHN_ + j] : 0.f;
            float attv = act ? g_att[i * MHN_ + j] : 1.f;
            bool mask = act && (j != i) && (simv > MU_F) && (attv < NU_F);
            float neg = -simv / TAU_F;
            float m = block_max(mask ? neg : -FLT_MAX, sm);
            if (m == -FLT_MAX) {
                if (tid == 0) { g_hnsum[i] = 0.f; g_hncnt[i] = 0.f; }
            } else {
                float s = block_sum(mask ? expf(neg - m) : 0.f, sm);
                float lse = m + logf(s);
                float wgt = fminf(simv / MU_F, 1.f);
                float pair = -wgt * (neg - lse);
                float ps = block_sum(mask ? pair : 0.f, sm);
                float pc = block_sum(mask ? 1.f : 0.f, sm);
                if (tid == 0) { g_hnsum[i] = ps; g_hncnt[i] = pc; }
            }
        }
        if (i < MFN_) {
            __shared__ unsigned char cand[128];
            __shared__ short clist[MFN_];
            __shared__ int ncand;
            if (tid < 128) cand[tid] = 0;
            __syncthreads();
            if (tid < MFN_) {
                bool g = (tid > i) && (g_sim[i * MHN_ + tid] > GAMMA_F)
                                   && (g_att[i * MHN_ + tid] > DELTA_F);
                cand[tid] = g ? 1 : 0;
            }
            __syncthreads();
            if (tid == 0) {
                int n = 0;
                for (int j = i + 1; j < MFN_; j++) if (cand[j]) clist[n++] = (short)j;
                ncand = n;
            }
            __syncthreads();
            int nc = ncand;
            float fsum = 0.f, fcnt = 0.f;
            for (int k = 0; k < nc; k++) {
                int j = clist[k];
                float ao = 0.f, ap = 0.f;
                for (int t = tid; t < E_; t += 256) {
                    ao += Ho[i * E_ + t] * Ho[j * E_ + t];
                    ap += Hp[i * E_ + t] * Hp[j * E_ + t];
                }
                ao = block_sum(ao, sm);
                ap = block_sum(ap, sm);
                if (ap == 0.f && ao > 0.f) {
                    fsum += -(g_sim[i * MHN_ + j] / TAU_F - g_lse[i]);
                    fcnt += 1.f;
                }
            }
            if (tid == 0) { g_fnrow[i] = fsum; g_fncnt[i] = fcnt; }
        }
    }
}

// final combine
__global__ void final_kernel(const float* __restrict__ bw, float* __restrict__ out) {
    __shared__ float sm[32];
    int tid = threadIdx.x;
    float v = 0.f;
    for (int i = tid; i < ECAP_; i += 512) v += g_clrow[i];
    float clsum = block_sum(v, sm);
    v = 0.f; float c = 0.f;
    for (int i = tid; i < MFN_; i += 512) { v += g_fnrow[i]; c += g_fncnt[i]; }
    float fnsum = block_sum(v, sm);
    float fncnt = block_sum(c, sm);
    v = 0.f; c = 0.f;
    for (int i = tid; i < MHN_; i += 512) { v += g_hnsum[i]; c += g_hncnt[i]; }
    float hnsum = block_sum(v, sm);
    float hncnt = block_sum(c, sm);
    float d2 = 0.f, o2 = 0.f;
    for (int i = tid; i < SAMP_; i += 512) { d2 += g_topo[i * 2]; o2 += g_topo[i * 2 + 1]; }
    float D2 = block_sum(d2, sm);
    float O2 = block_sum(o2, sm);
    float za = 0.f, zb = 0.f;
    for (int i = tid; i < 2048; i += 512) { za += (float)g_nza[i]; zb += (float)g_nzb[i]; }
    float NZ = block_sum(za, sm);
    float NZP = block_sum(zb, sm);
    if (tid == 0) {
        float cl_loss = -clsum / (float)ECAP_;
        float fn_loss = (fncnt > 0.f) ? fnsum / fmaxf(fncnt, 1.f) : 0.f;
        float hard_loss = (hncnt > 0.f) ? hnsum / fmaxf(hncnt, 1.f) : 0.f;
        float sparsity = (NZ > 0.f) ? NZP / fmaxf(NZ, 1.f) : 1.f;
        float dn = sqrtf(D2), on = sqrtf(O2);
        float topo = (on > 0.f) ? expf(-ALPHA_F * dn / fmaxf(on, 1e-12f)) : 1.f;
        float retention = sparsity * topo;
        out[0] = bw[0] * (retention * cl_loss + fn_loss + hard_loss);
    }
}

// ---------------- launch ----------------
extern "C" void kernel_launch(void* const* d_in, const int* in_sizes, int n_in,
                              void* d_out, int out_size) {
    (void)in_sizes; (void)n_in; (void)out_size;
    const float* Ho  = (const float*)d_in[0];
    const float* Hp  = (const float*)d_in[1];
    const float* ne  = (const float*)d_in[2];
    const float* bw  = (const float*)d_in[3];
    const float* Wn1 = (const float*)d_in[4];
    const float* bn1 = (const float*)d_in[5];
    const float* Wn2 = (const float*)d_in[6];
    const float* bn2 = (const float*)d_in[7];
    const float* We1 = (const float*)d_in[8];
    const float* be1 = (const float*)d_in[9];
    const float* We2 = (const float*)d_in[10];
    const float* be2 = (const float*)d_in[11];
    float* out = (float*)d_out;

    void *p;
    float *p_tmp, *p_z, *p_etmp, *p_hedges;
    cudaGetSymbolAddress(&p, g_tmp);    p_tmp    = (float*)p;
    cudaGetSymbolAddress(&p, g_z);      p_z      = (float*)p;
    cudaGetSymbolAddress(&p, g_etmp);   p_etmp   = (float*)p;
    cudaGetSymbolAddress(&p, g_hedges); p_hedges = (float*)p;

    // idx 0-1: node MLP via TF32 tensor cores (split-at-load)
    gemm_tf32_kernel<true,  false><<<dim3(64, 4), 256>>>(ne,    Wn1, bn1, p_tmp);
    gemm_tf32_kernel<false, true ><<<dim3(64, 4), 256>>>(p_tmp, Wn2, bn2, p_z);

    // idx 2: znorm finalize
    znorm_fin_kernel<<<32, 256>>>();

    // idx 3: att/sim/lse via TF32 tensor cores (PROFILED this round)
    attgemm_kernel<<<dim3(4, NSPL_), 256>>>();

    // idx 4-5: independent scans
    count_nz_kernel<<<2048, 256>>>((const float4*)Ho, (const float4*)Hp);
    topo_kernel<<<SAMP_, 128>>>(Ho, Hp);

    // idx 6: edge aggregation partials
    edge_part_kernel<<<dim3(ECAP_ / 4, 8), 256>>>(Hp, p_z);

    // idx 7-8: edge MLP
    gemm64_e1_kernel<<<dim3(8, 4), 256>>>(We1, be1, p_etmp);
    gemm64_e2_kernel<<<dim3(8, 4), 256>>>(p_etmp, We2, be2, p_hedges);

    // idx 9: merge finalizers (att softmax, lse, hnorm)
    merge_kernel<<<MHN_ + 2, 256>>>();

    // idx 10: cl logits GEMM
    clgemm_kernel<<<dim3(8, 4), 128>>>();

    // idx 11: fused losses
    losses_kernel<<<ECAP_ + MHN_, 256>>>(Ho, Hp);

    // idx 12: final combine
    final_kernel<<<1, 512>>>(bw, out);
}

// round 11
// speedup vs baseline: 6.1239x; 1.0229x over previous
#include <cuda_runtime.h>
#include <math.h>
#include <cfloat>
#include <stdint.h>

// ---------------- constants ----------------
#define TAU_F   0.4f
#define ALPHA_F 1.0f
#define GAMMA_F 0.7f
#define DELTA_F 0.6f
#define MU_F    0.6f
#define NU_F    0.3f

#define N_  8192
#define E_  2048
#define D_  256
#define SAMP_ 100
#define MFN_  100
#define MHN_  200
#define ECAP_ 500
#define NSPL_ 64

// ---------------- scratch (device globals) ----------------
__device__ float g_tmp[N_ * D_];
__device__ float g_z[N_ * D_];
__device__ float g_znpart[4][N_];
__device__ float g_edge_part[8][512 * D_];
__device__ int   g_cntp[8][512];
__device__ float g_etmp[512 * D_];
__device__ float g_hedges[512 * D_];
__device__ float g_hnpart[4][512];
__device__ float g_logits[512 * 512];
__device__ float g_sim[MHN_ * MHN_];
__device__ float g_attdot[MHN_ * MHN_];
__device__ float g_attm[MHN_ * NSPL_], g_atts[MHN_ * NSPL_];
__device__ float g_att[MHN_ * MHN_];
__device__ float g_lsem[MFN_ * NSPL_], g_lses[MFN_ * NSPL_];
__device__ float g_lse[MFN_];
__device__ float g_clrow[ECAP_];
__device__ float g_fnrow[MFN_], g_fncnt[MFN_];
__device__ float g_hnsum[MHN_], g_hncnt[MHN_];
__device__ int   g_nza[2048], g_nzb[2048];
__device__ float g_topo[SAMP_ * 2];

// ---------------- helpers ----------------
__device__ __forceinline__ float warp_sum(float v) {
#pragma unroll
    for (int o = 16; o > 0; o >>= 1) v += __shfl_xor_sync(0xffffffffu, v, o);
    return v;
}
__device__ __forceinline__ float warp_max(float v) {
#pragma unroll
    for (int o = 16; o > 0; o >>= 1) v = fmaxf(v, __shfl_xor_sync(0xffffffffu, v, o));
    return v;
}
__device__ __forceinline__ int warp_sum_i(int v) {
#pragma unroll
    for (int o = 16; o > 0; o >>= 1) v += __shfl_xor_sync(0xffffffffu, v, o);
    return v;
}
__device__ float block_sum(float v, float* sm) {
    int w = threadIdx.x >> 5, lane = threadIdx.x & 31, nw = blockDim.x >> 5;
    v = warp_sum(v);
    if (lane == 0) sm[w] = v;
    __syncthreads();
    float r = (threadIdx.x < nw) ? sm[threadIdx.x] : 0.f;
    if (w == 0) r = warp_sum(r);
    if (threadIdx.x == 0) sm[0] = r;
    __syncthreads();
    r = sm[0];
    __syncthreads();
    return r;
}
__device__ float block_max(float v, float* sm) {
    int w = threadIdx.x >> 5, lane = threadIdx.x & 31, nw = blockDim.x >> 5;
    v = warp_max(v);
    if (lane == 0) sm[w] = v;
    __syncthreads();
    float r = (threadIdx.x < nw) ? sm[threadIdx.x] : -FLT_MAX;
    if (w == 0) r = warp_max(r);
    if (threadIdx.x == 0) sm[0] = r;
    __syncthreads();
    r = sm[0];
    __syncthreads();
    return r;
}
__device__ __forceinline__ uint32_t f2tf32(float x) {
    uint32_t r;
    asm("cvt.rna.tf32.f32 %0, %1;" : "=r"(r) : "f"(x));
    return r;
}
__device__ __forceinline__ void mma_tf32(float* c, const uint32_t* a, const uint32_t* b) {
    asm volatile(
        "mma.sync.aligned.m16n8k8.row.col.f32.tf32.tf32.f32 "
        "{%0,%1,%2,%3}, {%4,%5,%6,%7}, {%8,%9}, {%0,%1,%2,%3};"
        : "+f"(c[0]), "+f"(c[1]), "+f"(c[2]), "+f"(c[3])
        : "r"(a[0]), "r"(a[1]), "r"(a[2]), "r"(a[3]), "r"(b[0]), "r"(b[1]));
}
__device__ __forceinline__ void ldsm4(uint32_t* r, uint32_t addr) {
    asm volatile("ldmatrix.sync.aligned.m8n8.x4.shared.b16 {%0,%1,%2,%3}, [%4];"
                 : "=r"(r[0]), "=r"(r[1]), "=r"(r[2]), "=r"(r[3]) : "r"(addr));
}
__device__ __forceinline__ uint32_t smem_u32(const void* p) {
    uint32_t a;
    asm("{ .reg .u64 t; cvta.to.shared.u64 t, %1; cvt.u32.u64 %0, t; }" : "=r"(a) : "l"(p));
    return a;
}
__device__ __forceinline__ void msmerge(float& m, float& s, float m2, float s2) {
    float M = fmaxf(m, m2);
    s = s * __expf(m - M) + s2 * __expf(m2 - M);
    m = M;
}
__device__ __forceinline__ void msadd(float& m, float& s, float v) {
    if (v <= m) s += __expf(v - m);
    else { s = s * __expf(m - v) + 1.f; m = v; }
}
__device__ __forceinline__ void split4(float4 v, uint32_t* hi, uint32_t* lo) {
    uint32_t h;
    h = f2tf32(v.x); hi[0] = h; lo[0] = f2tf32(v.x - __uint_as_float(h));
    h = f2tf32(v.y); hi[1] = h; lo[1] = f2tf32(v.y - __uint_as_float(h));
    h = f2tf32(v.z); hi[2] = h; lo[2] = f2tf32(v.z - __uint_as_float(h));
    h = f2tf32(v.w); hi[3] = h; lo[3] = f2tf32(v.w - __uint_as_float(h));
}

// ---------------- kernels ----------------

__global__ void count_nz_kernel(const float4* __restrict__ a, const float4* __restrict__ b) {
    const int n4 = N_ * E_ / 4;
    int ca = 0, cb = 0;
    for (int i = blockIdx.x * blockDim.x + threadIdx.x; i < n4; i += gridDim.x * blockDim.x) {
        float4 x = a[i];
        ca += (x.x != 0.f) + (x.y != 0.f) + (x.z != 0.f) + (x.w != 0.f);
        float4 y = b[i];
        cb += (y.x != 0.f) + (y.y != 0.f) + (y.z != 0.f) + (y.w != 0.f);
    }
    __shared__ int sa[32], sb[32];
    int w = threadIdx.x >> 5, lane = threadIdx.x & 31;
    ca = warp_sum_i(ca); cb = warp_sum_i(cb);
    if (lane == 0) { sa[w] = ca; sb[w] = cb; }
    __syncthreads();
    if (w == 0) {
        int x = (lane < 8) ? sa[lane] : 0;
        int y = (lane < 8) ? sb[lane] : 0;
        x = warp_sum_i(x); y = warp_sum_i(y);
        if (lane == 0) { g_nza[blockIdx.x] = x; g_nzb[blockIdx.x] = y; }
    }
}

__global__ void topo_kernel(const float* __restrict__ Ho, const float* __restrict__ Hp) {
    __shared__ float hoi[128], hpi[128];
    __shared__ float sm[32];
    int i = blockIdx.x;
    int tid = threadIdx.x;
    if (tid < SAMP_) { hoi[tid] = Ho[i * E_ + tid]; hpi[tid] = Hp[i * E_ + tid]; }
    else             { hoi[tid] = 0.f; hpi[tid] = 0.f; }
    __syncthreads();
    int w = tid >> 5, lane = tid & 31;
    float dn2 = 0.f, on2 = 0.f;
    for (int j = w; j < SAMP_; j += 4) {
        float as = 0.f, aps = 0.f;
#pragma unroll
        for (int t = 0; t < 4; t++) {
            int k = lane + 32 * t;
            if (k < SAMP_) {
                as  += hoi[k] * Ho[j * E_ + k];
                aps += hpi[k] * Hp[j * E_ + k];
            }
        }
        as = warp_sum(as);
        aps = warp_sum(aps);
        if (lane == 0) {
            float d = as - aps;
            dn2 += d * d;
            on2 += as * as;
        }
    }
    float D2 = block_sum(dn2, sm);
    float O2 = block_sum(on2, sm);
    if (tid == 0) { g_topo[i * 2] = D2; g_topo[i * 2 + 1] = O2; }
}

// TF32 MLP GEMM with ldmatrix fragment loads.
// BM=128, BN=64, 256 threads (8 warps: 4M x 2N), warp tile 32x32.
// A smem row-major [row][k], B smem n-major [n][k] (transposed at load), stride 20 words.
template <bool RELU, bool NORM>
__global__ void gemm_tf32_kernel(const float* __restrict__ A, const float* __restrict__ B,
                                 const float* __restrict__ bias, float* __restrict__ C) {
    __shared__ uint32_t Ah[128][20], Al[128][20];
    __shared__ uint32_t Bnh[64][20], Bnl[64][20];
    __shared__ float ssq[128][9];
    const int bm = blockIdx.x * 128, bn = blockIdx.y * 64;
    const int tid = threadIdx.x;
    const int lane = tid & 31, wid = tid >> 5;
    const int wm = wid >> 1, wn = wid & 1;
    const int g = lane >> 2, t = lane & 3;
    const uint32_t aH = smem_u32(&Ah[0][0]), aL = smem_u32(&Al[0][0]);
    const uint32_t bH = smem_u32(&Bnh[0][0]), bL = smem_u32(&Bnl[0][0]);
    float acc[2][4][4];
#pragma unroll
    for (int m = 0; m < 2; m++)
#pragma unroll
        for (int n = 0; n < 4; n++)
#pragma unroll
            for (int q = 0; q < 4; q++) acc[m][n][q] = 0.f;

    // ldmatrix per-lane address offsets (words)
    const int arow = (lane & 7) + ((lane >> 3) & 1) * 8;   // + rb
    const int acol = ((lane >> 4) & 1) * 4;                // + ks
    const int brow = (lane & 7) + ((lane >> 4) & 1) * 8;   // + cb
    const int bcol = ((lane >> 3) & 1) * 4;                // + ks

    for (int k0 = 0; k0 < D_; k0 += 16) {
        // load A tile (128 x 16) split hi/lo, row-major
#pragma unroll
        for (int l = 0; l < 2; l++) {
            int id = tid * 2 + l;
            int r = id >> 2, c4 = id & 3;
            float4 v = *(const float4*)&A[(bm + r) * D_ + k0 + c4 * 4];
            uint32_t hi[4], lo[4];
            split4(v, hi, lo);
            *(uint4*)&Ah[r][c4 * 4] = *(uint4*)hi;
            *(uint4*)&Al[r][c4 * 4] = *(uint4*)lo;
        }
        // load B tile (16k x 64n) transposed into [n][k]
        {
            int r = tid >> 4, c4 = tid & 15;   // k-row r, n-group c4
            float4 v = *(const float4*)&B[(k0 + r) * D_ + bn + c4 * 4];
            uint32_t hi[4], lo[4];
            split4(v, hi, lo);
#pragma unroll
            for (int j = 0; j < 4; j++) { Bnh[c4 * 4 + j][r] = hi[j]; Bnl[c4 * 4 + j][r] = lo[j]; }
        }
        __syncthreads();
#pragma unroll
        for (int ks = 0; ks < 16; ks += 8) {
            uint32_t ah[2][4], al[2][4], bh[2][4], bl[2][4];
#pragma unroll
            for (int m = 0; m < 2; m++) {
                uint32_t off = ((wm * 32 + m * 16 + arow) * 20 + ks + acol) * 4;
                ldsm4(ah[m], aH + off);
                ldsm4(al[m], aL + off);
            }
#pragma unroll
            for (int np = 0; np < 2; np++) {
                uint32_t off = ((wn * 32 + np * 16 + brow) * 20 + ks + bcol) * 4;
                ldsm4(bh[np], bH + off);
                ldsm4(bl[np], bL + off);
            }
#pragma unroll
            for (int m = 0; m < 2; m++)
#pragma unroll
                for (int n = 0; n < 4; n++) {
                    uint32_t* bhp = &bh[n >> 1][(n & 1) * 2];
                    uint32_t* blp = &bl[n >> 1][(n & 1) * 2];
                    mma_tf32(acc[m][n], ah[m], bhp);
                    mma_tf32(acc[m][n], ah[m], blp);
                    mma_tf32(acc[m][n], al[m], bhp);
                }
        }
        __syncthreads();
    }
    float sq[2][2] = {};
#pragma unroll
    for (int m = 0; m < 2; m++) {
        int row0 = bm + wm * 32 + m * 16 + g;
        int row1 = row0 + 8;
#pragma unroll
        for (int n = 0; n < 4; n++) {
            int col = bn + wn * 32 + n * 8 + t * 2;
            float b0 = bias[col], b1 = bias[col + 1];
            float v00 = acc[m][n][0] + b0, v01 = acc[m][n][1] + b1;
            float v10 = acc[m][n][2] + b0, v11 = acc[m][n][3] + b1;
            if (RELU) {
                v00 = fmaxf(v00, 0.f); v01 = fmaxf(v01, 0.f);
                v10 = fmaxf(v10, 0.f); v11 = fmaxf(v11, 0.f);
            }
            *(float2*)&C[row0 * D_ + col] = make_float2(v00, v01);
            *(float2*)&C[row1 * D_ + col] = make_float2(v10, v11);
            if (NORM) {
                sq[m][0] += v00 * v00 + v01 * v01;
                sq[m][1] += v10 * v10 + v11 * v11;
            }
        }
    }
    if (NORM) {
#pragma unroll
        for (int m = 0; m < 2; m++) {
            ssq[wm * 32 + m * 16 + g][wn * 4 + t] = sq[m][0];
            ssq[wm * 32 + m * 16 + g + 8][wn * 4 + t] = sq[m][1];
        }
        __syncthreads();
        if (tid < 128) {
            float s = 0.f;
#pragma unroll
            for (int q = 0; q < 8; q++) s += ssq[tid][q];
            g_znpart[blockIdx.y][bm + tid] = s;
        }
    }
}

// TF32 att/sim/lse GEMM with ldmatrix. Block 64 rows x 128 j, 256 threads
// (8 warps: 4m x 2n), warp tile m16 x n64. Inverse norms computed inline.
__global__ void attgemm_kernel() {
    __shared__ uint32_t Ah[64][20], Al[64][20];
    __shared__ uint32_t Bnh[128][20], Bnl[128][20];
    __shared__ float redm[64][2], reds[64][2];
    __shared__ float redm2[64][2], reds2[64][2];
    __shared__ float s_invi[64], s_invj[128];
    const int bm = blockIdx.x * 64;
    const int sp = blockIdx.y;
    const int j0 = sp * 128;
    const int tid = threadIdx.x;
    const int lane = tid & 31, wid = tid >> 5;
    const int wm = wid >> 1, wn = wid & 1;
    const int g = lane >> 2, t = lane & 3;
    const uint32_t aH = smem_u32(&Ah[0][0]), aL = smem_u32(&Al[0][0]);
    const uint32_t bH = smem_u32(&Bnh[0][0]), bL = smem_u32(&Bnl[0][0]);
    if (tid < 64) {
        int r = bm + tid;
        float s = g_znpart[0][r] + g_znpart[1][r] + g_znpart[2][r] + g_znpart[3][r];
        s_invi[tid] = 1.f / fmaxf(sqrtf(s), 1e-8f);
    } else if (tid >= 128) {
        int j = tid - 128;
        int r = j0 + j;
        float s = g_znpart[0][r] + g_znpart[1][r] + g_znpart[2][r] + g_znpart[3][r];
        s_invj[j] = 1.f / fmaxf(sqrtf(s), 1e-8f);
    }
    float acc[8][4];
#pragma unroll
    for (int n = 0; n < 8; n++)
#pragma unroll
        for (int q = 0; q < 4; q++) acc[n][q] = 0.f;

    const int arow = (lane & 7) + ((lane >> 3) & 1) * 8;
    const int acol = ((lane >> 4) & 1) * 4;
    const int brow = (lane & 7) + ((lane >> 4) & 1) * 8;
    const int bcol = ((lane >> 3) & 1) * 4;

    for (int k0 = 0; k0 < D_; k0 += 16) {
        // A: 64 rows x 16 k (row-major, natural layout of g_z)
        {
            int r = tid >> 2, c4 = tid & 3;
            float4 v = *(const float4*)&g_z[(bm + r) * D_ + k0 + c4 * 4];
            uint32_t hi[4], lo[4];
            split4(v, hi, lo);
            *(uint4*)&Ah[r][c4 * 4] = *(uint4*)hi;
            *(uint4*)&Al[r][c4 * 4] = *(uint4*)lo;
        }
        // B: 128 j-rows x 16 k (row-major — no transpose needed)
#pragma unroll
        for (int l = 0; l < 2; l++) {
            int id = tid + 256 * l;
            int jr = id >> 2, c4 = id & 3;
            float4 v = *(const float4*)&g_z[(j0 + jr) * D_ + k0 + c4 * 4];
            uint32_t hi[4], lo[4];
            split4(v, hi, lo);
            *(uint4*)&Bnh[jr][c4 * 4] = *(uint4*)hi;
            *(uint4*)&Bnl[jr][c4 * 4] = *(uint4*)lo;
        }
        __syncthreads();
#pragma unroll
        for (int ks = 0; ks < 16; ks += 8) {
            uint32_t ah[4], al[4];
            {
                uint32_t off = ((wm * 16 + arow) * 20 + ks + acol) * 4;
                ldsm4(ah, aH + off);
                ldsm4(al, aL + off);
            }
#pragma unroll
            for (int np = 0; np < 4; np++) {
                uint32_t b4h[4], b4l[4];
                uint32_t off = ((wn * 64 + np * 16 + brow) * 20 + ks + bcol) * 4;
                ldsm4(b4h, bH + off);
                ldsm4(b4l, bL + off);
                mma_tf32(acc[2 * np],     ah, b4h);
                mma_tf32(acc[2 * np],     ah, b4l);
                mma_tf32(acc[2 * np],     al, b4h);
                mma_tf32(acc[2 * np + 1], ah, b4h + 2);
                mma_tf32(acc[2 * np + 1], ah, b4l + 2);
                mma_tf32(acc[2 * np + 1], al, b4h + 2);
            }
        }
        __syncthreads();
    }
    const int rbase = wm * 16 + g;
    const int r0 = bm + rbase, r1 = r0 + 8;
    // sim / attdot stores
    if (j0 < MHN_) {
        float i0v = s_invi[rbase], i1v = s_invi[rbase + 8];
#pragma unroll
        for (int n = 0; n < 8; n++) {
            int cl = wn * 64 + n * 8 + 2 * t;
            int j = j0 + cl;
            if (j < MHN_) {
                float jv = s_invj[cl];
                if (r0 < MHN_) { g_attdot[r0 * MHN_ + j] = acc[n][0]; g_sim[r0 * MHN_ + j] = acc[n][0] * i0v * jv; }
                if (r1 < MHN_) { g_attdot[r1 * MHN_ + j] = acc[n][2]; g_sim[r1 * MHN_ + j] = acc[n][2] * i1v * jv; }
            }
            if (j + 1 < MHN_) {
                float jv = s_invj[cl + 1];
                if (r0 < MHN_) { g_attdot[r0 * MHN_ + j + 1] = acc[n][1]; g_sim[r0 * MHN_ + j + 1] = acc[n][1] * i0v * jv; }
                if (r1 < MHN_) { g_attdot[r1 * MHN_ + j + 1] = acc[n][3]; g_sim[r1 * MHN_ + j + 1] = acc[n][3] * i1v * jv; }
            }
        }
    }
    // att softmax partials (raw dots)
    {
        float m0 = -FLT_MAX, m1 = -FLT_MAX;
#pragma unroll
        for (int n = 0; n < 8; n++) {
            m0 = fmaxf(m0, fmaxf(acc[n][0], acc[n][1]));
            m1 = fmaxf(m1, fmaxf(acc[n][2], acc[n][3]));
        }
        float s0 = 0.f, s1 = 0.f;
#pragma unroll
        for (int n = 0; n < 8; n++) {
            s0 += __expf(acc[n][0] - m0) + __expf(acc[n][1] - m0);
            s1 += __expf(acc[n][2] - m1) + __expf(acc[n][3] - m1);
        }
#pragma unroll
        for (int o = 1; o <= 2; o <<= 1) {
            float mo = __shfl_xor_sync(0xffffffffu, m0, o);
            float so = __shfl_xor_sync(0xffffffffu, s0, o);
            msmerge(m0, s0, mo, so);
            mo = __shfl_xor_sync(0xffffffffu, m1, o);
            so = __shfl_xor_sync(0xffffffffu, s1, o);
            msmerge(m1, s1, mo, so);
        }
        if (t == 0) {
            redm[rbase][wn] = m0; reds[rbase][wn] = s0;
            redm[rbase + 8][wn] = m1; reds[rbase + 8][wn] = s1;
        }
    }
    // lse partials (rows < 100)
    if (bm < MFN_) {
        float vt0 = s_invi[rbase] * (1.f / TAU_F);
        float vt1 = s_invi[rbase + 8] * (1.f / TAU_F);
        float m2 = -FLT_MAX, s2 = 0.f, m3 = -FLT_MAX, s3 = 0.f;
#pragma unroll
        for (int n = 0; n < 8; n++) {
            int cl = wn * 64 + n * 8 + 2 * t;
            float j0v = s_invj[cl], j1v = s_invj[cl + 1];
            msadd(m2, s2, acc[n][0] * vt0 * j0v);
            msadd(m2, s2, acc[n][1] * vt0 * j1v);
            msadd(m3, s3, acc[n][2] * vt1 * j0v);
            msadd(m3, s3, acc[n][3] * vt1 * j1v);
        }
#pragma unroll
        for (int o = 1; o <= 2; o <<= 1) {
            float mo = __shfl_xor_sync(0xffffffffu, m2, o);
            float so = __shfl_xor_sync(0xffffffffu, s2, o);
            msmerge(m2, s2, mo, so);
            mo = __shfl_xor_sync(0xffffffffu, m3, o);
            so = __shfl_xor_sync(0xffffffffu, s3, o);
            msmerge(m3, s3, mo, so);
        }
        if (t == 0) {
            redm2[rbase][wn] = m2; reds2[rbase][wn] = s2;
            redm2[rbase + 8][wn] = m3; reds2[rbase + 8][wn] = s3;
        }
    }
    __syncthreads();
    if (tid < 64) {
        int i = bm + tid;
        if (i < MHN_) {
            float M = redm[tid][0], S = reds[tid][0];
            msmerge(M, S, redm[tid][1], reds[tid][1]);
            g_attm[i * NSPL_ + sp] = M;
            g_atts[i * NSPL_ + sp] = S;
        }
        if (i < MFN_) {
            float M = redm2[tid][0], S = reds2[tid][0];
            msmerge(M, S, redm2[tid][1], reds2[tid][1]);
            g_lsem[i * NSPL_ + sp] = M;
            g_lses[i * NSPL_ + sp] = S;
        }
    }
}

// cl logits GEMM: z[0:512] @ hedges[0:512]^T, inverse norms inline
__global__ void clgemm_kernel() {
    __shared__ float As[16][68];
    __shared__ float Bs[16][132];
    __shared__ float s_invi[64], s_invj[128];
    const int bm = blockIdx.x * 64;
    const int j0 = blockIdx.y * 128;
    const int tid = threadIdx.x;
    const int tx = tid & 15, ty = tid >> 4;
    if (tid < 64) {
        int r = bm + tid;
        float s = g_znpart[0][r] + g_znpart[1][r] + g_znpart[2][r] + g_znpart[3][r];
        s_invi[tid] = 1.f / fmaxf(sqrtf(s), 1e-8f);
    }
    {
        int r = j0 + tid;
        float s = g_hnpart[0][r] + g_hnpart[1][r] + g_hnpart[2][r] + g_hnpart[3][r];
        s_invj[tid] = 1.f / fmaxf(sqrtf(s), 1e-8f);
    }
    float acc[8][8];
#pragma unroll
    for (int r = 0; r < 8; r++)
#pragma unroll
        for (int c = 0; c < 8; c++) acc[r][c] = 0.f;
    for (int k0 = 0; k0 < D_; k0 += 16) {
#pragma unroll
        for (int l = 0; l < 2; l++) {
            int id = tid * 2 + l;
            int r = id >> 2, c4 = id & 3;
            float4 v = *(const float4*)&g_z[(bm + r) * D_ + k0 + c4 * 4];
            As[c4 * 4 + 0][r] = v.x;
            As[c4 * 4 + 1][r] = v.y;
            As[c4 * 4 + 2][r] = v.z;
            As[c4 * 4 + 3][r] = v.w;
        }
#pragma unroll
        for (int l = 0; l < 4; l++) {
            int id = tid + 128 * l;
            int jr = id >> 2, c4 = id & 3;
            float4 v = *(const float4*)&g_hedges[(j0 + jr) * D_ + k0 + c4 * 4];
            Bs[c4 * 4 + 0][jr] = v.x;
            Bs[c4 * 4 + 1][jr] = v.y;
            Bs[c4 * 4 + 2][jr] = v.z;
            Bs[c4 * 4 + 3][jr] = v.w;
        }
        __syncthreads();
#pragma unroll
        for (int kk = 0; kk < 16; kk++) {
            float4 a0 = *(const float4*)&As[kk][ty * 8];
            float4 a1 = *(const float4*)&As[kk][ty * 8 + 4];
            float4 b0 = *(const float4*)&Bs[kk][tx * 8];
            float4 b1 = *(const float4*)&Bs[kk][tx * 8 + 4];
            float a[8] = {a0.x, a0.y, a0.z, a0.w, a1.x, a1.y, a1.z, a1.w};
            float b[8] = {b0.x, b0.y, b0.z, b0.w, b1.x, b1.y, b1.z, b1.w};
#pragma unroll
            for (int r = 0; r < 8; r++)
#pragma unroll
                for (int c = 0; c < 8; c++) acc[r][c] += a[r] * b[c];
        }
        __syncthreads();
    }
#pragma unroll
    for (int r = 0; r < 8; r++) {
        int i = bm + ty * 8 + r;
        if (i >= ECAP_) continue;
        float vi = s_invi[ty * 8 + r] * (1.f / TAU_F);
#pragma unroll
        for (int c = 0; c < 8; c += 2) {
            int j = j0 + tx * 8 + c;
            if (j < ECAP_ - 1) {
                *(float2*)&g_logits[i * 512 + j] =
                    make_float2(acc[r][c] * vi * s_invj[tx * 8 + c],
                                acc[r][c + 1] * vi * s_invj[tx * 8 + c + 1]);
            } else {
                if (j < ECAP_) g_logits[i * 512 + j] = acc[r][c] * vi * s_invj[tx * 8 + c];
                if (j + 1 < ECAP_) g_logits[i * 512 + j + 1] = acc[r][c + 1] * vi * s_invj[tx * 8 + c + 1];
            }
        }
    }
}

// Sparse edge aggregation: grid (125 edge-groups, 8 i-splits), warp-local rows.
__global__ void edge_part_kernel(const float* __restrict__ Hp, const float* __restrict__ z) {
    __shared__ float racc[8][4][256];
    __shared__ int rcnt[8][4];
    const int tid = threadIdx.x;
    const int lane = tid & 31, w = tid >> 5;
    const int e0 = blockIdx.x * 4, sp = blockIdx.y;
    float acc[4][8] = {};
    int cnt[4] = {0, 0, 0, 0};
    const int ibase = sp * 1024;
#pragma unroll 1
    for (int ic = 0; ic < 1024; ic += 256) {
        int i0 = ibase + ic;
        float4 v = *(const float4*)&Hp[(size_t)(i0 + tid) * E_ + e0];
        int m = (v.x > 0.f) | ((v.y > 0.f) << 1) | ((v.z > 0.f) << 2) | ((v.w > 0.f) << 3);
        unsigned b = __ballot_sync(0xffffffffu, m != 0);
        int rowbase = i0 + w * 32;
        while (b) {
            int src = __ffs(b) - 1;
            b &= b - 1;
            int mm = __shfl_sync(0xffffffffu, m, src);
            const float* zr = &z[(size_t)(rowbase + src) * D_];
            float zv[8];
#pragma unroll
            for (int t = 0; t < 8; t++) zv[t] = zr[lane + 32 * t];
            switch (mm) {
                case 1:
#pragma unroll
                    for (int t = 0; t < 8; t++) acc[0][t] += zv[t];
                    cnt[0]++; break;
                case 2:
#pragma unroll
                    for (int t = 0; t < 8; t++) acc[1][t] += zv[t];
                    cnt[1]++; break;
                case 4:
#pragma unroll
                    for (int t = 0; t < 8; t++) acc[2][t] += zv[t];
                    cnt[2]++; break;
                case 8:
#pragma unroll
                    for (int t = 0; t < 8; t++) acc[3][t] += zv[t];
                    cnt[3]++; break;
                default:
                    if (mm & 1) {
#pragma unroll
                        for (int t = 0; t < 8; t++) acc[0][t] += zv[t];
                        cnt[0]++;
                    }
                    if (mm & 2) {
#pragma unroll
                        for (int t = 0; t < 8; t++) acc[1][t] += zv[t];
                        cnt[1]++;
                    }
                    if (mm & 4) {
#pragma unroll
                        for (int t = 0; t < 8; t++) acc[2][t] += zv[t];
                        cnt[2]++;
                    }
                    if (mm & 8) {
#pragma unroll
                        for (int t = 0; t < 8; t++) acc[3][t] += zv[t];
                        cnt[3]++;
                    }
            }
        }
    }
#pragma unroll
    for (int e = 0; e < 4; e++)
#pragma unroll
        for (int t = 0; t < 8; t++) racc[w][e][lane + 32 * t] = acc[e][t];
    if (lane == 0) {
#pragma unroll
        for (int e = 0; e < 4; e++) rcnt[w][e] = cnt[e];
    }
    __syncthreads();
#pragma unroll
    for (int e = 0; e < 4; e++) {
        float s = 0.f;
#pragma unroll
        for (int q = 0; q < 8; q++) s += racc[q][e][tid];
        g_edge_part[sp][(e0 + e) * D_ + tid] = s;
    }
    if (tid < 4) {
        int c = 0;
#pragma unroll
        for (int q = 0; q < 8; q++) c += rcnt[q][tid];
        g_cntp[sp][e0 + tid] = c;
    }
}

// edge MLP layer 1 (mean fused)
__global__ void gemm64_e1_kernel(const float* __restrict__ B, const float* __restrict__ bias,
                                 float* __restrict__ C) {
    __shared__ float As[16][68];
    __shared__ float Bs[16][68];
    const int bm = blockIdx.x * 64, bn = blockIdx.y * 64;
    const int tid = threadIdx.x;
    const int tx = tid & 15, ty = tid >> 4;
    const int arow = bm + (tid >> 2);
    float cinv = 0.f;
    {
        int c = 0;
#pragma unroll
        for (int p = 0; p < 8; p++) c += g_cntp[p][arow];
        cinv = (c > 0 && arow < ECAP_) ? 1.f / (float)c : 0.f;
    }
    float acc[4][4] = {};
    for (int k0 = 0; k0 < D_; k0 += 16) {
        {
            int r = tid >> 2, c4 = tid & 3;
            float4 s = make_float4(0.f, 0.f, 0.f, 0.f);
#pragma unroll
            for (int p = 0; p < 8; p++) {
                float4 t = *(const float4*)&g_edge_part[p][arow * D_ + k0 + c4 * 4];
                s.x += t.x; s.y += t.y; s.z += t.z; s.w += t.w;
            }
            As[c4 * 4 + 0][r] = s.x * cinv;
            As[c4 * 4 + 1][r] = s.y * cinv;
            As[c4 * 4 + 2][r] = s.z * cinv;
            As[c4 * 4 + 3][r] = s.w * cinv;
        }
        {
            int r = tid >> 4, c4 = tid & 15;
            float4 v = *(const float4*)&B[(k0 + r) * D_ + bn + c4 * 4];
            *(float4*)&Bs[r][c4 * 4] = v;
        }
        __syncthreads();
#pragma unroll
        for (int kk = 0; kk < 16; kk++) {
            float a[4], b[4];
#pragma unroll
            for (int u = 0; u < 4; u++) a[u] = As[kk][ty * 4 + u];
#pragma unroll
            for (int u = 0; u < 4; u++) b[u] = Bs[kk][tx * 4 + u];
#pragma unroll
            for (int i = 0; i < 4; i++)
#pragma unroll
                for (int j = 0; j < 4; j++) acc[i][j] += a[i] * b[j];
        }
        __syncthreads();
    }
#pragma unroll
    for (int i = 0; i < 4; i++) {
        int row = bm + ty * 4 + i;
#pragma unroll
        for (int j = 0; j < 4; j++) {
            int col = bn + tx * 4 + j;
            C[row * D_ + col] = fmaxf(acc[i][j] + bias[col], 0.f);
        }
    }
}

// edge MLP layer 2 (hnorm partials fused)
__global__ void gemm64_e2_kernel(const float* __restrict__ A, const float* __restrict__ B,
                                 const float* __restrict__ bias, float* __restrict__ C) {
    __shared__ float As[16][68];
    __shared__ float Bs[16][68];
    __shared__ float ssq[64][17];
    const int bm = blockIdx.x * 64, bn = blockIdx.y * 64;
    const int tid = threadIdx.x;
    const int tx = tid & 15, ty = tid >> 4;
    float acc[4][4] = {};
    for (int k0 = 0; k0 < D_; k0 += 16) {
        {
            int r = tid >> 2, c4 = tid & 3;
            float4 v = *(const float4*)&A[(bm + r) * D_ + k0 + c4 * 4];
            As[c4 * 4 + 0][r] = v.x;
            As[c4 * 4 + 1][r] = v.y;
            As[c4 * 4 + 2][r] = v.z;
            As[c4 * 4 + 3][r] = v.w;
        }
        {
            int r = tid >> 4, c4 = tid & 15;
            float4 v = *(const float4*)&B[(k0 + r) * D_ + bn + c4 * 4];
            *(float4*)&Bs[r][c4 * 4] = v;
        }
        __syncthreads();
#pragma unroll
        for (int kk = 0; kk < 16; kk++) {
            float a[4], b[4];
#pragma unroll
            for (int u = 0; u < 4; u++) a[u] = As[kk][ty * 4 + u];
#pragma unroll
            for (int u = 0; u < 4; u++) b[u] = Bs[kk][tx * 4 + u];
#pragma unroll
            for (int i = 0; i < 4; i++)
#pragma unroll
                for (int j = 0; j < 4; j++) acc[i][j] += a[i] * b[j];
        }
        __syncthreads();
    }
#pragma unroll
    for (int i = 0; i < 4; i++) {
        int row = bm + ty * 4 + i;
        float sq = 0.f;
#pragma unroll
        for (int j = 0; j < 4; j++) {
            int col = bn + tx * 4 + j;
            float v = acc[i][j] + bias[col];
            C[row * D_ + col] = v;
            sq += v * v;
        }
        ssq[ty * 4 + i][tx] = sq;
    }
    __syncthreads();
    if (tid < 64) {
        float s = 0.f;
#pragma unroll
        for (int q = 0; q < 16; q++) s += ssq[tid][q];
        g_hnpart[blockIdx.y][bm + tid] = s;
    }
}

// merged finalize: att rows (0..199), lse (200)
__global__ void merge_kernel() {
    int b = blockIdx.x;
    if (b < MHN_) {
        int i = b;
        __shared__ float Ms, Ss;
        if (threadIdx.x == 0) {
            float M = -FLT_MAX;
            for (int p = 0; p < NSPL_; p++) M = fmaxf(M, g_attm[i * NSPL_ + p]);
            float S = 0.f;
            for (int p = 0; p < NSPL_; p++) S += g_atts[i * NSPL_ + p] * __expf(g_attm[i * NSPL_ + p] - M);
            Ms = M; Ss = S;
        }
        __syncthreads();
        for (int j = threadIdx.x; j < MHN_; j += blockDim.x)
            g_att[i * MHN_ + j] = __expf(g_attdot[i * MHN_ + j] - Ms) / Ss;
    } else {
        int i = threadIdx.x;
        if (i < MFN_) {
            float M = -FLT_MAX;
            for (int p = 0; p < NSPL_; p++) M = fmaxf(M, g_lsem[i * NSPL_ + p]);
            float S = 0.f;
            for (int p = 0; p < NSPL_; p++) S += g_lses[i * NSPL_ + p] * __expf(g_lsem[i * NSPL_ + p] - M);
            g_lse[i] = M + logf(S);
        }
    }
}

// fused losses
__global__ void losses_kernel(const float* __restrict__ Ho, const float* __restrict__ Hp) {
    __shared__ float sm[32];
    int b = blockIdx.x;
    int tid = threadIdx.x;
    if (b < ECAP_) {
        int i = b;
        float lm = -FLT_MAX;
        for (int j = tid; j < ECAP_; j += 256) lm = fmaxf(lm, g_logits[i * 512 + j]);
        float M = block_max(lm, sm);
        float ls = 0.f;
        for (int j = tid; j < ECAP_; j += 256) ls += __expf(g_logits[i * 512 + j] - M);
        float S = block_sum(ls, sm);
        if (tid == 0) g_clrow[i] = g_logits[i * 512 + i] - (M + logf(S));
    } else {
        int i = b - ECAP_;
        {
            int j = tid;
            bool act = j < MHN_;
            float simv = act ? g_sim[i * MHN_ + j] : 0.f;
            float attv = act ? g_att[i * MHN_ + j] : 1.f;
            bool mask = act && (j != i) && (simv > MU_F) && (attv < NU_F);
            float neg = -simv / TAU_F;
            float m = block_max(mask ? neg : -FLT_MAX, sm);
            if (m == -FLT_MAX) {
                if (tid == 0) { g_hnsum[i] = 0.f; g_hncnt[i] = 0.f; }
            } else {
                float s = block_sum(mask ? expf(neg - m) : 0.f, sm);
                float lse = m + logf(s);
                float wgt = fminf(simv / MU_F, 1.f);
                float pair = -wgt * (neg - lse);
                float ps = block_sum(mask ? pair : 0.f, sm);
                float pc = block_sum(mask ? 1.f : 0.f, sm);
                if (tid == 0) { g_hnsum[i] = ps; g_hncnt[i] = pc; }
            }
        }
        if (i < MFN_) {
            __shared__ unsigned char cand[128];
            __shared__ short clist[MFN_];
            __shared__ int ncand;
            if (tid < 128) cand[tid] = 0;
            __syncthreads();
            if (tid < MFN_) {
                bool g = (tid > i) && (g_sim[i * MHN_ + tid] > GAMMA_F)
                                   && (g_att[i * MHN_ + tid] > DELTA_F);
                cand[tid] = g ? 1 : 0;
            }
            __syncthreads();
            if (tid == 0) {
                int n = 0;
                for (int j = i + 1; j < MFN_; j++) if (cand[j]) clist[n++] = (short)j;
                ncand = n;
            }
            __syncthreads();
            int nc = ncand;
            float fsum = 0.f, fcnt = 0.f;
            for (int k = 0; k < nc; k++) {
                int j = clist[k];
                float ao = 0.f, ap = 0.f;
                for (int t = tid; t < E_; t += 256) {
                    ao += Ho[i * E_ + t] * Ho[j * E_ + t];
                    ap += Hp[i * E_ + t] * Hp[j * E_ + t];
                }
                ao = block_sum(ao, sm);
                ap = block_sum(ap, sm);
                if (ap == 0.f && ao > 0.f) {
                    fsum += -(g_sim[i * MHN_ + j] / TAU_F - g_lse[i]);
                    fcnt += 1.f;
                }
            }
            if (tid == 0) { g_fnrow[i] = fsum; g_fncnt[i] = fcnt; }
        }
    }
}

// final combine
__global__ void final_kernel(const float* __restrict__ bw, float* __restrict__ out) {
    __shared__ float sm[32];
    int tid = threadIdx.x;
    float v = 0.f;
    for (int i = tid; i < ECAP_; i += 512) v += g_clrow[i];
    float clsum = block_sum(v, sm);
    v = 0.f; float c = 0.f;
    for (int i = tid; i < MFN_; i += 512) { v += g_fnrow[i]; c += g_fncnt[i]; }
    float fnsum = block_sum(v, sm);
    float fncnt = block_sum(c, sm);
    v = 0.f; c = 0.f;
    for (int i = tid; i < MHN_; i += 512) { v += g_hnsum[i]; c += g_hncnt[i]; }
    float hnsum = block_sum(v, sm);
    float hncnt = block_sum(c, sm);
    float d2 = 0.f, o2 = 0.f;
    for (int i = tid; i < SAMP_; i += 512) { d2 += g_topo[i * 2]; o2 += g_topo[i * 2 + 1]; }
    float D2 = block_sum(d2, sm);
    float O2 = block_sum(o2, sm);
    float za = 0.f, zb = 0.f;
    for (int i = tid; i < 2048; i += 512) { za += (float)g_nza[i]; zb += (float)g_nzb[i]; }
    float NZ = block_sum(za, sm);
    float NZP = block_sum(zb, sm);
    if (tid == 0) {
        float cl_loss = -clsum / (float)ECAP_;
        float fn_loss = (fncnt > 0.f) ? fnsum / fmaxf(fncnt, 1.f) : 0.f;
        float hard_loss = (hncnt > 0.f) ? hnsum / fmaxf(hncnt, 1.f) : 0.f;
        float sparsity = (NZ > 0.f) ? NZP / fmaxf(NZ, 1.f) : 1.f;
        float dn = sqrtf(D2), on = sqrtf(O2);
        float topo = (on > 0.f) ? expf(-ALPHA_F * dn / fmaxf(on, 1e-12f)) : 1.f;
        float retention = sparsity * topo;
        out[0] = bw[0] * (retention * cl_loss + fn_loss + hard_loss);
    }
}

// ---------------- launch ----------------
extern "C" void kernel_launch(void* const* d_in, const int* in_sizes, int n_in,
                              void* d_out, int out_size) {
    (void)in_sizes; (void)n_in; (void)out_size;
    const float* Ho  = (const float*)d_in[0];
    const float* Hp  = (const float*)d_in[1];
    const float* ne  = (const float*)d_in[2];
    const float* bw  = (const float*)d_in[3];
    const float* Wn1 = (const float*)d_in[4];
    const float* bn1 = (const float*)d_in[5];
    const float* Wn2 = (const float*)d_in[6];
    const float* bn2 = (const float*)d_in[7];
    const float* We1 = (const float*)d_in[8];
    const float* be1 = (const float*)d_in[9];
    const float* We2 = (const float*)d_in[10];
    const float* be2 = (const float*)d_in[11];
    float* out = (float*)d_out;

    void *p;
    float *p_tmp, *p_z, *p_etmp, *p_hedges;
    cudaGetSymbolAddress(&p, g_tmp);    p_tmp    = (float*)p;
    cudaGetSymbolAddress(&p, g_z);      p_z      = (float*)p;
    cudaGetSymbolAddress(&p, g_etmp);   p_etmp   = (float*)p;
    cudaGetSymbolAddress(&p, g_hedges); p_hedges = (float*)p;

    // idx 0-1: node MLP via TF32 tensor cores + ldmatrix
    gemm_tf32_kernel<true,  false><<<dim3(64, 4), 256>>>(ne,    Wn1, bn1, p_tmp);
    gemm_tf32_kernel<false, true ><<<dim3(64, 4), 256>>>(p_tmp, Wn2, bn2, p_z);

    // idx 2: independent scan (fills profile slot)
    count_nz_kernel<<<2048, 256>>>((const float4*)Ho, (const float4*)Hp);

    // idx 3: att/sim/lse via TF32 + ldmatrix (PROFILED this round)
    attgemm_kernel<<<dim3(4, NSPL_), 256>>>();

    // idx 4: topo
    topo_kernel<<<SAMP_, 128>>>(Ho, Hp);

    // idx 5: edge aggregation partials
    edge_part_kernel<<<dim3(ECAP_ / 4, 8), 256>>>(Hp, p_z);

    // idx 6-7: edge MLP
    gemm64_e1_kernel<<<dim3(8, 4), 256>>>(We1, be1, p_etmp);
    gemm64_e2_kernel<<<dim3(8, 4), 256>>>(p_etmp, We2, be2, p_hedges);

    // idx 8: merge finalizers (att softmax, lse)
    merge_kernel<<<MHN_ + 1, 256>>>();

    // idx 9: cl logits GEMM (norms inline)
    clgemm_kernel<<<dim3(8, 4), 128>>>();

    // idx 10: fused losses
    losses_kernel<<<ECAP_ + MHN_, 256>>>(Ho, Hp);

    // idx 11: final combine
    final_kernel<<<1, 512>>>(bw, out);
}